// round 10
// baseline (speedup 1.0000x reference)
#include <cuda_runtime.h>
#include <math.h>

#define PB 8
#define PC 64
#define PH 256
#define PW 256
#define PKX 64
#define PKY 32
#define NROWS (PB*PC*PH)

// ---- scratch (device globals; no runtime allocation) ----
__device__ __align__(16) float  g_T[256*64];
__device__ __align__(16) float  g_cos[256];
__device__ __align__(16) float  g_sin[256];
__device__ __align__(16) float2 g_ct[256];            // (cos, sin) pairs
__device__ __align__(16) float2 g_E[128*64];          // fwdH twiddles E[h][kxp]
__device__ __align__(16) float2 g_X1[PB*PC*PH*PKY];   // after fwd-W  [b,c,h,ky]
__device__ __align__(16) float2 g_XF[PB*PC*PKX*PKY];  // after fwd-H  [b,c,kx',ky]
__device__ __align__(16) float2 g_OF[PB*PC*PKX*PKY];  // after mix
__device__ __align__(16) float2 g_Y1[PB*PC*PKY*PH];   // after inv-H  [b,c,ky,h]
__device__ __align__(16) float  g_y[PB*PC*PH*PW];     // spectral conv out
__device__ __align__(16) float  g_z[PB*PC*PH*PW];     // MLP out
__device__ __align__(16) float  g_p1[PB*PC*4*2];      // per-invW-block partials
__device__ __align__(16) float  g_p2[PB*PH*2];
__device__ __align__(16) float  g_s1[PB*2];
__device__ __align__(16) float  g_s2[PB*2];
__device__ __align__(16) float  g_gb[PB*PC*2];

__device__ __forceinline__ float gelu_f(float v) {
    return 0.5f * v * (1.0f + erff(v * 0.7071067811865476f));
}

// ---- packed f32x2 helpers (FFMA2: 2 fp32 FMA per issue slot, bit-identical) ----
__device__ __forceinline__ unsigned long long fma2(unsigned long long a,
                                                   unsigned long long b,
                                                   unsigned long long c) {
    unsigned long long d;
    asm("fma.rn.f32x2 %0, %1, %2, %3;" : "=l"(d) : "l"(a), "l"(b), "l"(c));
    return d;
}
__device__ __forceinline__ void upk2(unsigned long long v, float& lo, float& hi) {
    asm("mov.b64 {%0, %1}, %2;" : "=f"(lo), "=f"(hi) : "l"(v));
}

// ---- twiddle tables ----
__global__ void k_tab() {
    int tid = threadIdx.x;
    {
        int j = tid;
        double sd, cd;
        sincospi((double)j * (2.0 / 256.0), &sd, &cd);
        g_cos[j] = (float)cd;
        g_sin[j] = (float)sd;
        g_ct[j] = make_float2((float)cd, (float)sd);
        for (int ky = 0; ky < 32; ++ky) {
            int idx = (ky * j) & 255;
            double s2, c2;
            sincospi((double)idx * (2.0 / 256.0), &s2, &c2);
            g_T[j * 64 + 2 * ky]     = (float)c2;
            g_T[j * 64 + 2 * ky + 1] = (float)(-s2);
        }
    }
    for (int i = tid; i < 128 * 64; i += 256) {
        int h = i >> 6, kxp = i & 63;
        int kxm = kxp + ((kxp >= 32) ? 192 : 0);
        int idx = (kxm * h) & 255;
        double s2, c2;
        sincospi((double)idx * (2.0 / 256.0), &s2, &c2);
        g_E[i] = make_float2((float)c2, (float)s2);
    }
}

// ---- FiLM gamma/beta ----
__global__ void k_film(const float* __restrict__ t,
                       const float* __restrict__ gw, const float* __restrict__ gb,
                       const float* __restrict__ bw, const float* __restrict__ bb) {
    int b = blockIdx.x, o = threadIdx.x;
    float g = gb[o], be = bb[o];
    for (int c = 0; c < PC; ++c) {
        float tv = t[b * PC + c];
        g  += gw[o * PC + c] * tv;
        be += bw[o * PC + c] * tv;
    }
    g_gb[(b * PC + o) * 2]     = g;
    g_gb[(b * PC + o) * 2 + 1] = be;
}

// ---- forward DFT along W, radix-2; 64 rows/block, 2r x 8c thread tiles ----
__global__ void __launch_bounds__(256) k_fwdW(const float* __restrict__ x) {
    extern __shared__ char smraw[];
    float2* su = (float2*)smraw;            // [row 64][w<128] (u0,u1)  64KB
    float*  sT = (float*)(smraw + 65536);   // [w<128][64]              32KB
    int tid = threadIdx.x;
    size_t base = (size_t)blockIdx.x * 64 * 256;

    for (int i = tid; i < 2048; i += 256) {
        int row = i >> 5, w4 = (i & 31) * 4;
        float4 a = *(const float4*)&x[base + row * 256 + w4];
        float4 b = *(const float4*)&x[base + row * 256 + w4 + 128];
        float4* d = (float4*)&su[row * 128 + w4];
        d[0] = make_float4(a.x + b.x, a.x - b.x, a.y + b.y, a.y - b.y);
        d[1] = make_float4(a.z + b.z, a.z - b.z, a.w + b.w, a.w - b.w);
    }
    const float4* gT4 = (const float4*)g_T;
    float4* sT4 = (float4*)sT;
    for (int i = tid; i < 2048; i += 256) sT4[i] = gT4[i];
    __syncthreads();

    int r0 = (tid >> 3) * 2;
    int c0 = (tid & 7) * 8;

    float acc[2][8];
#pragma unroll
    for (int r = 0; r < 2; ++r)
#pragma unroll
        for (int u = 0; u < 8; ++u) acc[r][u] = 0.0f;

    const float2* rowA = su + r0 * 128;
    const float2* rowB = rowA + 128;
#pragma unroll 4
    for (int k = 0; k < 128; ++k) {
        float2 ua = rowA[k];
        float2 ub = rowB[k];
        float4 t0 = *(const float4*)&sT[k * 64 + c0];
        float4 t1 = *(const float4*)&sT[k * 64 + c0 + 4];
        acc[0][0] += ua.x * t0.x; acc[0][1] += ua.x * t0.y;
        acc[0][2] += ua.y * t0.z; acc[0][3] += ua.y * t0.w;
        acc[0][4] += ua.x * t1.x; acc[0][5] += ua.x * t1.y;
        acc[0][6] += ua.y * t1.z; acc[0][7] += ua.y * t1.w;
        acc[1][0] += ub.x * t0.x; acc[1][1] += ub.x * t0.y;
        acc[1][2] += ub.y * t0.z; acc[1][3] += ub.y * t0.w;
        acc[1][4] += ub.x * t1.x; acc[1][5] += ub.x * t1.y;
        acc[1][6] += ub.y * t1.z; acc[1][7] += ub.y * t1.w;
    }
    float* go = (float*)g_X1 + (size_t)blockIdx.x * 64 * 64;
#pragma unroll
    for (int r = 0; r < 2; ++r) {
        *(float4*)&go[(r0 + r) * 64 + c0] =
            make_float4(acc[r][0], acc[r][1], acc[r][2], acc[r][3]);
        *(float4*)&go[(r0 + r) * 64 + c0 + 4] =
            make_float4(acc[r][4], acc[r][5], acc[r][6], acc[r][7]);
    }
}

// ---- forward DFT along H, radix-2 over h; 1 kx x 8 ky per thread, E via LDG ----
__global__ void __launch_bounds__(256) k_fwdH() {
    extern __shared__ char smraw[];
    float2* sv0 = (float2*)smraw;                     // [h<128][32] sum operand
    float2* sv1 = (float2*)(smraw + 32768 + 32);      // diff operand (bank-skewed)
    int tid = threadIdx.x, bc = blockIdx.x;

    const float4* src = (const float4*)(g_X1 + (size_t)bc * 8192);
    float4* d0 = (float4*)sv0;
    float4* d1 = (float4*)sv1;
    for (int i = tid; i < 2048; i += 256) {
        float4 a = src[i];
        float4 b = src[i + 2048];                     // h+128
        d0[i] = make_float4(a.x + b.x, a.y + b.y, a.z + b.z, a.w + b.w);
        d1[i] = make_float4(a.x - b.x, a.y - b.y, a.z - b.z, a.w - b.w);
    }
    __syncthreads();

    int kxp = tid & 63;
    int ky0 = (tid >> 6) * 8;
    const float2* sv = (kxp & 1) ? sv1 : sv0;         // kxm parity == kxp parity
    const float2* E = g_E + kxp;

    float2 acc[8];
#pragma unroll
    for (int j = 0; j < 8; ++j) acc[j] = make_float2(0.f, 0.f);

#pragma unroll 2
    for (int h = 0; h < 128; ++h) {
        float2 e = E[h * 64];
        const float2* row = &sv[h * 32 + ky0];
        float4 vA = *(const float4*)&row[0];
        float4 vB = *(const float4*)&row[2];
        float4 vC = *(const float4*)&row[4];
        float4 vD = *(const float4*)&row[6];
        float2 v[8] = { {vA.x,vA.y},{vA.z,vA.w},{vB.x,vB.y},{vB.z,vB.w},
                        {vC.x,vC.y},{vC.z,vC.w},{vD.x,vD.y},{vD.z,vD.w} };
#pragma unroll
        for (int j = 0; j < 8; ++j) {
            // (xr + i xi)(c - i s)
            acc[j].x += v[j].x * e.x + v[j].y * e.y;
            acc[j].y += v[j].y * e.x - v[j].x * e.y;
        }
    }
    float2* o = g_XF + ((size_t)bc * 64 + kxp) * 32 + ky0;
#pragma unroll
    for (int j = 0; j < 8; j += 2)
        *(float4*)&o[j] = make_float4(acc[j].x, acc[j].y, acc[j+1].x, acc[j+1].y);
}

// ---- per-mode complex channel mixing, ky-split for occupancy ----
__global__ void __launch_bounds__(512)
k_mix(const float* __restrict__ w1r, const float* __restrict__ w1i,
      const float* __restrict__ w2r, const float* __restrict__ w2i) {
    extern __shared__ char smraw[];
    float2* sXF = (float2*)smraw;   // [(b*64+i)*16 + kyl], 8192 float2 = 64KB
    int kxp   = blockIdx.x >> 2;
    int ohalf = (blockIdx.x >> 1) & 1;
    int kh    = blockIdx.x & 1;
    int tid = threadIdx.x;

    for (int i = tid; i < 8192; i += 512) {
        int b = i >> 10, rest = i & 1023, ii = rest >> 4, kk = rest & 15;
        sXF[i] = g_XF[(((size_t)b * PC + ii) * PKX + kxp) * PKY + kh * 16 + kk];
    }
    __syncthreads();

    int o   = ohalf * 32 + (tid >> 4);
    int kyl = tid & 15;
    int ky  = kh * 16 + kyl;
    const float* wr; const float* wi; int kxl;
    if (kxp < 32) { wr = w1r; wi = w1i; kxl = kxp; }
    else          { wr = w2r; wi = w2i; kxl = kxp - 32; }

    float ar[8], ai[8];
#pragma unroll
    for (int b = 0; b < 8; ++b) { ar[b] = 0.0f; ai[b] = 0.0f; }

    const float* wrp = wr + (size_t)o * 1024 + kxl * 32 + ky;
    const float* wip = wi + (size_t)o * 1024 + kxl * 32 + ky;
#pragma unroll 2
    for (int i = 0; i < 64; ++i) {
        float wrv = wrp[(size_t)i * 65536];
        float wiv = wip[(size_t)i * 65536];
#pragma unroll
        for (int b = 0; b < 8; ++b) {
            float2 v = sXF[(b * 64 + i) * 16 + kyl];
            ar[b] += v.x * wrv - v.y * wiv;
            ai[b] += v.x * wiv + v.y * wrv;
        }
    }
#pragma unroll
    for (int b = 0; b < 8; ++b)
        g_OF[(((size_t)b * PC + o) * PKX + kxp) * PKY + ky] = make_float2(ar[b], ai[b]);
}

// ---- inverse DFT along H, radix-2: Se/So over kx parity, emit h and h+128 ----
__global__ void __launch_bounds__(256) k_invH() {
    __shared__ float2 sOF[2048];
    __shared__ float2 ct[256];
    int tid = threadIdx.x, bc = blockIdx.x;

    const float4* src = (const float4*)(g_OF + (size_t)bc * 2048);
    float4* dst = (float4*)sOF;
    for (int i = tid; i < 1024; i += 256) dst[i] = src[i];
    ct[tid] = g_ct[tid];
    __syncthreads();

    int h0  = (tid >> 3) * 4;     // h<128
    int ky0 = (tid & 7) * 4;

    float2 ae[4][4], ao[4][4];
#pragma unroll
    for (int hh = 0; hh < 4; ++hh)
#pragma unroll
        for (int j = 0; j < 4; ++j) {
            ae[hh][j] = make_float2(0.f, 0.f);
            ao[hh][j] = make_float2(0.f, 0.f);
        }

    for (int kxp = 0; kxp < 64; kxp += 2) {
        int kxm = kxp + ((kxp >= 32) ? 192 : 0);
        float2 te[4], to[4];
#pragma unroll
        for (int hh = 0; hh < 4; ++hh) {
            int h = h0 + hh;
            te[hh] = ct[(kxm * h) & 255];
            to[hh] = ct[((kxm + 1) * h) & 255];
        }
        float4 eA = *(const float4*)&sOF[kxp * 32 + ky0];
        float4 eB = *(const float4*)&sOF[kxp * 32 + ky0 + 2];
        float4 oA = *(const float4*)&sOF[(kxp + 1) * 32 + ky0];
        float4 oB = *(const float4*)&sOF[(kxp + 1) * 32 + ky0 + 2];
        float2 ove[4] = { {eA.x, eA.y}, {eA.z, eA.w}, {eB.x, eB.y}, {eB.z, eB.w} };
        float2 ovo[4] = { {oA.x, oA.y}, {oA.z, oA.w}, {oB.x, oB.y}, {oB.z, oB.w} };
#pragma unroll
        for (int hh = 0; hh < 4; ++hh) {
#pragma unroll
            for (int j = 0; j < 4; ++j) {
                ae[hh][j].x += ove[j].x * te[hh].x - ove[j].y * te[hh].y;
                ae[hh][j].y += ove[j].x * te[hh].y + ove[j].y * te[hh].x;
                ao[hh][j].x += ovo[j].x * to[hh].x - ovo[j].y * to[hh].y;
                ao[hh][j].y += ovo[j].x * to[hh].y + ovo[j].y * to[hh].x;
            }
        }
    }
#pragma unroll
    for (int j = 0; j < 4; ++j) {
        float2* out = g_Y1 + (size_t)bc * 8192 + (ky0 + j) * 256 + h0;
#pragma unroll
        for (int hh = 0; hh < 4; hh += 2) {
            *(float4*)&out[hh] = make_float4(
                ae[hh][j].x + ao[hh][j].x,     ae[hh][j].y + ao[hh][j].y,
                ae[hh+1][j].x + ao[hh+1][j].x, ae[hh+1][j].y + ao[hh+1][j].y);
            *(float4*)&out[hh + 128] = make_float4(
                ae[hh][j].x - ao[hh][j].x,     ae[hh][j].y - ao[hh][j].y,
                ae[hh+1][j].x - ao[hh+1][j].x, ae[hh+1][j].y - ao[hh+1][j].y);
        }
    }
}

// ---- inverse rfft along W, radix-2: Se/So over ky parity, emit w and w+128 ----
__global__ void __launch_bounds__(256) k_invW() {
    extern __shared__ char smraw[];
    float2* sY = (float2*)smraw;               // 8192 float2 (64KB)
    float2* sW = (float2*)(smraw + 65536);     // 31*32 float2
    __shared__ float rbuf[16];
    int tid = threadIdx.x;
    int bc = blockIdx.x >> 2, wt = blockIdx.x & 3;
    int w0 = wt * 32;

    const float4* src = (const float4*)(g_Y1 + (size_t)bc * 8192);
    float4* dst = (float4*)sY;
    for (int i = tid; i < 4096; i += 256) dst[i] = src[i];

    const float inv = 1.0f / 65536.0f;
    for (int i = tid; i < 31 * 32; i += 256) {
        int ky = (i >> 5) + 1;
        int w  = w0 + (i & 31);
        int idx = (ky * w) & 255;
        sW[i] = make_float2(2.0f * inv * g_cos[idx], 2.0f * inv * g_sin[idx]);
    }
    __syncthreads();

    int h0  = (tid >> 3) * 8;
    int wth = (tid & 7) * 4;

    float se[8][4], so[8][4], dc[8];
#pragma unroll
    for (int hh = 0; hh < 8; ++hh) {
        dc[hh] = inv * sY[h0 + hh].x;
#pragma unroll
        for (int ww = 0; ww < 4; ++ww) { se[hh][ww] = 0.f; so[hh][ww] = 0.f; }
    }

    for (int ky = 1; ky < 31; ky += 2) {
        {
            float2 av[8], bv[4];
            const float4* ap = (const float4*)&sY[ky * 256 + h0];
#pragma unroll
            for (int u = 0; u < 4; ++u) {
                float4 t1 = ap[u];
                av[2*u] = make_float2(t1.x, t1.y);
                av[2*u+1] = make_float2(t1.z, t1.w);
            }
            const float4* bp = (const float4*)&sW[(ky - 1) * 32 + wth];
            float4 t2 = bp[0], t3 = bp[1];
            bv[0] = make_float2(t2.x, t2.y); bv[1] = make_float2(t2.z, t2.w);
            bv[2] = make_float2(t3.x, t3.y); bv[3] = make_float2(t3.z, t3.w);
#pragma unroll
            for (int hh = 0; hh < 8; ++hh)
#pragma unroll
                for (int ww = 0; ww < 4; ++ww)
                    so[hh][ww] += av[hh].x * bv[ww].x - av[hh].y * bv[ww].y;
        }
        {
            float2 av[8], bv[4];
            const float4* ap = (const float4*)&sY[(ky + 1) * 256 + h0];
#pragma unroll
            for (int u = 0; u < 4; ++u) {
                float4 t1 = ap[u];
                av[2*u] = make_float2(t1.x, t1.y);
                av[2*u+1] = make_float2(t1.z, t1.w);
            }
            const float4* bp = (const float4*)&sW[ky * 32 + wth];
            float4 t2 = bp[0], t3 = bp[1];
            bv[0] = make_float2(t2.x, t2.y); bv[1] = make_float2(t2.z, t2.w);
            bv[2] = make_float2(t3.x, t3.y); bv[3] = make_float2(t3.z, t3.w);
#pragma unroll
            for (int hh = 0; hh < 8; ++hh)
#pragma unroll
                for (int ww = 0; ww < 4; ++ww)
                    se[hh][ww] += av[hh].x * bv[ww].x - av[hh].y * bv[ww].y;
        }
    }
    {
        float2 av[8], bv[4];
        const float4* ap = (const float4*)&sY[31 * 256 + h0];
#pragma unroll
        for (int u = 0; u < 4; ++u) {
            float4 t1 = ap[u];
            av[2*u] = make_float2(t1.x, t1.y);
            av[2*u+1] = make_float2(t1.z, t1.w);
        }
        const float4* bp = (const float4*)&sW[30 * 32 + wth];
        float4 t2 = bp[0], t3 = bp[1];
        bv[0] = make_float2(t2.x, t2.y); bv[1] = make_float2(t2.z, t2.w);
        bv[2] = make_float2(t3.x, t3.y); bv[3] = make_float2(t3.z, t3.w);
#pragma unroll
        for (int hh = 0; hh < 8; ++hh)
#pragma unroll
            for (int ww = 0; ww < 4; ++ww)
                so[hh][ww] += av[hh].x * bv[ww].x - av[hh].y * bv[ww].y;
    }

    float s = 0.0f, s2 = 0.0f;
#pragma unroll
    for (int hh = 0; hh < 8; ++hh) {
        float lo[4], hi[4];
#pragma unroll
        for (int ww = 0; ww < 4; ++ww) {
            lo[ww] = dc[hh] + se[hh][ww] + so[hh][ww];
            hi[ww] = dc[hh] + se[hh][ww] - so[hh][ww];
            s += lo[ww] + hi[ww];
            s2 += lo[ww] * lo[ww] + hi[ww] * hi[ww];
        }
        size_t base = (size_t)bc * 65536 + (size_t)(h0 + hh) * 256 + w0 + wth;
        *(float4*)&g_y[base]       = make_float4(lo[0], lo[1], lo[2], lo[3]);
        *(float4*)&g_y[base + 128] = make_float4(hi[0], hi[1], hi[2], hi[3]);
    }

    for (int off = 16; off > 0; off >>= 1) {
        s  += __shfl_down_sync(0xffffffffu, s,  off);
        s2 += __shfl_down_sync(0xffffffffu, s2, off);
    }
    int lane = tid & 31, wid = tid >> 5;
    if (lane == 0) { rbuf[wid] = s; rbuf[wid + 8] = s2; }
    __syncthreads();
    if (tid == 0) {
        float S = 0.0f, S2 = 0.0f;
        for (int i = 0; i < 8; ++i) { S += rbuf[i]; S2 += rbuf[i + 8]; }
        g_p1[blockIdx.x * 2] = S;
        g_p1[blockIdx.x * 2 + 1] = S2;
    }
}

__global__ void k_red1() {
    __shared__ float rbuf[16];
    int b = blockIdx.x, tid = threadIdx.x;
    float s  = g_p1[(b * 256 + tid) * 2];
    float s2 = g_p1[(b * 256 + tid) * 2 + 1];
    for (int off = 16; off > 0; off >>= 1) {
        s  += __shfl_down_sync(0xffffffffu, s,  off);
        s2 += __shfl_down_sync(0xffffffffu, s2, off);
    }
    int lane = tid & 31, wid = tid >> 5;
    if (lane == 0) { rbuf[wid] = s; rbuf[wid + 8] = s2; }
    __syncthreads();
    if (tid == 0) {
        float S = 0.0f, S2 = 0.0f;
        for (int i = 0; i < 8; ++i) { S += rbuf[i]; S2 += rbuf[i + 8]; }
        float mean = S * (1.0f / 4194304.0f);
        float var  = S2 * (1.0f / 4194304.0f) - mean * mean;
        g_s1[b * 2] = mean;
        g_s1[b * 2 + 1] = rsqrtf(var + 1e-5f);
    }
}

// ---- GN1 apply + residual + gelu + MLP (FFMA2, dup weights) + GN2 partials ----
__global__ void __launch_bounds__(256, 3) k_mlp(const float* __restrict__ x,
                      const float* __restrict__ nw, const float* __restrict__ nb,
                      const float* __restrict__ w1, const float* __restrict__ b1,
                      const float* __restrict__ w2, const float* __restrict__ b2) {
    extern __shared__ char smraw[];
    float* sy2 = (float*)smraw;                                  // [c 64][w 64]
    float* sh  = (float*)(smraw + 16384);                        // [m 32][w 64]
    unsigned long long* sw1q = (unsigned long long*)(smraw + 24576);  // [c][m] dup pairs
    unsigned long long* sw2q = (unsigned long long*)(smraw + 40960);  // [m][c] dup pairs
    float* sb1  = (float*)(smraw + 57344);
    float* sb2v = sb1 + 32;
    float* snw  = sb2v + 64;
    float* snb  = snw + 64;
    __shared__ float rbuf[16];

    int tid = threadIdx.x;
    int b = blockIdx.x >> 8, h = blockIdx.x & 255;

    for (int i = tid; i < 2048; i += 256) {
        int c = i >> 5, m = i & 31;
        float w = w1[m * 64 + c];
        ((float2*)sw1q)[c * 32 + m] = make_float2(w, w);
        int m2 = i >> 6, c2 = i & 63;
        float v = w2[c2 * 32 + m2];
        ((float2*)sw2q)[m2 * 64 + c2] = make_float2(v, v);
    }
    if (tid < 64) {
        sb2v[tid] = b2[tid];
        snw[tid] = nw[tid];
        snb[tid] = nb[tid];
        if (tid < 32) sb1[tid] = b1[tid];
    }
    float mean1 = g_s1[b * 2], rstd1 = g_s1[b * 2 + 1];
    __syncthreads();

    int m0 = (tid >> 5) * 4;      // layer1: 4 m per thread
    int c0 = (tid >> 5) * 8;      // layer2: 8 c per thread
    int wl = (tid & 31) * 2;      // 2 w per thread (packed pair)

    float s = 0.0f, s2 = 0.0f;
    for (int q = 0; q < 4; ++q) {
        int wbase = q * 64;

        // Phase A: y2 = gelu( gn1(y)*nw + nb + x )
        for (int i = tid; i < 1024; i += 256) {   // float4 units
            int c = i >> 4, w4 = (i & 15) * 4;
            size_t gid = (size_t)(b * 64 + c) * 65536 + (size_t)h * 256 + wbase + w4;
            float4 yv = *(const float4*)&g_y[gid];
            float4 xv = *(const float4*)&x[gid];
            float a = snw[c] * rstd1, bb = snb[c] - mean1 * rstd1 * snw[c];
            float4 o;
            o.x = gelu_f(yv.x * a + bb + xv.x);
            o.y = gelu_f(yv.y * a + bb + xv.y);
            o.z = gelu_f(yv.z * a + bb + xv.z);
            o.w = gelu_f(yv.w * a + bb + xv.w);
            *(float4*)&sy2[c * 64 + w4] = o;
        }
        __syncthreads();

        // Layer 1: h = gelu(W1 @ y2 + b1)   (32x64 @ 64x64), packed over w pair
        {
            unsigned long long acc[4] = {0ull, 0ull, 0ull, 0ull};
            for (int c = 0; c < 64; ++c) {
                ulonglong2 a01 = *(const ulonglong2*)&sw1q[c * 32 + m0];
                ulonglong2 a23 = *(const ulonglong2*)&sw1q[c * 32 + m0 + 2];
                unsigned long long bv = *(const unsigned long long*)&sy2[c * 64 + wl];
                acc[0] = fma2(a01.x, bv, acc[0]);
                acc[1] = fma2(a01.y, bv, acc[1]);
                acc[2] = fma2(a23.x, bv, acc[2]);
                acc[3] = fma2(a23.y, bv, acc[3]);
            }
#pragma unroll
            for (int mm = 0; mm < 4; ++mm) {
                float o0, o1;
                upk2(acc[mm], o0, o1);
                float bb = sb1[m0 + mm];
                sh[(m0 + mm) * 64 + wl]     = gelu_f(o0 + bb);
                sh[(m0 + mm) * 64 + wl + 1] = gelu_f(o1 + bb);
            }
        }
        __syncthreads();

        // Layer 2: y3 = W2 @ h + b2   (64x32 @ 32x64) + GN2 partial stats
        {
            unsigned long long acc2[8] = {0ull,0ull,0ull,0ull,0ull,0ull,0ull,0ull};
            for (int m = 0; m < 32; ++m) {
                ulonglong2 aA = *(const ulonglong2*)&sw2q[m * 64 + c0];
                ulonglong2 aB = *(const ulonglong2*)&sw2q[m * 64 + c0 + 2];
                ulonglong2 aC = *(const ulonglong2*)&sw2q[m * 64 + c0 + 4];
                ulonglong2 aD = *(const ulonglong2*)&sw2q[m * 64 + c0 + 6];
                unsigned long long bv = *(const unsigned long long*)&sh[m * 64 + wl];
                acc2[0] = fma2(aA.x, bv, acc2[0]);
                acc2[1] = fma2(aA.y, bv, acc2[1]);
                acc2[2] = fma2(aB.x, bv, acc2[2]);
                acc2[3] = fma2(aB.y, bv, acc2[3]);
                acc2[4] = fma2(aC.x, bv, acc2[4]);
                acc2[5] = fma2(aC.y, bv, acc2[5]);
                acc2[6] = fma2(aD.x, bv, acc2[6]);
                acc2[7] = fma2(aD.y, bv, acc2[7]);
            }
#pragma unroll
            for (int cc = 0; cc < 8; ++cc) {
                float o0, o1;
                upk2(acc2[cc], o0, o1);
                float bb = sb2v[c0 + cc];
                o0 += bb; o1 += bb;
                s += o0 + o1;
                s2 += o0 * o0 + o1 * o1;
                size_t gbase = (size_t)(b * 64 + c0 + cc) * 65536 + (size_t)h * 256 + wbase;
                *(float2*)&g_z[gbase + wl] = make_float2(o0, o1);
            }
        }
        __syncthreads();
    }

    for (int off = 16; off > 0; off >>= 1) {
        s  += __shfl_down_sync(0xffffffffu, s,  off);
        s2 += __shfl_down_sync(0xffffffffu, s2, off);
    }
    int lane = tid & 31, widx = tid >> 5;
    if (lane == 0) { rbuf[widx] = s; rbuf[widx + 8] = s2; }
    __syncthreads();
    if (tid == 0) {
        float S = 0.0f, S2 = 0.0f;
        for (int i = 0; i < 8; ++i) { S += rbuf[i]; S2 += rbuf[i + 8]; }
        g_p2[blockIdx.x * 2] = S;
        g_p2[blockIdx.x * 2 + 1] = S2;
    }
}

__global__ void k_red2() {
    __shared__ float rbuf[16];
    int b = blockIdx.x, tid = threadIdx.x;
    float s  = g_p2[(b * 256 + tid) * 2];
    float s2 = g_p2[(b * 256 + tid) * 2 + 1];
    for (int off = 16; off > 0; off >>= 1) {
        s  += __shfl_down_sync(0xffffffffu, s,  off);
        s2 += __shfl_down_sync(0xffffffffu, s2, off);
    }
    int lane = tid & 31, wid = tid >> 5;
    if (lane == 0) { rbuf[wid] = s; rbuf[wid + 8] = s2; }
    __syncthreads();
    if (tid == 0) {
        float S = 0.0f, S2 = 0.0f;
        for (int i = 0; i < 8; ++i) { S += rbuf[i]; S2 += rbuf[i + 8]; }
        float mean = S * (1.0f / 4194304.0f);
        float var  = S2 * (1.0f / 4194304.0f) - mean * mean;
        g_s2[b * 2] = mean;
        g_s2[b * 2 + 1] = rsqrtf(var + 1e-5f);
    }
}

// ---- final: FiLM GN + skip2 ----
__global__ void k_final(const float* __restrict__ x, float* __restrict__ out) {
    int gi = blockIdx.x * 256 + threadIdx.x;
#pragma unroll
    for (int u = 0; u < 4; ++u) {
        size_t i4 = (size_t)gi + (size_t)u * 2097152;
        size_t e = i4 * 4;
        int b = (int)(e >> 22);
        int c = (int)((e >> 16) & 63);
        float mean = g_s2[b * 2], rstd = g_s2[b * 2 + 1];
        float ga = g_gb[(b * 64 + c) * 2], be = g_gb[(b * 64 + c) * 2 + 1];
        float4 zv = ((const float4*)g_z)[i4];
        float4 xv = ((const float4*)x)[i4];
        float4 ov;
        ov.x = ga * (zv.x - mean) * rstd + be + gelu_f(xv.x);
        ov.y = ga * (zv.y - mean) * rstd + be + gelu_f(xv.y);
        ov.z = ga * (zv.z - mean) * rstd + be + gelu_f(xv.z);
        ov.w = ga * (zv.w - mean) * rstd + be + gelu_f(xv.w);
        ((float4*)out)[i4] = ov;
    }
}

extern "C" void kernel_launch(void* const* d_in, const int* in_sizes, int n_in,
                              void* d_out, int out_size) {
    const float* x       = (const float*)d_in[0];
    const float* t       = (const float*)d_in[1];
    const float* w1r     = (const float*)d_in[2];
    const float* w1i     = (const float*)d_in[3];
    const float* w2r     = (const float*)d_in[4];
    const float* w2i     = (const float*)d_in[5];
    const float* norm1_w = (const float*)d_in[6];
    const float* norm1_b = (const float*)d_in[7];
    const float* mlp_w1  = (const float*)d_in[8];
    const float* mlp_b1  = (const float*)d_in[9];
    const float* mlp_w2  = (const float*)d_in[10];
    const float* mlp_b2  = (const float*)d_in[11];
    const float* gamma_w = (const float*)d_in[12];
    const float* gamma_b = (const float*)d_in[13];
    const float* beta_w  = (const float*)d_in[14];
    const float* beta_b  = (const float*)d_in[15];
    float* out = (float*)d_out;

    cudaFuncSetAttribute(k_fwdW, cudaFuncAttributeMaxDynamicSharedMemorySize, 98304);
    cudaFuncSetAttribute(k_fwdH, cudaFuncAttributeMaxDynamicSharedMemorySize, 65600);
    cudaFuncSetAttribute(k_mix,  cudaFuncAttributeMaxDynamicSharedMemorySize, 65536);
    cudaFuncSetAttribute(k_invW, cudaFuncAttributeMaxDynamicSharedMemorySize, 73728);
    cudaFuncSetAttribute(k_mlp,  cudaFuncAttributeMaxDynamicSharedMemorySize, 58368);

    k_tab<<<1, 256>>>();
    k_film<<<PB, PC>>>(t, gamma_w, gamma_b, beta_w, beta_b);
    k_fwdW<<<NROWS / 64, 256, 98304>>>(x);
    k_fwdH<<<PB * PC, 256, 65600>>>();
    k_mix<<<256, 512, 65536>>>(w1r, w1i, w2r, w2i);
    k_invH<<<PB * PC, 256>>>();
    k_invW<<<PB * PC * 4, 256, 73728>>>();
    k_red1<<<PB, 256>>>();
    k_mlp<<<PB * PH, 256, 58368>>>(x, norm1_w, norm1_b,
                                   mlp_w1, mlp_b1, mlp_w2, mlp_b2);
    k_red2<<<PB, 256>>>();
    k_final<<<8192, 256>>>(x, out);
}

// round 11
// speedup vs baseline: 1.0877x; 1.0877x over previous
#include <cuda_runtime.h>
#include <math.h>

#define PB 8
#define PC 64
#define PH 256
#define PW 256
#define PKX 64
#define PKY 32
#define NROWS (PB*PC*PH)

// ---- scratch (device globals; no runtime allocation) ----
__device__ __align__(16) float  g_T[256*64];
__device__ __align__(16) float  g_cos[256];
__device__ __align__(16) float  g_sin[256];
__device__ __align__(16) float2 g_ct[256];            // (cos, sin) pairs
__device__ __align__(16) float2 g_E[128*64];          // fwdH twiddles E[h][kxp]
__device__ __align__(16) float2 g_X1[PB*PC*PH*PKY];   // after fwd-W  [b,c,h,ky]
__device__ __align__(16) float2 g_XF[PB*PC*PKX*PKY];  // after fwd-H  [b,c,kx',ky]
__device__ __align__(16) float2 g_OF[PB*PC*PKX*PKY];  // after mix
__device__ __align__(16) float2 g_Y1[PB*PC*PKY*PH];   // after inv-H  [b,c,ky,h]
__device__ __align__(16) float  g_y[PB*PC*PH*PW];     // spectral conv out
__device__ __align__(16) float  g_z[PB*PC*PH*PW];     // MLP out
__device__ __align__(16) float  g_p1[PB*PC*4*2];      // per-invW-block partials
__device__ __align__(16) float  g_p2[PB*PH*2];
__device__ __align__(16) float  g_s1[PB*2];
__device__ __align__(16) float  g_s2[PB*2];
__device__ __align__(16) float  g_gb[PB*PC*2];

__device__ __forceinline__ float gelu_f(float v) {
    return 0.5f * v * (1.0f + erff(v * 0.7071067811865476f));
}

// ---- twiddle tables ----
__global__ void k_tab() {
    int tid = threadIdx.x;
    {
        int j = tid;
        double sd, cd;
        sincospi((double)j * (2.0 / 256.0), &sd, &cd);
        g_cos[j] = (float)cd;
        g_sin[j] = (float)sd;
        g_ct[j] = make_float2((float)cd, (float)sd);
        for (int ky = 0; ky < 32; ++ky) {
            int idx = (ky * j) & 255;
            double s2, c2;
            sincospi((double)idx * (2.0 / 256.0), &s2, &c2);
            g_T[j * 64 + 2 * ky]     = (float)c2;
            g_T[j * 64 + 2 * ky + 1] = (float)(-s2);
        }
    }
    for (int i = tid; i < 128 * 64; i += 256) {
        int h = i >> 6, kxp = i & 63;
        int kxm = kxp + ((kxp >= 32) ? 192 : 0);
        int idx = (kxm * h) & 255;
        double s2, c2;
        sincospi((double)idx * (2.0 / 256.0), &s2, &c2);
        g_E[i] = make_float2((float)c2, (float)s2);
    }
}

// ---- FiLM gamma/beta ----
__global__ void k_film(const float* __restrict__ t,
                       const float* __restrict__ gw, const float* __restrict__ gb,
                       const float* __restrict__ bw, const float* __restrict__ bb) {
    int b = blockIdx.x, o = threadIdx.x;
    float g = gb[o], be = bb[o];
    for (int c = 0; c < PC; ++c) {
        float tv = t[b * PC + c];
        g  += gw[o * PC + c] * tv;
        be += bw[o * PC + c] * tv;
    }
    g_gb[(b * PC + o) * 2]     = g;
    g_gb[(b * PC + o) * 2 + 1] = be;
}

// ---- forward DFT along W, radix-2; 64 rows/block, 2r x 8c thread tiles ----
__global__ void __launch_bounds__(256) k_fwdW(const float* __restrict__ x) {
    extern __shared__ char smraw[];
    float2* su = (float2*)smraw;            // [row 64][w<128] (u0,u1)  64KB
    float*  sT = (float*)(smraw + 65536);   // [w<128][64]              32KB
    int tid = threadIdx.x;
    size_t base = (size_t)blockIdx.x * 64 * 256;

    for (int i = tid; i < 2048; i += 256) {
        int row = i >> 5, w4 = (i & 31) * 4;
        float4 a = *(const float4*)&x[base + row * 256 + w4];
        float4 b = *(const float4*)&x[base + row * 256 + w4 + 128];
        float4* d = (float4*)&su[row * 128 + w4];
        d[0] = make_float4(a.x + b.x, a.x - b.x, a.y + b.y, a.y - b.y);
        d[1] = make_float4(a.z + b.z, a.z - b.z, a.w + b.w, a.w - b.w);
    }
    const float4* gT4 = (const float4*)g_T;
    float4* sT4 = (float4*)sT;
    for (int i = tid; i < 2048; i += 256) sT4[i] = gT4[i];
    __syncthreads();

    int r0 = (tid >> 3) * 2;
    int c0 = (tid & 7) * 8;

    float acc[2][8];
#pragma unroll
    for (int r = 0; r < 2; ++r)
#pragma unroll
        for (int u = 0; u < 8; ++u) acc[r][u] = 0.0f;

    const float2* rowA = su + r0 * 128;
    const float2* rowB = rowA + 128;
#pragma unroll 4
    for (int k = 0; k < 128; ++k) {
        float2 ua = rowA[k];
        float2 ub = rowB[k];
        float4 t0 = *(const float4*)&sT[k * 64 + c0];
        float4 t1 = *(const float4*)&sT[k * 64 + c0 + 4];
        acc[0][0] += ua.x * t0.x; acc[0][1] += ua.x * t0.y;
        acc[0][2] += ua.y * t0.z; acc[0][3] += ua.y * t0.w;
        acc[0][4] += ua.x * t1.x; acc[0][5] += ua.x * t1.y;
        acc[0][6] += ua.y * t1.z; acc[0][7] += ua.y * t1.w;
        acc[1][0] += ub.x * t0.x; acc[1][1] += ub.x * t0.y;
        acc[1][2] += ub.y * t0.z; acc[1][3] += ub.y * t0.w;
        acc[1][4] += ub.x * t1.x; acc[1][5] += ub.x * t1.y;
        acc[1][6] += ub.y * t1.z; acc[1][7] += ub.y * t1.w;
    }
    float* go = (float*)g_X1 + (size_t)blockIdx.x * 64 * 64;
#pragma unroll
    for (int r = 0; r < 2; ++r) {
        *(float4*)&go[(r0 + r) * 64 + c0] =
            make_float4(acc[r][0], acc[r][1], acc[r][2], acc[r][3]);
        *(float4*)&go[(r0 + r) * 64 + c0 + 4] =
            make_float4(acc[r][4], acc[r][5], acc[r][6], acc[r][7]);
    }
}

// ---- forward DFT along H, radix-2 over h; ky-split (occupancy) + E via LDG ----
__global__ void __launch_bounds__(256) k_fwdH() {
    extern __shared__ char smraw[];
    float2* sv0 = (float2*)smraw;                    // [h<128][16] sum operand
    float2* sv1 = (float2*)(smraw + 16384 + 32);     // diff operand (skewed)
    int tid = threadIdx.x;
    int bc = blockIdx.x >> 1, kh = blockIdx.x & 1;

    const float4* src = (const float4*)(g_X1 + (size_t)bc * 8192);
    float4* d0 = (float4*)sv0;
    float4* d1 = (float4*)sv1;
    for (int i = tid; i < 1024; i += 256) {
        int h = i >> 3, j = i & 7;
        int s = h * 16 + kh * 8 + j;
        float4 a = src[s];
        float4 b = src[s + 2048];                    // h+128
        d0[i] = make_float4(a.x + b.x, a.y + b.y, a.z + b.z, a.w + b.w);
        d1[i] = make_float4(a.x - b.x, a.y - b.y, a.z - b.z, a.w - b.w);
    }
    __syncthreads();

    int kxp = tid & 63;
    int ky0 = (tid >> 6) * 4;                        // local ky group (4 per thread)
    const float2* sv = (kxp & 1) ? sv1 : sv0;        // kxm parity == kxp parity
    const float2* E = g_E + kxp;

    float2 acc[4];
#pragma unroll
    for (int j = 0; j < 4; ++j) acc[j] = make_float2(0.f, 0.f);

#pragma unroll 4
    for (int h = 0; h < 128; ++h) {
        float2 e = E[h * 64];                        // coalesced LDG, L1/L2-hot
        const float2* row = &sv[h * 16 + ky0];
        float4 vA = *(const float4*)&row[0];
        float4 vB = *(const float4*)&row[2];
        float2 v[4] = { {vA.x,vA.y},{vA.z,vA.w},{vB.x,vB.y},{vB.z,vB.w} };
#pragma unroll
        for (int j = 0; j < 4; ++j) {
            // (xr + i xi)(c - i s)
            acc[j].x += v[j].x * e.x + v[j].y * e.y;
            acc[j].y += v[j].y * e.x - v[j].x * e.y;
        }
    }
    int kyg = kh * 16 + ky0;
    float2* o = g_XF + ((size_t)bc * 64 + kxp) * 32 + kyg;
    *(float4*)&o[0] = make_float4(acc[0].x, acc[0].y, acc[1].x, acc[1].y);
    *(float4*)&o[2] = make_float4(acc[2].x, acc[2].y, acc[3].x, acc[3].y);
}

// ---- per-mode complex channel mixing, ky-split for occupancy ----
__global__ void __launch_bounds__(512)
k_mix(const float* __restrict__ w1r, const float* __restrict__ w1i,
      const float* __restrict__ w2r, const float* __restrict__ w2i) {
    extern __shared__ char smraw[];
    float2* sXF = (float2*)smraw;   // [(b*64+i)*16 + kyl], 8192 float2 = 64KB
    int kxp   = blockIdx.x >> 2;
    int ohalf = (blockIdx.x >> 1) & 1;
    int kh    = blockIdx.x & 1;
    int tid = threadIdx.x;

    for (int i = tid; i < 8192; i += 512) {
        int b = i >> 10, rest = i & 1023, ii = rest >> 4, kk = rest & 15;
        sXF[i] = g_XF[(((size_t)b * PC + ii) * PKX + kxp) * PKY + kh * 16 + kk];
    }
    __syncthreads();

    int o   = ohalf * 32 + (tid >> 4);
    int kyl = tid & 15;
    int ky  = kh * 16 + kyl;
    const float* wr; const float* wi; int kxl;
    if (kxp < 32) { wr = w1r; wi = w1i; kxl = kxp; }
    else          { wr = w2r; wi = w2i; kxl = kxp - 32; }

    float ar[8], ai[8];
#pragma unroll
    for (int b = 0; b < 8; ++b) { ar[b] = 0.0f; ai[b] = 0.0f; }

    const float* wrp = wr + (size_t)o * 1024 + kxl * 32 + ky;
    const float* wip = wi + (size_t)o * 1024 + kxl * 32 + ky;
#pragma unroll 2
    for (int i = 0; i < 64; ++i) {
        float wrv = wrp[(size_t)i * 65536];
        float wiv = wip[(size_t)i * 65536];
#pragma unroll
        for (int b = 0; b < 8; ++b) {
            float2 v = sXF[(b * 64 + i) * 16 + kyl];
            ar[b] += v.x * wrv - v.y * wiv;
            ai[b] += v.x * wiv + v.y * wrv;
        }
    }
#pragma unroll
    for (int b = 0; b < 8; ++b)
        g_OF[(((size_t)b * PC + o) * PKX + kxp) * PKY + ky] = make_float2(ar[b], ai[b]);
}

// ---- inverse DFT along H, radix-2: Se/So over kx parity, emit h and h+128 ----
__global__ void __launch_bounds__(256) k_invH() {
    __shared__ float2 sOF[2048];
    __shared__ float2 ct[256];
    int tid = threadIdx.x, bc = blockIdx.x;

    const float4* src = (const float4*)(g_OF + (size_t)bc * 2048);
    float4* dst = (float4*)sOF;
    for (int i = tid; i < 1024; i += 256) dst[i] = src[i];
    ct[tid] = g_ct[tid];
    __syncthreads();

    int h0  = (tid >> 3) * 4;     // h<128
    int ky0 = (tid & 7) * 4;

    float2 ae[4][4], ao[4][4];
#pragma unroll
    for (int hh = 0; hh < 4; ++hh)
#pragma unroll
        for (int j = 0; j < 4; ++j) {
            ae[hh][j] = make_float2(0.f, 0.f);
            ao[hh][j] = make_float2(0.f, 0.f);
        }

    for (int kxp = 0; kxp < 64; kxp += 2) {
        int kxm = kxp + ((kxp >= 32) ? 192 : 0);
        float2 te[4], to[4];
#pragma unroll
        for (int hh = 0; hh < 4; ++hh) {
            int h = h0 + hh;
            te[hh] = ct[(kxm * h) & 255];
            to[hh] = ct[((kxm + 1) * h) & 255];
        }
        float4 eA = *(const float4*)&sOF[kxp * 32 + ky0];
        float4 eB = *(const float4*)&sOF[kxp * 32 + ky0 + 2];
        float4 oA = *(const float4*)&sOF[(kxp + 1) * 32 + ky0];
        float4 oB = *(const float4*)&sOF[(kxp + 1) * 32 + ky0 + 2];
        float2 ove[4] = { {eA.x, eA.y}, {eA.z, eA.w}, {eB.x, eB.y}, {eB.z, eB.w} };
        float2 ovo[4] = { {oA.x, oA.y}, {oA.z, oA.w}, {oB.x, oB.y}, {oB.z, oB.w} };
#pragma unroll
        for (int hh = 0; hh < 4; ++hh) {
#pragma unroll
            for (int j = 0; j < 4; ++j) {
                ae[hh][j].x += ove[j].x * te[hh].x - ove[j].y * te[hh].y;
                ae[hh][j].y += ove[j].x * te[hh].y + ove[j].y * te[hh].x;
                ao[hh][j].x += ovo[j].x * to[hh].x - ovo[j].y * to[hh].y;
                ao[hh][j].y += ovo[j].x * to[hh].y + ovo[j].y * to[hh].x;
            }
        }
    }
#pragma unroll
    for (int j = 0; j < 4; ++j) {
        float2* out = g_Y1 + (size_t)bc * 8192 + (ky0 + j) * 256 + h0;
#pragma unroll
        for (int hh = 0; hh < 4; hh += 2) {
            *(float4*)&out[hh] = make_float4(
                ae[hh][j].x + ao[hh][j].x,     ae[hh][j].y + ao[hh][j].y,
                ae[hh+1][j].x + ao[hh+1][j].x, ae[hh+1][j].y + ao[hh+1][j].y);
            *(float4*)&out[hh + 128] = make_float4(
                ae[hh][j].x - ao[hh][j].x,     ae[hh][j].y - ao[hh][j].y,
                ae[hh+1][j].x - ao[hh+1][j].x, ae[hh+1][j].y - ao[hh+1][j].y);
        }
    }
}

// ---- inverse rfft along W, radix-2: Se/So over ky parity, emit w and w+128 ----
__global__ void __launch_bounds__(256) k_invW() {
    extern __shared__ char smraw[];
    float2* sY = (float2*)smraw;               // 8192 float2 (64KB)
    float2* sW = (float2*)(smraw + 65536);     // 31*32 float2
    __shared__ float rbuf[16];
    int tid = threadIdx.x;
    int bc = blockIdx.x >> 2, wt = blockIdx.x & 3;
    int w0 = wt * 32;

    const float4* src = (const float4*)(g_Y1 + (size_t)bc * 8192);
    float4* dst = (float4*)sY;
    for (int i = tid; i < 4096; i += 256) dst[i] = src[i];

    const float inv = 1.0f / 65536.0f;
    for (int i = tid; i < 31 * 32; i += 256) {
        int ky = (i >> 5) + 1;
        int w  = w0 + (i & 31);
        int idx = (ky * w) & 255;
        sW[i] = make_float2(2.0f * inv * g_cos[idx], 2.0f * inv * g_sin[idx]);
    }
    __syncthreads();

    int h0  = (tid >> 3) * 8;
    int wth = (tid & 7) * 4;

    float se[8][4], so[8][4], dc[8];
#pragma unroll
    for (int hh = 0; hh < 8; ++hh) {
        dc[hh] = inv * sY[h0 + hh].x;
#pragma unroll
        for (int ww = 0; ww < 4; ++ww) { se[hh][ww] = 0.f; so[hh][ww] = 0.f; }
    }

    for (int ky = 1; ky < 31; ky += 2) {
        {
            float2 av[8], bv[4];
            const float4* ap = (const float4*)&sY[ky * 256 + h0];
#pragma unroll
            for (int u = 0; u < 4; ++u) {
                float4 t1 = ap[u];
                av[2*u] = make_float2(t1.x, t1.y);
                av[2*u+1] = make_float2(t1.z, t1.w);
            }
            const float4* bp = (const float4*)&sW[(ky - 1) * 32 + wth];
            float4 t2 = bp[0], t3 = bp[1];
            bv[0] = make_float2(t2.x, t2.y); bv[1] = make_float2(t2.z, t2.w);
            bv[2] = make_float2(t3.x, t3.y); bv[3] = make_float2(t3.z, t3.w);
#pragma unroll
            for (int hh = 0; hh < 8; ++hh)
#pragma unroll
                for (int ww = 0; ww < 4; ++ww)
                    so[hh][ww] += av[hh].x * bv[ww].x - av[hh].y * bv[ww].y;
        }
        {
            float2 av[8], bv[4];
            const float4* ap = (const float4*)&sY[(ky + 1) * 256 + h0];
#pragma unroll
            for (int u = 0; u < 4; ++u) {
                float4 t1 = ap[u];
                av[2*u] = make_float2(t1.x, t1.y);
                av[2*u+1] = make_float2(t1.z, t1.w);
            }
            const float4* bp = (const float4*)&sW[ky * 32 + wth];
            float4 t2 = bp[0], t3 = bp[1];
            bv[0] = make_float2(t2.x, t2.y); bv[1] = make_float2(t2.z, t2.w);
            bv[2] = make_float2(t3.x, t3.y); bv[3] = make_float2(t3.z, t3.w);
#pragma unroll
            for (int hh = 0; hh < 8; ++hh)
#pragma unroll
                for (int ww = 0; ww < 4; ++ww)
                    se[hh][ww] += av[hh].x * bv[ww].x - av[hh].y * bv[ww].y;
        }
    }
    {
        float2 av[8], bv[4];
        const float4* ap = (const float4*)&sY[31 * 256 + h0];
#pragma unroll
        for (int u = 0; u < 4; ++u) {
            float4 t1 = ap[u];
            av[2*u] = make_float2(t1.x, t1.y);
            av[2*u+1] = make_float2(t1.z, t1.w);
        }
        const float4* bp = (const float4*)&sW[30 * 32 + wth];
        float4 t2 = bp[0], t3 = bp[1];
        bv[0] = make_float2(t2.x, t2.y); bv[1] = make_float2(t2.z, t2.w);
        bv[2] = make_float2(t3.x, t3.y); bv[3] = make_float2(t3.z, t3.w);
#pragma unroll
        for (int hh = 0; hh < 8; ++hh)
#pragma unroll
            for (int ww = 0; ww < 4; ++ww)
                so[hh][ww] += av[hh].x * bv[ww].x - av[hh].y * bv[ww].y;
    }

    float s = 0.0f, s2 = 0.0f;
#pragma unroll
    for (int hh = 0; hh < 8; ++hh) {
        float lo[4], hi[4];
#pragma unroll
        for (int ww = 0; ww < 4; ++ww) {
            lo[ww] = dc[hh] + se[hh][ww] + so[hh][ww];
            hi[ww] = dc[hh] + se[hh][ww] - so[hh][ww];
            s += lo[ww] + hi[ww];
            s2 += lo[ww] * lo[ww] + hi[ww] * hi[ww];
        }
        size_t base = (size_t)bc * 65536 + (size_t)(h0 + hh) * 256 + w0 + wth;
        *(float4*)&g_y[base]       = make_float4(lo[0], lo[1], lo[2], lo[3]);
        *(float4*)&g_y[base + 128] = make_float4(hi[0], hi[1], hi[2], hi[3]);
    }

    for (int off = 16; off > 0; off >>= 1) {
        s  += __shfl_down_sync(0xffffffffu, s,  off);
        s2 += __shfl_down_sync(0xffffffffu, s2, off);
    }
    int lane = tid & 31, wid = tid >> 5;
    if (lane == 0) { rbuf[wid] = s; rbuf[wid + 8] = s2; }
    __syncthreads();
    if (tid == 0) {
        float S = 0.0f, S2 = 0.0f;
        for (int i = 0; i < 8; ++i) { S += rbuf[i]; S2 += rbuf[i + 8]; }
        g_p1[blockIdx.x * 2] = S;
        g_p1[blockIdx.x * 2 + 1] = S2;
    }
}

__global__ void k_red1() {
    __shared__ float rbuf[16];
    int b = blockIdx.x, tid = threadIdx.x;
    float s  = g_p1[(b * 256 + tid) * 2];
    float s2 = g_p1[(b * 256 + tid) * 2 + 1];
    for (int off = 16; off > 0; off >>= 1) {
        s  += __shfl_down_sync(0xffffffffu, s,  off);
        s2 += __shfl_down_sync(0xffffffffu, s2, off);
    }
    int lane = tid & 31, wid = tid >> 5;
    if (lane == 0) { rbuf[wid] = s; rbuf[wid + 8] = s2; }
    __syncthreads();
    if (tid == 0) {
        float S = 0.0f, S2 = 0.0f;
        for (int i = 0; i < 8; ++i) { S += rbuf[i]; S2 += rbuf[i + 8]; }
        float mean = S * (1.0f / 4194304.0f);
        float var  = S2 * (1.0f / 4194304.0f) - mean * mean;
        g_s1[b * 2] = mean;
        g_s1[b * 2 + 1] = rsqrtf(var + 1e-5f);
    }
}

// ---- GN1 apply + residual + gelu + MLP + GN2 partials (W split in halves) ----
__global__ void __launch_bounds__(256) k_mlp(const float* __restrict__ x,
                      const float* __restrict__ nw, const float* __restrict__ nb,
                      const float* __restrict__ w1, const float* __restrict__ b1,
                      const float* __restrict__ w2, const float* __restrict__ b2) {
    extern __shared__ char smraw[];
    float* sy2  = (float*)smraw;        // [c][w]  64*128
    float* sh   = sy2 + 8192;           // [m][w]  32*128
    float* sw1  = sh + 4096;            // [c][m]  64*32
    float* sw2  = sw1 + 2048;           // [m][c]  32*64
    float* sb1  = sw2 + 2048;           // 32
    float* sb2v = sb1 + 32;             // 64
    float* snw  = sb2v + 64;            // 64
    float* snb  = snw + 64;             // 64
    __shared__ float rbuf[16];

    int tid = threadIdx.x;
    int b = blockIdx.x >> 8, h = blockIdx.x & 255;

    for (int i = tid; i < 2048; i += 256) {
        int c = i >> 5, m = i & 31;
        sw1[i] = w1[m * 64 + c];
        int m2 = i >> 6, c2 = i & 63;
        sw2[i] = w2[c2 * 32 + m2];
    }
    if (tid < 64) {
        sb2v[tid] = b2[tid];
        snw[tid] = nw[tid];
        snb[tid] = nb[tid];
        if (tid < 32) sb1[tid] = b1[tid];
    }
    float mean1 = g_s1[b * 2], rstd1 = g_s1[b * 2 + 1];
    __syncthreads();

    int m0 = (tid >> 5) * 4;
    int c0 = (tid >> 5) * 8;
    int wl = (tid & 31) * 4;

    float s = 0.0f, s2 = 0.0f;
    for (int half = 0; half < 2; ++half) {
        int wbase = half * 128;

        for (int i = tid; i < 2048; i += 256) {
            int c = i >> 5, w4 = (i & 31) * 4;
            size_t gid = (size_t)(b * 64 + c) * 65536 + (size_t)h * 256 + wbase + w4;
            float4 yv = *(const float4*)&g_y[gid];
            float4 xv = *(const float4*)&x[gid];
            float a = snw[c] * rstd1, bb = snb[c] - mean1 * rstd1 * snw[c];
            float4 o;
            o.x = gelu_f(yv.x * a + bb + xv.x);
            o.y = gelu_f(yv.y * a + bb + xv.y);
            o.z = gelu_f(yv.z * a + bb + xv.z);
            o.w = gelu_f(yv.w * a + bb + xv.w);
            *(float4*)&sy2[c * 128 + w4] = o;
        }
        __syncthreads();

        {
            float acc[4][4];
#pragma unroll
            for (int mm = 0; mm < 4; ++mm)
#pragma unroll
                for (int ww = 0; ww < 4; ++ww) acc[mm][ww] = 0.0f;
            for (int c = 0; c < 64; ++c) {
                float4 wv = *(const float4*)&sw1[c * 32 + m0];
                float4 yv = *(const float4*)&sy2[c * 128 + wl];
                float wa[4] = { wv.x, wv.y, wv.z, wv.w };
                float yy[4] = { yv.x, yv.y, yv.z, yv.w };
#pragma unroll
                for (int mm = 0; mm < 4; ++mm)
#pragma unroll
                    for (int ww = 0; ww < 4; ++ww) acc[mm][ww] += wa[mm] * yy[ww];
            }
#pragma unroll
            for (int mm = 0; mm < 4; ++mm) {
                float bb = sb1[m0 + mm];
                float4 o;
                o.x = gelu_f(acc[mm][0] + bb);
                o.y = gelu_f(acc[mm][1] + bb);
                o.z = gelu_f(acc[mm][2] + bb);
                o.w = gelu_f(acc[mm][3] + bb);
                *(float4*)&sh[(m0 + mm) * 128 + wl] = o;
            }
        }
        __syncthreads();

        {
            float acc2[8][4];
#pragma unroll
            for (int cc = 0; cc < 8; ++cc)
#pragma unroll
                for (int ww = 0; ww < 4; ++ww) acc2[cc][ww] = 0.0f;
            for (int m = 0; m < 32; ++m) {
                float4 a0 = *(const float4*)&sw2[m * 64 + c0];
                float4 a1 = *(const float4*)&sw2[m * 64 + c0 + 4];
                float4 hv = *(const float4*)&sh[m * 128 + wl];
                float wa[8] = { a0.x, a0.y, a0.z, a0.w, a1.x, a1.y, a1.z, a1.w };
                float hh[4] = { hv.x, hv.y, hv.z, hv.w };
#pragma unroll
                for (int cc = 0; cc < 8; ++cc)
#pragma unroll
                    for (int ww = 0; ww < 4; ++ww) acc2[cc][ww] += wa[cc] * hh[ww];
            }
#pragma unroll
            for (int cc = 0; cc < 8; ++cc) {
                float bb = sb2v[c0 + cc];
                float o[4];
#pragma unroll
                for (int ww = 0; ww < 4; ++ww) {
                    o[ww] = acc2[cc][ww] + bb;
                    s += o[ww];
                    s2 += o[ww] * o[ww];
                }
                size_t gbase = (size_t)(b * 64 + c0 + cc) * 65536 + (size_t)h * 256 + wbase;
                *(float4*)&g_z[gbase + wl] = make_float4(o[0], o[1], o[2], o[3]);
            }
        }
        __syncthreads();
    }

    for (int off = 16; off > 0; off >>= 1) {
        s  += __shfl_down_sync(0xffffffffu, s,  off);
        s2 += __shfl_down_sync(0xffffffffu, s2, off);
    }
    int lane = tid & 31, widx = tid >> 5;
    if (lane == 0) { rbuf[widx] = s; rbuf[widx + 8] = s2; }
    __syncthreads();
    if (tid == 0) {
        float S = 0.0f, S2 = 0.0f;
        for (int i = 0; i < 8; ++i) { S += rbuf[i]; S2 += rbuf[i + 8]; }
        g_p2[blockIdx.x * 2] = S;
        g_p2[blockIdx.x * 2 + 1] = S2;
    }
}

__global__ void k_red2() {
    __shared__ float rbuf[16];
    int b = blockIdx.x, tid = threadIdx.x;
    float s  = g_p2[(b * 256 + tid) * 2];
    float s2 = g_p2[(b * 256 + tid) * 2 + 1];
    for (int off = 16; off > 0; off >>= 1) {
        s  += __shfl_down_sync(0xffffffffu, s,  off);
        s2 += __shfl_down_sync(0xffffffffu, s2, off);
    }
    int lane = tid & 31, wid = tid >> 5;
    if (lane == 0) { rbuf[wid] = s; rbuf[wid + 8] = s2; }
    __syncthreads();
    if (tid == 0) {
        float S = 0.0f, S2 = 0.0f;
        for (int i = 0; i < 8; ++i) { S += rbuf[i]; S2 += rbuf[i + 8]; }
        float mean = S * (1.0f / 4194304.0f);
        float var  = S2 * (1.0f / 4194304.0f) - mean * mean;
        g_s2[b * 2] = mean;
        g_s2[b * 2 + 1] = rsqrtf(var + 1e-5f);
    }
}

// ---- final: FiLM GN + skip2 ----
__global__ void k_final(const float* __restrict__ x, float* __restrict__ out) {
    int gi = blockIdx.x * 256 + threadIdx.x;
#pragma unroll
    for (int u = 0; u < 4; ++u) {
        size_t i4 = (size_t)gi + (size_t)u * 2097152;
        size_t e = i4 * 4;
        int b = (int)(e >> 22);
        int c = (int)((e >> 16) & 63);
        float mean = g_s2[b * 2], rstd = g_s2[b * 2 + 1];
        float ga = g_gb[(b * 64 + c) * 2], be = g_gb[(b * 64 + c) * 2 + 1];
        float4 zv = ((const float4*)g_z)[i4];
        float4 xv = ((const float4*)x)[i4];
        float4 ov;
        ov.x = ga * (zv.x - mean) * rstd + be + gelu_f(xv.x);
        ov.y = ga * (zv.y - mean) * rstd + be + gelu_f(xv.y);
        ov.z = ga * (zv.z - mean) * rstd + be + gelu_f(xv.z);
        ov.w = ga * (zv.w - mean) * rstd + be + gelu_f(xv.w);
        ((float4*)out)[i4] = ov;
    }
}

extern "C" void kernel_launch(void* const* d_in, const int* in_sizes, int n_in,
                              void* d_out, int out_size) {
    const float* x       = (const float*)d_in[0];
    const float* t       = (const float*)d_in[1];
    const float* w1r     = (const float*)d_in[2];
    const float* w1i     = (const float*)d_in[3];
    const float* w2r     = (const float*)d_in[4];
    const float* w2i     = (const float*)d_in[5];
    const float* norm1_w = (const float*)d_in[6];
    const float* norm1_b = (const float*)d_in[7];
    const float* mlp_w1  = (const float*)d_in[8];
    const float* mlp_b1  = (const float*)d_in[9];
    const float* mlp_w2  = (const float*)d_in[10];
    const float* mlp_b2  = (const float*)d_in[11];
    const float* gamma_w = (const float*)d_in[12];
    const float* gamma_b = (const float*)d_in[13];
    const float* beta_w  = (const float*)d_in[14];
    const float* beta_b  = (const float*)d_in[15];
    float* out = (float*)d_out;

    cudaFuncSetAttribute(k_fwdW, cudaFuncAttributeMaxDynamicSharedMemorySize, 98304);
    cudaFuncSetAttribute(k_fwdH, cudaFuncAttributeMaxDynamicSharedMemorySize, 32800);
    cudaFuncSetAttribute(k_mix,  cudaFuncAttributeMaxDynamicSharedMemorySize, 65536);
    cudaFuncSetAttribute(k_invW, cudaFuncAttributeMaxDynamicSharedMemorySize, 73728);
    cudaFuncSetAttribute(k_mlp,  cudaFuncAttributeMaxDynamicSharedMemorySize, 66432);

    k_tab<<<1, 256>>>();
    k_film<<<PB, PC>>>(t, gamma_w, gamma_b, beta_w, beta_b);
    k_fwdW<<<NROWS / 64, 256, 98304>>>(x);
    k_fwdH<<<PB * PC * 2, 256, 32800>>>();
    k_mix<<<256, 512, 65536>>>(w1r, w1i, w2r, w2i);
    k_invH<<<PB * PC, 256>>>();
    k_invW<<<PB * PC * 4, 256, 73728>>>();
    k_red1<<<PB, 256>>>();
    k_mlp<<<PB * PH, 256, 66432>>>(x, norm1_w, norm1_b,
                                   mlp_w1, mlp_b1, mlp_w2, mlp_b2);
    k_red2<<<PB, 256>>>();
    k_final<<<8192, 256>>>(x, out);
}

// round 12
// speedup vs baseline: 1.2949x; 1.1906x over previous
#include <cuda_runtime.h>
#include <math.h>

#define PB 8
#define PC 64
#define PH 256
#define PW 256
#define PKX 64
#define PKY 32
#define NROWS (PB*PC*PH)

// ---- scratch (device globals; no runtime allocation) ----
__device__ __align__(16) float  g_T[256*64];
__device__ __align__(16) float  g_cos[256];
__device__ __align__(16) float  g_sin[256];
__device__ __align__(16) float2 g_ct[256];            // (cos, sin) pairs
__device__ __align__(16) float2 g_E[128*64];          // fwdH twiddles E[h][kxp]
__device__ __align__(16) float2 g_X1[PB*PC*PH*PKY];   // after fwd-W  [b,c,h,ky]
__device__ __align__(16) float2 g_XF[PB*PC*PKX*PKY];  // after fwd-H  [b,c,kx',ky]
__device__ __align__(16) float2 g_OF[PB*PC*PKX*PKY];  // after mix
__device__ __align__(16) float2 g_Y1[PB*PC*PKY*PH];   // after inv-H  [b,c,ky,h]
__device__ __align__(16) float  g_y[PB*PC*PH*PW];     // spectral conv out
__device__ __align__(16) float  g_z[PB*PC*PH*PW];     // MLP out
__device__ __align__(16) float  g_p1[PB*PC*4*2];      // per-invW-block partials
__device__ __align__(16) float  g_p2[PB*PH*2];
__device__ __align__(16) float  g_s1[PB*2];
__device__ __align__(16) float  g_s2[PB*2];
__device__ __align__(16) float  g_gb[PB*PC*2];

__device__ __forceinline__ float gelu_f(float v) {
    return 0.5f * v * (1.0f + erff(v * 0.7071067811865476f));
}

// ---- twiddle tables: fully parallel grid-stride (was 1-block serial!) ----
// item layout: [0, 8192)        -> g_T[j][2*ky..2*ky+1], j=i>>5, ky=i&31
//              [8192, 8448)     -> g_cos/g_sin/g_ct[j], j=i-8192
//              [8448, 16640)    -> g_E[h][kxp], h=(i-8448)>>6, kxp=(i-8448)&63
__global__ void k_tab() {
    int i = blockIdx.x * blockDim.x + threadIdx.x;
    if (i < 8192) {
        int j = i >> 5, ky = i & 31;
        int idx = (ky * j) & 255;
        double s2, c2;
        sincospi((double)idx * (2.0 / 256.0), &s2, &c2);
        g_T[j * 64 + 2 * ky]     = (float)c2;
        g_T[j * 64 + 2 * ky + 1] = (float)(-s2);
    } else if (i < 8448) {
        int j = i - 8192;
        double sd, cd;
        sincospi((double)j * (2.0 / 256.0), &sd, &cd);
        g_cos[j] = (float)cd;
        g_sin[j] = (float)sd;
        g_ct[j] = make_float2((float)cd, (float)sd);
    } else if (i < 16640) {
        int k = i - 8448;
        int h = k >> 6, kxp = k & 63;
        int kxm = kxp + ((kxp >= 32) ? 192 : 0);
        int idx = (kxm * h) & 255;
        double s2, c2;
        sincospi((double)idx * (2.0 / 256.0), &s2, &c2);
        g_E[k] = make_float2((float)c2, (float)s2);
    }
}

// ---- FiLM gamma/beta ----
__global__ void k_film(const float* __restrict__ t,
                       const float* __restrict__ gw, const float* __restrict__ gb,
                       const float* __restrict__ bw, const float* __restrict__ bb) {
    int b = blockIdx.x, o = threadIdx.x;
    float g = gb[o], be = bb[o];
    for (int c = 0; c < PC; ++c) {
        float tv = t[b * PC + c];
        g  += gw[o * PC + c] * tv;
        be += bw[o * PC + c] * tv;
    }
    g_gb[(b * PC + o) * 2]     = g;
    g_gb[(b * PC + o) * 2 + 1] = be;
}

// ---- forward DFT along W, radix-2; 64 rows/block, 2r x 8c thread tiles ----
__global__ void __launch_bounds__(256) k_fwdW(const float* __restrict__ x) {
    extern __shared__ char smraw[];
    float2* su = (float2*)smraw;            // [row 64][w<128] (u0,u1)  64KB
    float*  sT = (float*)(smraw + 65536);   // [w<128][64]              32KB
    int tid = threadIdx.x;
    size_t base = (size_t)blockIdx.x * 64 * 256;

    for (int i = tid; i < 2048; i += 256) {
        int row = i >> 5, w4 = (i & 31) * 4;
        float4 a = *(const float4*)&x[base + row * 256 + w4];
        float4 b = *(const float4*)&x[base + row * 256 + w4 + 128];
        float4* d = (float4*)&su[row * 128 + w4];
        d[0] = make_float4(a.x + b.x, a.x - b.x, a.y + b.y, a.y - b.y);
        d[1] = make_float4(a.z + b.z, a.z - b.z, a.w + b.w, a.w - b.w);
    }
    const float4* gT4 = (const float4*)g_T;
    float4* sT4 = (float4*)sT;
    for (int i = tid; i < 2048; i += 256) sT4[i] = gT4[i];
    __syncthreads();

    int r0 = (tid >> 3) * 2;
    int c0 = (tid & 7) * 8;

    float acc[2][8];
#pragma unroll
    for (int r = 0; r < 2; ++r)
#pragma unroll
        for (int u = 0; u < 8; ++u) acc[r][u] = 0.0f;

    const float2* rowA = su + r0 * 128;
    const float2* rowB = rowA + 128;
#pragma unroll 4
    for (int k = 0; k < 128; ++k) {
        float2 ua = rowA[k];
        float2 ub = rowB[k];
        float4 t0 = *(const float4*)&sT[k * 64 + c0];
        float4 t1 = *(const float4*)&sT[k * 64 + c0 + 4];
        acc[0][0] += ua.x * t0.x; acc[0][1] += ua.x * t0.y;
        acc[0][2] += ua.y * t0.z; acc[0][3] += ua.y * t0.w;
        acc[0][4] += ua.x * t1.x; acc[0][5] += ua.x * t1.y;
        acc[0][6] += ua.y * t1.z; acc[0][7] += ua.y * t1.w;
        acc[1][0] += ub.x * t0.x; acc[1][1] += ub.x * t0.y;
        acc[1][2] += ub.y * t0.z; acc[1][3] += ub.y * t0.w;
        acc[1][4] += ub.x * t1.x; acc[1][5] += ub.x * t1.y;
        acc[1][6] += ub.y * t1.z; acc[1][7] += ub.y * t1.w;
    }
    float* go = (float*)g_X1 + (size_t)blockIdx.x * 64 * 64;
#pragma unroll
    for (int r = 0; r < 2; ++r) {
        *(float4*)&go[(r0 + r) * 64 + c0] =
            make_float4(acc[r][0], acc[r][1], acc[r][2], acc[r][3]);
        *(float4*)&go[(r0 + r) * 64 + c0 + 4] =
            make_float4(acc[r][4], acc[r][5], acc[r][6], acc[r][7]);
    }
}

// ---- forward DFT along H, radix-2 over h; ky-split (occupancy) + E via LDG ----
__global__ void __launch_bounds__(256) k_fwdH() {
    extern __shared__ char smraw[];
    float2* sv0 = (float2*)smraw;                    // [h<128][16] sum operand
    float2* sv1 = (float2*)(smraw + 16384 + 32);     // diff operand (skewed)
    int tid = threadIdx.x;
    int bc = blockIdx.x >> 1, kh = blockIdx.x & 1;

    const float4* src = (const float4*)(g_X1 + (size_t)bc * 8192);
    float4* d0 = (float4*)sv0;
    float4* d1 = (float4*)sv1;
    for (int i = tid; i < 1024; i += 256) {
        int h = i >> 3, j = i & 7;
        int s = h * 16 + kh * 8 + j;
        float4 a = src[s];
        float4 b = src[s + 2048];                    // h+128
        d0[i] = make_float4(a.x + b.x, a.y + b.y, a.z + b.z, a.w + b.w);
        d1[i] = make_float4(a.x - b.x, a.y - b.y, a.z - b.z, a.w - b.w);
    }
    __syncthreads();

    int kxp = tid & 63;
    int ky0 = (tid >> 6) * 4;                        // local ky group (4 per thread)
    const float2* sv = (kxp & 1) ? sv1 : sv0;        // kxm parity == kxp parity
    const float2* E = g_E + kxp;

    float2 acc[4];
#pragma unroll
    for (int j = 0; j < 4; ++j) acc[j] = make_float2(0.f, 0.f);

#pragma unroll 4
    for (int h = 0; h < 128; ++h) {
        float2 e = E[h * 64];                        // coalesced LDG, L1/L2-hot
        const float2* row = &sv[h * 16 + ky0];
        float4 vA = *(const float4*)&row[0];
        float4 vB = *(const float4*)&row[2];
        float2 v[4] = { {vA.x,vA.y},{vA.z,vA.w},{vB.x,vB.y},{vB.z,vB.w} };
#pragma unroll
        for (int j = 0; j < 4; ++j) {
            // (xr + i xi)(c - i s)
            acc[j].x += v[j].x * e.x + v[j].y * e.y;
            acc[j].y += v[j].y * e.x - v[j].x * e.y;
        }
    }
    int kyg = kh * 16 + ky0;
    float2* o = g_XF + ((size_t)bc * 64 + kxp) * 32 + kyg;
    *(float4*)&o[0] = make_float4(acc[0].x, acc[0].y, acc[1].x, acc[1].y);
    *(float4*)&o[2] = make_float4(acc[2].x, acc[2].y, acc[3].x, acc[3].y);
}

// ---- per-mode complex channel mixing, ky-split for occupancy ----
__global__ void __launch_bounds__(512)
k_mix(const float* __restrict__ w1r, const float* __restrict__ w1i,
      const float* __restrict__ w2r, const float* __restrict__ w2i) {
    extern __shared__ char smraw[];
    float2* sXF = (float2*)smraw;   // [(b*64+i)*16 + kyl], 8192 float2 = 64KB
    int kxp   = blockIdx.x >> 2;
    int ohalf = (blockIdx.x >> 1) & 1;
    int kh    = blockIdx.x & 1;
    int tid = threadIdx.x;

    for (int i = tid; i < 8192; i += 512) {
        int b = i >> 10, rest = i & 1023, ii = rest >> 4, kk = rest & 15;
        sXF[i] = g_XF[(((size_t)b * PC + ii) * PKX + kxp) * PKY + kh * 16 + kk];
    }
    __syncthreads();

    int o   = ohalf * 32 + (tid >> 4);
    int kyl = tid & 15;
    int ky  = kh * 16 + kyl;
    const float* wr; const float* wi; int kxl;
    if (kxp < 32) { wr = w1r; wi = w1i; kxl = kxp; }
    else          { wr = w2r; wi = w2i; kxl = kxp - 32; }

    float ar[8], ai[8];
#pragma unroll
    for (int b = 0; b < 8; ++b) { ar[b] = 0.0f; ai[b] = 0.0f; }

    const float* wrp = wr + (size_t)o * 1024 + kxl * 32 + ky;
    const float* wip = wi + (size_t)o * 1024 + kxl * 32 + ky;
#pragma unroll 2
    for (int i = 0; i < 64; ++i) {
        float wrv = wrp[(size_t)i * 65536];
        float wiv = wip[(size_t)i * 65536];
#pragma unroll
        for (int b = 0; b < 8; ++b) {
            float2 v = sXF[(b * 64 + i) * 16 + kyl];
            ar[b] += v.x * wrv - v.y * wiv;
            ai[b] += v.x * wiv + v.y * wrv;
        }
    }
#pragma unroll
    for (int b = 0; b < 8; ++b)
        g_OF[(((size_t)b * PC + o) * PKX + kxp) * PKY + ky] = make_float2(ar[b], ai[b]);
}

// ---- inverse DFT along H, radix-2: Se/So over kx parity, emit h and h+128 ----
__global__ void __launch_bounds__(256) k_invH() {
    __shared__ float2 sOF[2048];
    __shared__ float2 ct[256];
    int tid = threadIdx.x, bc = blockIdx.x;

    const float4* src = (const float4*)(g_OF + (size_t)bc * 2048);
    float4* dst = (float4*)sOF;
    for (int i = tid; i < 1024; i += 256) dst[i] = src[i];
    ct[tid] = g_ct[tid];
    __syncthreads();

    int h0  = (tid >> 3) * 4;     // h<128
    int ky0 = (tid & 7) * 4;

    float2 ae[4][4], ao[4][4];
#pragma unroll
    for (int hh = 0; hh < 4; ++hh)
#pragma unroll
        for (int j = 0; j < 4; ++j) {
            ae[hh][j] = make_float2(0.f, 0.f);
            ao[hh][j] = make_float2(0.f, 0.f);
        }

    for (int kxp = 0; kxp < 64; kxp += 2) {
        int kxm = kxp + ((kxp >= 32) ? 192 : 0);
        float2 te[4], to[4];
#pragma unroll
        for (int hh = 0; hh < 4; ++hh) {
            int h = h0 + hh;
            te[hh] = ct[(kxm * h) & 255];
            to[hh] = ct[((kxm + 1) * h) & 255];
        }
        float4 eA = *(const float4*)&sOF[kxp * 32 + ky0];
        float4 eB = *(const float4*)&sOF[kxp * 32 + ky0 + 2];
        float4 oA = *(const float4*)&sOF[(kxp + 1) * 32 + ky0];
        float4 oB = *(const float4*)&sOF[(kxp + 1) * 32 + ky0 + 2];
        float2 ove[4] = { {eA.x, eA.y}, {eA.z, eA.w}, {eB.x, eB.y}, {eB.z, eB.w} };
        float2 ovo[4] = { {oA.x, oA.y}, {oA.z, oA.w}, {oB.x, oB.y}, {oB.z, oB.w} };
#pragma unroll
        for (int hh = 0; hh < 4; ++hh) {
#pragma unroll
            for (int j = 0; j < 4; ++j) {
                ae[hh][j].x += ove[j].x * te[hh].x - ove[j].y * te[hh].y;
                ae[hh][j].y += ove[j].x * te[hh].y + ove[j].y * te[hh].x;
                ao[hh][j].x += ovo[j].x * to[hh].x - ovo[j].y * to[hh].y;
                ao[hh][j].y += ovo[j].x * to[hh].y + ovo[j].y * to[hh].x;
            }
        }
    }
#pragma unroll
    for (int j = 0; j < 4; ++j) {
        float2* out = g_Y1 + (size_t)bc * 8192 + (ky0 + j) * 256 + h0;
#pragma unroll
        for (int hh = 0; hh < 4; hh += 2) {
            *(float4*)&out[hh] = make_float4(
                ae[hh][j].x + ao[hh][j].x,     ae[hh][j].y + ao[hh][j].y,
                ae[hh+1][j].x + ao[hh+1][j].x, ae[hh+1][j].y + ao[hh+1][j].y);
            *(float4*)&out[hh + 128] = make_float4(
                ae[hh][j].x - ao[hh][j].x,     ae[hh][j].y - ao[hh][j].y,
                ae[hh+1][j].x - ao[hh+1][j].x, ae[hh+1][j].y - ao[hh+1][j].y);
        }
    }
}

// ---- inverse rfft along W, radix-2: Se/So over ky parity, emit w and w+128 ----
__global__ void __launch_bounds__(256) k_invW() {
    extern __shared__ char smraw[];
    float2* sY = (float2*)smraw;               // 8192 float2 (64KB)
    float2* sW = (float2*)(smraw + 65536);     // 31*32 float2
    __shared__ float rbuf[16];
    int tid = threadIdx.x;
    int bc = blockIdx.x >> 2, wt = blockIdx.x & 3;
    int w0 = wt * 32;

    const float4* src = (const float4*)(g_Y1 + (size_t)bc * 8192);
    float4* dst = (float4*)sY;
    for (int i = tid; i < 4096; i += 256) dst[i] = src[i];

    const float inv = 1.0f / 65536.0f;
    for (int i = tid; i < 31 * 32; i += 256) {
        int ky = (i >> 5) + 1;
        int w  = w0 + (i & 31);
        int idx = (ky * w) & 255;
        sW[i] = make_float2(2.0f * inv * g_cos[idx], 2.0f * inv * g_sin[idx]);
    }
    __syncthreads();

    int h0  = (tid >> 3) * 8;
    int wth = (tid & 7) * 4;

    float se[8][4], so[8][4], dc[8];
#pragma unroll
    for (int hh = 0; hh < 8; ++hh) {
        dc[hh] = inv * sY[h0 + hh].x;
#pragma unroll
        for (int ww = 0; ww < 4; ++ww) { se[hh][ww] = 0.f; so[hh][ww] = 0.f; }
    }

    for (int ky = 1; ky < 31; ky += 2) {
        {
            float2 av[8], bv[4];
            const float4* ap = (const float4*)&sY[ky * 256 + h0];
#pragma unroll
            for (int u = 0; u < 4; ++u) {
                float4 t1 = ap[u];
                av[2*u] = make_float2(t1.x, t1.y);
                av[2*u+1] = make_float2(t1.z, t1.w);
            }
            const float4* bp = (const float4*)&sW[(ky - 1) * 32 + wth];
            float4 t2 = bp[0], t3 = bp[1];
            bv[0] = make_float2(t2.x, t2.y); bv[1] = make_float2(t2.z, t2.w);
            bv[2] = make_float2(t3.x, t3.y); bv[3] = make_float2(t3.z, t3.w);
#pragma unroll
            for (int hh = 0; hh < 8; ++hh)
#pragma unroll
                for (int ww = 0; ww < 4; ++ww)
                    so[hh][ww] += av[hh].x * bv[ww].x - av[hh].y * bv[ww].y;
        }
        {
            float2 av[8], bv[4];
            const float4* ap = (const float4*)&sY[(ky + 1) * 256 + h0];
#pragma unroll
            for (int u = 0; u < 4; ++u) {
                float4 t1 = ap[u];
                av[2*u] = make_float2(t1.x, t1.y);
                av[2*u+1] = make_float2(t1.z, t1.w);
            }
            const float4* bp = (const float4*)&sW[ky * 32 + wth];
            float4 t2 = bp[0], t3 = bp[1];
            bv[0] = make_float2(t2.x, t2.y); bv[1] = make_float2(t2.z, t2.w);
            bv[2] = make_float2(t3.x, t3.y); bv[3] = make_float2(t3.z, t3.w);
#pragma unroll
            for (int hh = 0; hh < 8; ++hh)
#pragma unroll
                for (int ww = 0; ww < 4; ++ww)
                    se[hh][ww] += av[hh].x * bv[ww].x - av[hh].y * bv[ww].y;
        }
    }
    {
        float2 av[8], bv[4];
        const float4* ap = (const float4*)&sY[31 * 256 + h0];
#pragma unroll
        for (int u = 0; u < 4; ++u) {
            float4 t1 = ap[u];
            av[2*u] = make_float2(t1.x, t1.y);
            av[2*u+1] = make_float2(t1.z, t1.w);
        }
        const float4* bp = (const float4*)&sW[30 * 32 + wth];
        float4 t2 = bp[0], t3 = bp[1];
        bv[0] = make_float2(t2.x, t2.y); bv[1] = make_float2(t2.z, t2.w);
        bv[2] = make_float2(t3.x, t3.y); bv[3] = make_float2(t3.z, t3.w);
#pragma unroll
        for (int hh = 0; hh < 8; ++hh)
#pragma unroll
            for (int ww = 0; ww < 4; ++ww)
                so[hh][ww] += av[hh].x * bv[ww].x - av[hh].y * bv[ww].y;
    }

    float s = 0.0f, s2 = 0.0f;
#pragma unroll
    for (int hh = 0; hh < 8; ++hh) {
        float lo[4], hi[4];
#pragma unroll
        for (int ww = 0; ww < 4; ++ww) {
            lo[ww] = dc[hh] + se[hh][ww] + so[hh][ww];
            hi[ww] = dc[hh] + se[hh][ww] - so[hh][ww];
            s += lo[ww] + hi[ww];
            s2 += lo[ww] * lo[ww] + hi[ww] * hi[ww];
        }
        size_t base = (size_t)bc * 65536 + (size_t)(h0 + hh) * 256 + w0 + wth;
        *(float4*)&g_y[base]       = make_float4(lo[0], lo[1], lo[2], lo[3]);
        *(float4*)&g_y[base + 128] = make_float4(hi[0], hi[1], hi[2], hi[3]);
    }

    for (int off = 16; off > 0; off >>= 1) {
        s  += __shfl_down_sync(0xffffffffu, s,  off);
        s2 += __shfl_down_sync(0xffffffffu, s2, off);
    }
    int lane = tid & 31, wid = tid >> 5;
    if (lane == 0) { rbuf[wid] = s; rbuf[wid + 8] = s2; }
    __syncthreads();
    if (tid == 0) {
        float S = 0.0f, S2 = 0.0f;
        for (int i = 0; i < 8; ++i) { S += rbuf[i]; S2 += rbuf[i + 8]; }
        g_p1[blockIdx.x * 2] = S;
        g_p1[blockIdx.x * 2 + 1] = S2;
    }
}

__global__ void k_red1() {
    __shared__ float rbuf[16];
    int b = blockIdx.x, tid = threadIdx.x;
    float s  = g_p1[(b * 256 + tid) * 2];
    float s2 = g_p1[(b * 256 + tid) * 2 + 1];
    for (int off = 16; off > 0; off >>= 1) {
        s  += __shfl_down_sync(0xffffffffu, s,  off);
        s2 += __shfl_down_sync(0xffffffffu, s2, off);
    }
    int lane = tid & 31, wid = tid >> 5;
    if (lane == 0) { rbuf[wid] = s; rbuf[wid + 8] = s2; }
    __syncthreads();
    if (tid == 0) {
        float S = 0.0f, S2 = 0.0f;
        for (int i = 0; i < 8; ++i) { S += rbuf[i]; S2 += rbuf[i + 8]; }
        float mean = S * (1.0f / 4194304.0f);
        float var  = S2 * (1.0f / 4194304.0f) - mean * mean;
        g_s1[b * 2] = mean;
        g_s1[b * 2 + 1] = rsqrtf(var + 1e-5f);
    }
}

// ---- GN1 apply + residual + gelu + MLP + GN2 partials (W split in halves) ----
__global__ void __launch_bounds__(256) k_mlp(const float* __restrict__ x,
                      const float* __restrict__ nw, const float* __restrict__ nb,
                      const float* __restrict__ w1, const float* __restrict__ b1,
                      const float* __restrict__ w2, const float* __restrict__ b2) {
    extern __shared__ char smraw[];
    float* sy2  = (float*)smraw;        // [c][w]  64*128
    float* sh   = sy2 + 8192;           // [m][w]  32*128
    float* sw1  = sh + 4096;            // [c][m]  64*32
    float* sw2  = sw1 + 2048;           // [m][c]  32*64
    float* sb1  = sw2 + 2048;           // 32
    float* sb2v = sb1 + 32;             // 64
    float* snw  = sb2v + 64;            // 64
    float* snb  = snw + 64;             // 64
    __shared__ float rbuf[16];

    int tid = threadIdx.x;
    int b = blockIdx.x >> 8, h = blockIdx.x & 255;

    for (int i = tid; i < 2048; i += 256) {
        int c = i >> 5, m = i & 31;
        sw1[i] = w1[m * 64 + c];
        int m2 = i >> 6, c2 = i & 63;
        sw2[i] = w2[c2 * 32 + m2];
    }
    if (tid < 64) {
        sb2v[tid] = b2[tid];
        snw[tid] = nw[tid];
        snb[tid] = nb[tid];
        if (tid < 32) sb1[tid] = b1[tid];
    }
    float mean1 = g_s1[b * 2], rstd1 = g_s1[b * 2 + 1];
    __syncthreads();

    int m0 = (tid >> 5) * 4;
    int c0 = (tid >> 5) * 8;
    int wl = (tid & 31) * 4;

    float s = 0.0f, s2 = 0.0f;
    for (int half = 0; half < 2; ++half) {
        int wbase = half * 128;

        for (int i = tid; i < 2048; i += 256) {
            int c = i >> 5, w4 = (i & 31) * 4;
            size_t gid = (size_t)(b * 64 + c) * 65536 + (size_t)h * 256 + wbase + w4;
            float4 yv = *(const float4*)&g_y[gid];
            float4 xv = *(const float4*)&x[gid];
            float a = snw[c] * rstd1, bb = snb[c] - mean1 * rstd1 * snw[c];
            float4 o;
            o.x = gelu_f(yv.x * a + bb + xv.x);
            o.y = gelu_f(yv.y * a + bb + xv.y);
            o.z = gelu_f(yv.z * a + bb + xv.z);
            o.w = gelu_f(yv.w * a + bb + xv.w);
            *(float4*)&sy2[c * 128 + w4] = o;
        }
        __syncthreads();

        {
            float acc[4][4];
#pragma unroll
            for (int mm = 0; mm < 4; ++mm)
#pragma unroll
                for (int ww = 0; ww < 4; ++ww) acc[mm][ww] = 0.0f;
            for (int c = 0; c < 64; ++c) {
                float4 wv = *(const float4*)&sw1[c * 32 + m0];
                float4 yv = *(const float4*)&sy2[c * 128 + wl];
                float wa[4] = { wv.x, wv.y, wv.z, wv.w };
                float yy[4] = { yv.x, yv.y, yv.z, yv.w };
#pragma unroll
                for (int mm = 0; mm < 4; ++mm)
#pragma unroll
                    for (int ww = 0; ww < 4; ++ww) acc[mm][ww] += wa[mm] * yy[ww];
            }
#pragma unroll
            for (int mm = 0; mm < 4; ++mm) {
                float bb = sb1[m0 + mm];
                float4 o;
                o.x = gelu_f(acc[mm][0] + bb);
                o.y = gelu_f(acc[mm][1] + bb);
                o.z = gelu_f(acc[mm][2] + bb);
                o.w = gelu_f(acc[mm][3] + bb);
                *(float4*)&sh[(m0 + mm) * 128 + wl] = o;
            }
        }
        __syncthreads();

        {
            float acc2[8][4];
#pragma unroll
            for (int cc = 0; cc < 8; ++cc)
#pragma unroll
                for (int ww = 0; ww < 4; ++ww) acc2[cc][ww] = 0.0f;
            for (int m = 0; m < 32; ++m) {
                float4 a0 = *(const float4*)&sw2[m * 64 + c0];
                float4 a1 = *(const float4*)&sw2[m * 64 + c0 + 4];
                float4 hv = *(const float4*)&sh[m * 128 + wl];
                float wa[8] = { a0.x, a0.y, a0.z, a0.w, a1.x, a1.y, a1.z, a1.w };
                float hh[4] = { hv.x, hv.y, hv.z, hv.w };
#pragma unroll
                for (int cc = 0; cc < 8; ++cc)
#pragma unroll
                    for (int ww = 0; ww < 4; ++ww) acc2[cc][ww] += wa[cc] * hh[ww];
            }
#pragma unroll
            for (int cc = 0; cc < 8; ++cc) {
                float bb = sb2v[c0 + cc];
                float o[4];
#pragma unroll
                for (int ww = 0; ww < 4; ++ww) {
                    o[ww] = acc2[cc][ww] + bb;
                    s += o[ww];
                    s2 += o[ww] * o[ww];
                }
                size_t gbase = (size_t)(b * 64 + c0 + cc) * 65536 + (size_t)h * 256 + wbase;
                *(float4*)&g_z[gbase + wl] = make_float4(o[0], o[1], o[2], o[3]);
            }
        }
        __syncthreads();
    }

    for (int off = 16; off > 0; off >>= 1) {
        s  += __shfl_down_sync(0xffffffffu, s,  off);
        s2 += __shfl_down_sync(0xffffffffu, s2, off);
    }
    int lane = tid & 31, widx = tid >> 5;
    if (lane == 0) { rbuf[widx] = s; rbuf[widx + 8] = s2; }
    __syncthreads();
    if (tid == 0) {
        float S = 0.0f, S2 = 0.0f;
        for (int i = 0; i < 8; ++i) { S += rbuf[i]; S2 += rbuf[i + 8]; }
        g_p2[blockIdx.x * 2] = S;
        g_p2[blockIdx.x * 2 + 1] = S2;
    }
}

__global__ void k_red2() {
    __shared__ float rbuf[16];
    int b = blockIdx.x, tid = threadIdx.x;
    float s  = g_p2[(b * 256 + tid) * 2];
    float s2 = g_p2[(b * 256 + tid) * 2 + 1];
    for (int off = 16; off > 0; off >>= 1) {
        s  += __shfl_down_sync(0xffffffffu, s,  off);
        s2 += __shfl_down_sync(0xffffffffu, s2, off);
    }
    int lane = tid & 31, wid = tid >> 5;
    if (lane == 0) { rbuf[wid] = s; rbuf[wid + 8] = s2; }
    __syncthreads();
    if (tid == 0) {
        float S = 0.0f, S2 = 0.0f;
        for (int i = 0; i < 8; ++i) { S += rbuf[i]; S2 += rbuf[i + 8]; }
        float mean = S * (1.0f / 4194304.0f);
        float var  = S2 * (1.0f / 4194304.0f) - mean * mean;
        g_s2[b * 2] = mean;
        g_s2[b * 2 + 1] = rsqrtf(var + 1e-5f);
    }
}

// ---- final: FiLM GN + skip2 ----
__global__ void k_final(const float* __restrict__ x, float* __restrict__ out) {
    int gi = blockIdx.x * 256 + threadIdx.x;
#pragma unroll
    for (int u = 0; u < 4; ++u) {
        size_t i4 = (size_t)gi + (size_t)u * 2097152;
        size_t e = i4 * 4;
        int b = (int)(e >> 22);
        int c = (int)((e >> 16) & 63);
        float mean = g_s2[b * 2], rstd = g_s2[b * 2 + 1];
        float ga = g_gb[(b * 64 + c) * 2], be = g_gb[(b * 64 + c) * 2 + 1];
        float4 zv = ((const float4*)g_z)[i4];
        float4 xv = ((const float4*)x)[i4];
        float4 ov;
        ov.x = ga * (zv.x - mean) * rstd + be + gelu_f(xv.x);
        ov.y = ga * (zv.y - mean) * rstd + be + gelu_f(xv.y);
        ov.z = ga * (zv.z - mean) * rstd + be + gelu_f(xv.z);
        ov.w = ga * (zv.w - mean) * rstd + be + gelu_f(xv.w);
        ((float4*)out)[i4] = ov;
    }
}

extern "C" void kernel_launch(void* const* d_in, const int* in_sizes, int n_in,
                              void* d_out, int out_size) {
    const float* x       = (const float*)d_in[0];
    const float* t       = (const float*)d_in[1];
    const float* w1r     = (const float*)d_in[2];
    const float* w1i     = (const float*)d_in[3];
    const float* w2r     = (const float*)d_in[4];
    const float* w2i     = (const float*)d_in[5];
    const float* norm1_w = (const float*)d_in[6];
    const float* norm1_b = (const float*)d_in[7];
    const float* mlp_w1  = (const float*)d_in[8];
    const float* mlp_b1  = (const float*)d_in[9];
    const float* mlp_w2  = (const float*)d_in[10];
    const float* mlp_b2  = (const float*)d_in[11];
    const float* gamma_w = (const float*)d_in[12];
    const float* gamma_b = (const float*)d_in[13];
    const float* beta_w  = (const float*)d_in[14];
    const float* beta_b  = (const float*)d_in[15];
    float* out = (float*)d_out;

    cudaFuncSetAttribute(k_fwdW, cudaFuncAttributeMaxDynamicSharedMemorySize, 98304);
    cudaFuncSetAttribute(k_fwdH, cudaFuncAttributeMaxDynamicSharedMemorySize, 32800);
    cudaFuncSetAttribute(k_mix,  cudaFuncAttributeMaxDynamicSharedMemorySize, 65536);
    cudaFuncSetAttribute(k_invW, cudaFuncAttributeMaxDynamicSharedMemorySize, 73728);
    cudaFuncSetAttribute(k_mlp,  cudaFuncAttributeMaxDynamicSharedMemorySize, 66432);

    k_tab<<<65, 256>>>();
    k_film<<<PB, PC>>>(t, gamma_w, gamma_b, beta_w, beta_b);
    k_fwdW<<<NROWS / 64, 256, 98304>>>(x);
    k_fwdH<<<PB * PC * 2, 256, 32800>>>();
    k_mix<<<256, 512, 65536>>>(w1r, w1i, w2r, w2i);
    k_invH<<<PB * PC, 256>>>();
    k_invW<<<PB * PC * 4, 256, 73728>>>();
    k_red1<<<PB, 256>>>();
    k_mlp<<<PB * PH, 256, 66432>>>(x, norm1_w, norm1_b,
                                   mlp_w1, mlp_b1, mlp_w2, mlp_b2);
    k_red2<<<PB, 256>>>();
    k_final<<<8192, 256>>>(x, out);
}

// round 13
// speedup vs baseline: 1.3234x; 1.0220x over previous
#include <cuda_runtime.h>
#include <math.h>

#define PB 8
#define PC 64
#define PH 256
#define PW 256
#define PKX 64
#define PKY 32
#define NROWS (PB*PC*PH)

// ---- scratch (device globals; no runtime allocation) ----
__device__ __align__(16) float  g_T[256*64];
__device__ __align__(16) float  g_cos[256];
__device__ __align__(16) float  g_sin[256];
__device__ __align__(16) float2 g_ct[256];            // (cos, sin) pairs
__device__ __align__(16) float2 g_E[128*64];          // fwdH twiddles E[h][kxp]
__device__ __align__(16) float2 g_X1[PB*PC*PH*PKY];   // after fwd-W  [b,c,h,ky]
__device__ __align__(16) float2 g_XF[PB*PC*PKX*PKY];  // after fwd-H  [b,c,kx',ky]
__device__ __align__(16) float2 g_OF[PB*PC*PKX*PKY];  // after mix
__device__ __align__(16) float2 g_Y1[PB*PC*PKY*PH];   // after inv-H  [b,c,ky,h]
__device__ __align__(16) float  g_y[PB*PC*PH*PW];     // spectral conv out
__device__ __align__(16) float  g_z[PB*PC*PH*PW];     // MLP out
__device__ __align__(16) float  g_p1[PB*PC*4*2];      // per-invW-block partials
__device__ __align__(16) float  g_p2[PB*PH*2];
__device__ __align__(16) float  g_s1[PB*2];
__device__ __align__(16) float  g_s2[PB*2];
__device__ __align__(16) float  g_gb[PB*PC*2];

__device__ __forceinline__ float gelu_f(float v) {
    return 0.5f * v * (1.0f + erff(v * 0.7071067811865476f));
}

// ---- packed f32x2 helpers (bit-identical fp32 FMA, 2 per issue slot) ----
__device__ __forceinline__ unsigned long long fma2(unsigned long long a,
                                                   unsigned long long b,
                                                   unsigned long long c) {
    unsigned long long d;
    asm("fma.rn.f32x2 %0, %1, %2, %3;" : "=l"(d) : "l"(a), "l"(b), "l"(c));
    return d;
}
__device__ __forceinline__ unsigned long long pack2(float v) {
    unsigned long long d;
    asm("mov.b64 %0, {%1, %1};" : "=l"(d) : "f"(v));
    return d;
}
__device__ __forceinline__ void upk2(unsigned long long v, float& lo, float& hi) {
    asm("mov.b64 {%0, %1}, %2;" : "=f"(lo), "=f"(hi) : "l"(v));
}

// ---- twiddle tables: fully parallel grid-stride ----
__global__ void k_tab() {
    int i = blockIdx.x * blockDim.x + threadIdx.x;
    if (i < 8192) {
        int j = i >> 5, ky = i & 31;
        int idx = (ky * j) & 255;
        double s2, c2;
        sincospi((double)idx * (2.0 / 256.0), &s2, &c2);
        g_T[j * 64 + 2 * ky]     = (float)c2;
        g_T[j * 64 + 2 * ky + 1] = (float)(-s2);
    } else if (i < 8448) {
        int j = i - 8192;
        double sd, cd;
        sincospi((double)j * (2.0 / 256.0), &sd, &cd);
        g_cos[j] = (float)cd;
        g_sin[j] = (float)sd;
        g_ct[j] = make_float2((float)cd, (float)sd);
    } else if (i < 16640) {
        int k = i - 8448;
        int h = k >> 6, kxp = k & 63;
        int kxm = kxp + ((kxp >= 32) ? 192 : 0);
        int idx = (kxm * h) & 255;
        double s2, c2;
        sincospi((double)idx * (2.0 / 256.0), &s2, &c2);
        g_E[k] = make_float2((float)c2, (float)s2);
    }
}

// ---- FiLM gamma/beta ----
__global__ void k_film(const float* __restrict__ t,
                       const float* __restrict__ gw, const float* __restrict__ gb,
                       const float* __restrict__ bw, const float* __restrict__ bb) {
    int b = blockIdx.x, o = threadIdx.x;
    float g = gb[o], be = bb[o];
    for (int c = 0; c < PC; ++c) {
        float tv = t[b * PC + c];
        g  += gw[o * PC + c] * tv;
        be += bw[o * PC + c] * tv;
    }
    g_gb[(b * PC + o) * 2]     = g;
    g_gb[(b * PC + o) * 2 + 1] = be;
}

// ---- forward DFT along W, radix-2; T via LDG (L1-hot), su-only smem ----
__global__ void __launch_bounds__(256) k_fwdW(const float* __restrict__ x) {
    extern __shared__ char smraw[];
    float2* su = (float2*)smraw;            // [row 64][w<128] (u0,u1)  64KB
    int tid = threadIdx.x;
    size_t base = (size_t)blockIdx.x * 64 * 256;

    for (int i = tid; i < 2048; i += 256) {
        int row = i >> 5, w4 = (i & 31) * 4;
        float4 a = *(const float4*)&x[base + row * 256 + w4];
        float4 b = *(const float4*)&x[base + row * 256 + w4 + 128];
        float4* d = (float4*)&su[row * 128 + w4];
        d[0] = make_float4(a.x + b.x, a.x - b.x, a.y + b.y, a.y - b.y);
        d[1] = make_float4(a.z + b.z, a.z - b.z, a.w + b.w, a.w - b.w);
    }
    __syncthreads();

    int r0 = (tid >> 3) * 2;
    int c0 = (tid & 7) * 8;

    float acc[2][8];
#pragma unroll
    for (int r = 0; r < 2; ++r)
#pragma unroll
        for (int u = 0; u < 8; ++u) acc[r][u] = 0.0f;

    const float2* rowA = su + r0 * 128;
    const float2* rowB = rowA + 128;
    const float4* Tg = (const float4*)g_T;
    int tcol = c0 >> 2;
#pragma unroll 4
    for (int k = 0; k < 128; ++k) {
        float2 ua = rowA[k];
        float2 ub = rowB[k];
        float4 t0 = Tg[k * 16 + tcol];
        float4 t1 = Tg[k * 16 + tcol + 1];
        acc[0][0] += ua.x * t0.x; acc[0][1] += ua.x * t0.y;
        acc[0][2] += ua.y * t0.z; acc[0][3] += ua.y * t0.w;
        acc[0][4] += ua.x * t1.x; acc[0][5] += ua.x * t1.y;
        acc[0][6] += ua.y * t1.z; acc[0][7] += ua.y * t1.w;
        acc[1][0] += ub.x * t0.x; acc[1][1] += ub.x * t0.y;
        acc[1][2] += ub.y * t0.z; acc[1][3] += ub.y * t0.w;
        acc[1][4] += ub.x * t1.x; acc[1][5] += ub.x * t1.y;
        acc[1][6] += ub.y * t1.z; acc[1][7] += ub.y * t1.w;
    }
    float* go = (float*)g_X1 + (size_t)blockIdx.x * 64 * 64;
#pragma unroll
    for (int r = 0; r < 2; ++r) {
        *(float4*)&go[(r0 + r) * 64 + c0] =
            make_float4(acc[r][0], acc[r][1], acc[r][2], acc[r][3]);
        *(float4*)&go[(r0 + r) * 64 + c0 + 4] =
            make_float4(acc[r][4], acc[r][5], acc[r][6], acc[r][7]);
    }
}

// ---- forward DFT along H, radix-2 over h; ky-split (occupancy) + E via LDG ----
__global__ void __launch_bounds__(256) k_fwdH() {
    extern __shared__ char smraw[];
    float2* sv0 = (float2*)smraw;                    // [h<128][16] sum operand
    float2* sv1 = (float2*)(smraw + 16384 + 32);     // diff operand (skewed)
    int tid = threadIdx.x;
    int bc = blockIdx.x >> 1, kh = blockIdx.x & 1;

    const float4* src = (const float4*)(g_X1 + (size_t)bc * 8192);
    float4* d0 = (float4*)sv0;
    float4* d1 = (float4*)sv1;
    for (int i = tid; i < 1024; i += 256) {
        int h = i >> 3, j = i & 7;
        int s = h * 16 + kh * 8 + j;
        float4 a = src[s];
        float4 b = src[s + 2048];                    // h+128
        d0[i] = make_float4(a.x + b.x, a.y + b.y, a.z + b.z, a.w + b.w);
        d1[i] = make_float4(a.x - b.x, a.y - b.y, a.z - b.z, a.w - b.w);
    }
    __syncthreads();

    int kxp = tid & 63;
    int ky0 = (tid >> 6) * 4;                        // local ky group (4 per thread)
    const float2* sv = (kxp & 1) ? sv1 : sv0;        // kxm parity == kxp parity
    const float2* E = g_E + kxp;

    float2 acc[4];
#pragma unroll
    for (int j = 0; j < 4; ++j) acc[j] = make_float2(0.f, 0.f);

#pragma unroll 4
    for (int h = 0; h < 128; ++h) {
        float2 e = E[h * 64];                        // coalesced LDG, L1/L2-hot
        const float2* row = &sv[h * 16 + ky0];
        float4 vA = *(const float4*)&row[0];
        float4 vB = *(const float4*)&row[2];
        float2 v[4] = { {vA.x,vA.y},{vA.z,vA.w},{vB.x,vB.y},{vB.z,vB.w} };
#pragma unroll
        for (int j = 0; j < 4; ++j) {
            acc[j].x += v[j].x * e.x + v[j].y * e.y;
            acc[j].y += v[j].y * e.x - v[j].x * e.y;
        }
    }
    int kyg = kh * 16 + ky0;
    float2* o = g_XF + ((size_t)bc * 64 + kxp) * 32 + kyg;
    *(float4*)&o[0] = make_float4(acc[0].x, acc[0].y, acc[1].x, acc[1].y);
    *(float4*)&o[2] = make_float4(acc[2].x, acc[2].y, acc[3].x, acc[3].y);
}

// ---- per-mode complex channel mixing, ky-split for occupancy ----
__global__ void __launch_bounds__(512)
k_mix(const float* __restrict__ w1r, const float* __restrict__ w1i,
      const float* __restrict__ w2r, const float* __restrict__ w2i) {
    extern __shared__ char smraw[];
    float2* sXF = (float2*)smraw;   // [(b*64+i)*16 + kyl], 8192 float2 = 64KB
    int kxp   = blockIdx.x >> 2;
    int ohalf = (blockIdx.x >> 1) & 1;
    int kh    = blockIdx.x & 1;
    int tid = threadIdx.x;

    for (int i = tid; i < 8192; i += 512) {
        int b = i >> 10, rest = i & 1023, ii = rest >> 4, kk = rest & 15;
        sXF[i] = g_XF[(((size_t)b * PC + ii) * PKX + kxp) * PKY + kh * 16 + kk];
    }
    __syncthreads();

    int o   = ohalf * 32 + (tid >> 4);
    int kyl = tid & 15;
    int ky  = kh * 16 + kyl;
    const float* wr; const float* wi; int kxl;
    if (kxp < 32) { wr = w1r; wi = w1i; kxl = kxp; }
    else          { wr = w2r; wi = w2i; kxl = kxp - 32; }

    float ar[8], ai[8];
#pragma unroll
    for (int b = 0; b < 8; ++b) { ar[b] = 0.0f; ai[b] = 0.0f; }

    const float* wrp = wr + (size_t)o * 1024 + kxl * 32 + ky;
    const float* wip = wi + (size_t)o * 1024 + kxl * 32 + ky;
#pragma unroll 2
    for (int i = 0; i < 64; ++i) {
        float wrv = wrp[(size_t)i * 65536];
        float wiv = wip[(size_t)i * 65536];
#pragma unroll
        for (int b = 0; b < 8; ++b) {
            float2 v = sXF[(b * 64 + i) * 16 + kyl];
            ar[b] += v.x * wrv - v.y * wiv;
            ai[b] += v.x * wiv + v.y * wrv;
        }
    }
#pragma unroll
    for (int b = 0; b < 8; ++b)
        g_OF[(((size_t)b * PC + o) * PKX + kxp) * PKY + ky] = make_float2(ar[b], ai[b]);
}

// ---- inverse DFT along H, radix-2: Se/So over kx parity, emit h and h+128 ----
__global__ void __launch_bounds__(256) k_invH() {
    __shared__ float2 sOF[2048];
    __shared__ float2 ct[256];
    int tid = threadIdx.x, bc = blockIdx.x;

    const float4* src = (const float4*)(g_OF + (size_t)bc * 2048);
    float4* dst = (float4*)sOF;
    for (int i = tid; i < 1024; i += 256) dst[i] = src[i];
    ct[tid] = g_ct[tid];
    __syncthreads();

    int h0  = (tid >> 3) * 4;     // h<128
    int ky0 = (tid & 7) * 4;

    float2 ae[4][4], ao[4][4];
#pragma unroll
    for (int hh = 0; hh < 4; ++hh)
#pragma unroll
        for (int j = 0; j < 4; ++j) {
            ae[hh][j] = make_float2(0.f, 0.f);
            ao[hh][j] = make_float2(0.f, 0.f);
        }

    for (int kxp = 0; kxp < 64; kxp += 2) {
        int kxm = kxp + ((kxp >= 32) ? 192 : 0);
        float2 te[4], to[4];
#pragma unroll
        for (int hh = 0; hh < 4; ++hh) {
            int h = h0 + hh;
            te[hh] = ct[(kxm * h) & 255];
            to[hh] = ct[((kxm + 1) * h) & 255];
        }
        float4 eA = *(const float4*)&sOF[kxp * 32 + ky0];
        float4 eB = *(const float4*)&sOF[kxp * 32 + ky0 + 2];
        float4 oA = *(const float4*)&sOF[(kxp + 1) * 32 + ky0];
        float4 oB = *(const float4*)&sOF[(kxp + 1) * 32 + ky0 + 2];
        float2 ove[4] = { {eA.x, eA.y}, {eA.z, eA.w}, {eB.x, eB.y}, {eB.z, eB.w} };
        float2 ovo[4] = { {oA.x, oA.y}, {oA.z, oA.w}, {oB.x, oB.y}, {oB.z, oB.w} };
#pragma unroll
        for (int hh = 0; hh < 4; ++hh) {
#pragma unroll
            for (int j = 0; j < 4; ++j) {
                ae[hh][j].x += ove[j].x * te[hh].x - ove[j].y * te[hh].y;
                ae[hh][j].y += ove[j].x * te[hh].y + ove[j].y * te[hh].x;
                ao[hh][j].x += ovo[j].x * to[hh].x - ovo[j].y * to[hh].y;
                ao[hh][j].y += ovo[j].x * to[hh].y + ovo[j].y * to[hh].x;
            }
        }
    }
#pragma unroll
    for (int j = 0; j < 4; ++j) {
        float2* out = g_Y1 + (size_t)bc * 8192 + (ky0 + j) * 256 + h0;
#pragma unroll
        for (int hh = 0; hh < 4; hh += 2) {
            *(float4*)&out[hh] = make_float4(
                ae[hh][j].x + ao[hh][j].x,     ae[hh][j].y + ao[hh][j].y,
                ae[hh+1][j].x + ao[hh+1][j].x, ae[hh+1][j].y + ao[hh+1][j].y);
            *(float4*)&out[hh + 128] = make_float4(
                ae[hh][j].x - ao[hh][j].x,     ae[hh][j].y - ao[hh][j].y,
                ae[hh+1][j].x - ao[hh+1][j].x, ae[hh+1][j].y - ao[hh+1][j].y);
        }
    }
}

// ---- inverse rfft along W, radix-2: Se/So over ky parity, emit w and w+128 ----
__global__ void __launch_bounds__(256) k_invW() {
    extern __shared__ char smraw[];
    float2* sY = (float2*)smraw;               // 8192 float2 (64KB)
    float2* sW = (float2*)(smraw + 65536);     // 31*32 float2
    __shared__ float rbuf[16];
    int tid = threadIdx.x;
    int bc = blockIdx.x >> 2, wt = blockIdx.x & 3;
    int w0 = wt * 32;

    const float4* src = (const float4*)(g_Y1 + (size_t)bc * 8192);
    float4* dst = (float4*)sY;
    for (int i = tid; i < 4096; i += 256) dst[i] = src[i];

    const float inv = 1.0f / 65536.0f;
    for (int i = tid; i < 31 * 32; i += 256) {
        int ky = (i >> 5) + 1;
        int w  = w0 + (i & 31);
        int idx = (ky * w) & 255;
        sW[i] = make_float2(2.0f * inv * g_cos[idx], 2.0f * inv * g_sin[idx]);
    }
    __syncthreads();

    int h0  = (tid >> 3) * 8;
    int wth = (tid & 7) * 4;

    float se[8][4], so[8][4], dc[8];
#pragma unroll
    for (int hh = 0; hh < 8; ++hh) {
        dc[hh] = inv * sY[h0 + hh].x;
#pragma unroll
        for (int ww = 0; ww < 4; ++ww) { se[hh][ww] = 0.f; so[hh][ww] = 0.f; }
    }

    for (int ky = 1; ky < 31; ky += 2) {
        {
            float2 av[8], bv[4];
            const float4* ap = (const float4*)&sY[ky * 256 + h0];
#pragma unroll
            for (int u = 0; u < 4; ++u) {
                float4 t1 = ap[u];
                av[2*u] = make_float2(t1.x, t1.y);
                av[2*u+1] = make_float2(t1.z, t1.w);
            }
            const float4* bp = (const float4*)&sW[(ky - 1) * 32 + wth];
            float4 t2 = bp[0], t3 = bp[1];
            bv[0] = make_float2(t2.x, t2.y); bv[1] = make_float2(t2.z, t2.w);
            bv[2] = make_float2(t3.x, t3.y); bv[3] = make_float2(t3.z, t3.w);
#pragma unroll
            for (int hh = 0; hh < 8; ++hh)
#pragma unroll
                for (int ww = 0; ww < 4; ++ww)
                    so[hh][ww] += av[hh].x * bv[ww].x - av[hh].y * bv[ww].y;
        }
        {
            float2 av[8], bv[4];
            const float4* ap = (const float4*)&sY[(ky + 1) * 256 + h0];
#pragma unroll
            for (int u = 0; u < 4; ++u) {
                float4 t1 = ap[u];
                av[2*u] = make_float2(t1.x, t1.y);
                av[2*u+1] = make_float2(t1.z, t1.w);
            }
            const float4* bp = (const float4*)&sW[ky * 32 + wth];
            float4 t2 = bp[0], t3 = bp[1];
            bv[0] = make_float2(t2.x, t2.y); bv[1] = make_float2(t2.z, t2.w);
            bv[2] = make_float2(t3.x, t3.y); bv[3] = make_float2(t3.z, t3.w);
#pragma unroll
            for (int hh = 0; hh < 8; ++hh)
#pragma unroll
                for (int ww = 0; ww < 4; ++ww)
                    se[hh][ww] += av[hh].x * bv[ww].x - av[hh].y * bv[ww].y;
        }
    }
    {
        float2 av[8], bv[4];
        const float4* ap = (const float4*)&sY[31 * 256 + h0];
#pragma unroll
        for (int u = 0; u < 4; ++u) {
            float4 t1 = ap[u];
            av[2*u] = make_float2(t1.x, t1.y);
            av[2*u+1] = make_float2(t1.z, t1.w);
        }
        const float4* bp = (const float4*)&sW[30 * 32 + wth];
        float4 t2 = bp[0], t3 = bp[1];
        bv[0] = make_float2(t2.x, t2.y); bv[1] = make_float2(t2.z, t2.w);
        bv[2] = make_float2(t3.x, t3.y); bv[3] = make_float2(t3.z, t3.w);
#pragma unroll
        for (int hh = 0; hh < 8; ++hh)
#pragma unroll
            for (int ww = 0; ww < 4; ++ww)
                so[hh][ww] += av[hh].x * bv[ww].x - av[hh].y * bv[ww].y;
    }

    float s = 0.0f, s2 = 0.0f;
#pragma unroll
    for (int hh = 0; hh < 8; ++hh) {
        float lo[4], hi[4];
#pragma unroll
        for (int ww = 0; ww < 4; ++ww) {
            lo[ww] = dc[hh] + se[hh][ww] + so[hh][ww];
            hi[ww] = dc[hh] + se[hh][ww] - so[hh][ww];
            s += lo[ww] + hi[ww];
            s2 += lo[ww] * lo[ww] + hi[ww] * hi[ww];
        }
        size_t base = (size_t)bc * 65536 + (size_t)(h0 + hh) * 256 + w0 + wth;
        *(float4*)&g_y[base]       = make_float4(lo[0], lo[1], lo[2], lo[3]);
        *(float4*)&g_y[base + 128] = make_float4(hi[0], hi[1], hi[2], hi[3]);
    }

    for (int off = 16; off > 0; off >>= 1) {
        s  += __shfl_down_sync(0xffffffffu, s,  off);
        s2 += __shfl_down_sync(0xffffffffu, s2, off);
    }
    int lane = tid & 31, wid = tid >> 5;
    if (lane == 0) { rbuf[wid] = s; rbuf[wid + 8] = s2; }
    __syncthreads();
    if (tid == 0) {
        float S = 0.0f, S2 = 0.0f;
        for (int i = 0; i < 8; ++i) { S += rbuf[i]; S2 += rbuf[i + 8]; }
        g_p1[blockIdx.x * 2] = S;
        g_p1[blockIdx.x * 2 + 1] = S2;
    }
}

__global__ void k_red1() {
    __shared__ float rbuf[16];
    int b = blockIdx.x, tid = threadIdx.x;
    float s  = g_p1[(b * 256 + tid) * 2];
    float s2 = g_p1[(b * 256 + tid) * 2 + 1];
    for (int off = 16; off > 0; off >>= 1) {
        s  += __shfl_down_sync(0xffffffffu, s,  off);
        s2 += __shfl_down_sync(0xffffffffu, s2, off);
    }
    int lane = tid & 31, wid = tid >> 5;
    if (lane == 0) { rbuf[wid] = s; rbuf[wid + 8] = s2; }
    __syncthreads();
    if (tid == 0) {
        float S = 0.0f, S2 = 0.0f;
        for (int i = 0; i < 8; ++i) { S += rbuf[i]; S2 += rbuf[i + 8]; }
        float mean = S * (1.0f / 4194304.0f);
        float var  = S2 * (1.0f / 4194304.0f) - mean * mean;
        g_s1[b * 2] = mean;
        g_s1[b * 2 + 1] = rsqrtf(var + 1e-5f);
    }
}

// ---- GN1 apply + residual + gelu + MLP (FFMA2, natural weight pairs) ----
__global__ void __launch_bounds__(256) k_mlp(const float* __restrict__ x,
                      const float* __restrict__ nw, const float* __restrict__ nb,
                      const float* __restrict__ w1, const float* __restrict__ b1,
                      const float* __restrict__ w2, const float* __restrict__ b2) {
    extern __shared__ char smraw[];
    float* sy2  = (float*)smraw;        // [c][w]  64*128
    float* sh   = sy2 + 8192;           // [m][w]  32*128
    float* sw1  = sh + 4096;            // [c][m]  64*32
    float* sw2  = sw1 + 2048;           // [m][c]  32*64
    float* sb1  = sw2 + 2048;           // 32
    float* sb2v = sb1 + 32;             // 64
    float* snw  = sb2v + 64;            // 64
    float* snb  = snw + 64;             // 64
    __shared__ float rbuf[16];

    int tid = threadIdx.x;
    int b = blockIdx.x >> 8, h = blockIdx.x & 255;

    for (int i = tid; i < 2048; i += 256) {
        int c = i >> 5, m = i & 31;
        sw1[i] = w1[m * 64 + c];
        int m2 = i >> 6, c2 = i & 63;
        sw2[i] = w2[c2 * 32 + m2];
    }
    if (tid < 64) {
        sb2v[tid] = b2[tid];
        snw[tid] = nw[tid];
        snb[tid] = nb[tid];
        if (tid < 32) sb1[tid] = b1[tid];
    }
    float mean1 = g_s1[b * 2], rstd1 = g_s1[b * 2 + 1];
    __syncthreads();

    int m0 = (tid >> 5) * 4;   // 4 m = 2 natural pairs
    int c0 = (tid >> 5) * 8;   // 8 c = 4 natural pairs
    int wl = (tid & 31) * 4;   // 4 w

    float s = 0.0f, s2 = 0.0f;
    for (int half = 0; half < 2; ++half) {
        int wbase = half * 128;

        for (int i = tid; i < 2048; i += 256) {
            int c = i >> 5, w4 = (i & 31) * 4;
            size_t gid = (size_t)(b * 64 + c) * 65536 + (size_t)h * 256 + wbase + w4;
            float4 yv = *(const float4*)&g_y[gid];
            float4 xv = *(const float4*)&x[gid];
            float a = snw[c] * rstd1, bb = snb[c] - mean1 * rstd1 * snw[c];
            float4 o;
            o.x = gelu_f(yv.x * a + bb + xv.x);
            o.y = gelu_f(yv.y * a + bb + xv.y);
            o.z = gelu_f(yv.z * a + bb + xv.z);
            o.w = gelu_f(yv.w * a + bb + xv.w);
            *(float4*)&sy2[c * 128 + w4] = o;
        }
        __syncthreads();

        {   // layer 1: acc[mpair][w], weights as natural (m,m+1) f32x2 pairs
            unsigned long long acc[2][4];
#pragma unroll
            for (int p = 0; p < 2; ++p)
#pragma unroll
                for (int ww = 0; ww < 4; ++ww) acc[p][ww] = 0ull;
            for (int c = 0; c < 64; ++c) {
                ulonglong2 wp = *(const ulonglong2*)&sw1[c * 32 + m0];
                float4 yv = *(const float4*)&sy2[c * 128 + wl];
                unsigned long long y0 = pack2(yv.x), y1 = pack2(yv.y),
                                   y2 = pack2(yv.z), y3 = pack2(yv.w);
                acc[0][0] = fma2(wp.x, y0, acc[0][0]);
                acc[0][1] = fma2(wp.x, y1, acc[0][1]);
                acc[0][2] = fma2(wp.x, y2, acc[0][2]);
                acc[0][3] = fma2(wp.x, y3, acc[0][3]);
                acc[1][0] = fma2(wp.y, y0, acc[1][0]);
                acc[1][1] = fma2(wp.y, y1, acc[1][1]);
                acc[1][2] = fma2(wp.y, y2, acc[1][2]);
                acc[1][3] = fma2(wp.y, y3, acc[1][3]);
            }
#pragma unroll
            for (int p = 0; p < 2; ++p) {
                int mA = m0 + 2 * p, mB = mA + 1;
                float bA = sb1[mA], bB = sb1[mB];
#pragma unroll
                for (int ww = 0; ww < 4; ++ww) {
                    float lo, hi;
                    upk2(acc[p][ww], lo, hi);
                    sh[mA * 128 + wl + ww] = gelu_f(lo + bA);
                    sh[mB * 128 + wl + ww] = gelu_f(hi + bB);
                }
            }
        }
        __syncthreads();

        {   // layer 2: acc2[cpair][w], weights as natural (c,c+1) f32x2 pairs
            unsigned long long acc2[4][4];
#pragma unroll
            for (int p = 0; p < 4; ++p)
#pragma unroll
                for (int ww = 0; ww < 4; ++ww) acc2[p][ww] = 0ull;
            for (int m = 0; m < 32; ++m) {
                ulonglong2 wA = *(const ulonglong2*)&sw2[m * 64 + c0];
                ulonglong2 wB = *(const ulonglong2*)&sw2[m * 64 + c0 + 4];
                float4 hv = *(const float4*)&sh[m * 128 + wl];
                unsigned long long h0p = pack2(hv.x), h1p = pack2(hv.y),
                                   h2p = pack2(hv.z), h3p = pack2(hv.w);
                acc2[0][0] = fma2(wA.x, h0p, acc2[0][0]);
                acc2[0][1] = fma2(wA.x, h1p, acc2[0][1]);
                acc2[0][2] = fma2(wA.x, h2p, acc2[0][2]);
                acc2[0][3] = fma2(wA.x, h3p, acc2[0][3]);
                acc2[1][0] = fma2(wA.y, h0p, acc2[1][0]);
                acc2[1][1] = fma2(wA.y, h1p, acc2[1][1]);
                acc2[1][2] = fma2(wA.y, h2p, acc2[1][2]);
                acc2[1][3] = fma2(wA.y, h3p, acc2[1][3]);
                acc2[2][0] = fma2(wB.x, h0p, acc2[2][0]);
                acc2[2][1] = fma2(wB.x, h1p, acc2[2][1]);
                acc2[2][2] = fma2(wB.x, h2p, acc2[2][2]);
                acc2[2][3] = fma2(wB.x, h3p, acc2[2][3]);
                acc2[3][0] = fma2(wB.y, h0p, acc2[3][0]);
                acc2[3][1] = fma2(wB.y, h1p, acc2[3][1]);
                acc2[3][2] = fma2(wB.y, h2p, acc2[3][2]);
                acc2[3][3] = fma2(wB.y, h3p, acc2[3][3]);
            }
#pragma unroll
            for (int p = 0; p < 4; ++p) {
                int cA = c0 + 2 * p, cB = cA + 1;
                float bA = sb2v[cA], bB = sb2v[cB];
                float oA[4], oB[4];
#pragma unroll
                for (int ww = 0; ww < 4; ++ww) {
                    float lo, hi;
                    upk2(acc2[p][ww], lo, hi);
                    oA[ww] = lo + bA;
                    oB[ww] = hi + bB;
                    s += oA[ww] + oB[ww];
                    s2 += oA[ww] * oA[ww] + oB[ww] * oB[ww];
                }
                size_t gA = (size_t)(b * 64 + cA) * 65536 + (size_t)h * 256 + wbase + wl;
                size_t gB = (size_t)(b * 64 + cB) * 65536 + (size_t)h * 256 + wbase + wl;
                *(float4*)&g_z[gA] = make_float4(oA[0], oA[1], oA[2], oA[3]);
                *(float4*)&g_z[gB] = make_float4(oB[0], oB[1], oB[2], oB[3]);
            }
        }
        __syncthreads();
    }

    for (int off = 16; off > 0; off >>= 1) {
        s  += __shfl_down_sync(0xffffffffu, s,  off);
        s2 += __shfl_down_sync(0xffffffffu, s2, off);
    }
    int lane = tid & 31, widx = tid >> 5;
    if (lane == 0) { rbuf[widx] = s; rbuf[widx + 8] = s2; }
    __syncthreads();
    if (tid == 0) {
        float S = 0.0f, S2 = 0.0f;
        for (int i = 0; i < 8; ++i) { S += rbuf[i]; S2 += rbuf[i + 8]; }
        g_p2[blockIdx.x * 2] = S;
        g_p2[blockIdx.x * 2 + 1] = S2;
    }
}

__global__ void k_red2() {
    __shared__ float rbuf[16];
    int b = blockIdx.x, tid = threadIdx.x;
    float s  = g_p2[(b * 256 + tid) * 2];
    float s2 = g_p2[(b * 256 + tid) * 2 + 1];
    for (int off = 16; off > 0; off >>= 1) {
        s  += __shfl_down_sync(0xffffffffu, s,  off);
        s2 += __shfl_down_sync(0xffffffffu, s2, off);
    }
    int lane = tid & 31, wid = tid >> 5;
    if (lane == 0) { rbuf[wid] = s; rbuf[wid + 8] = s2; }
    __syncthreads();
    if (tid == 0) {
        float S = 0.0f, S2 = 0.0f;
        for (int i = 0; i < 8; ++i) { S += rbuf[i]; S2 += rbuf[i + 8]; }
        float mean = S * (1.0f / 4194304.0f);
        float var  = S2 * (1.0f / 4194304.0f) - mean * mean;
        g_s2[b * 2] = mean;
        g_s2[b * 2 + 1] = rsqrtf(var + 1e-5f);
    }
}

// ---- final: FiLM GN + skip2 ----
__global__ void k_final(const float* __restrict__ x, float* __restrict__ out) {
    int gi = blockIdx.x * 256 + threadIdx.x;
#pragma unroll
    for (int u = 0; u < 4; ++u) {
        size_t i4 = (size_t)gi + (size_t)u * 2097152;
        size_t e = i4 * 4;
        int b = (int)(e >> 22);
        int c = (int)((e >> 16) & 63);
        float mean = g_s2[b * 2], rstd = g_s2[b * 2 + 1];
        float ga = g_gb[(b * 64 + c) * 2], be = g_gb[(b * 64 + c) * 2 + 1];
        float4 zv = ((const float4*)g_z)[i4];
        float4 xv = ((const float4*)x)[i4];
        float4 ov;
        ov.x = ga * (zv.x - mean) * rstd + be + gelu_f(xv.x);
        ov.y = ga * (zv.y - mean) * rstd + be + gelu_f(xv.y);
        ov.z = ga * (zv.z - mean) * rstd + be + gelu_f(xv.z);
        ov.w = ga * (zv.w - mean) * rstd + be + gelu_f(xv.w);
        ((float4*)out)[i4] = ov;
    }
}

extern "C" void kernel_launch(void* const* d_in, const int* in_sizes, int n_in,
                              void* d_out, int out_size) {
    const float* x       = (const float*)d_in[0];
    const float* t       = (const float*)d_in[1];
    const float* w1r     = (const float*)d_in[2];
    const float* w1i     = (const float*)d_in[3];
    const float* w2r     = (const float*)d_in[4];
    const float* w2i     = (const float*)d_in[5];
    const float* norm1_w = (const float*)d_in[6];
    const float* norm1_b = (const float*)d_in[7];
    const float* mlp_w1  = (const float*)d_in[8];
    const float* mlp_b1  = (const float*)d_in[9];
    const float* mlp_w2  = (const float*)d_in[10];
    const float* mlp_b2  = (const float*)d_in[11];
    const float* gamma_w = (const float*)d_in[12];
    const float* gamma_b = (const float*)d_in[13];
    const float* beta_w  = (const float*)d_in[14];
    const float* beta_b  = (const float*)d_in[15];
    float* out = (float*)d_out;

    cudaFuncSetAttribute(k_fwdW, cudaFuncAttributeMaxDynamicSharedMemorySize, 65536);
    cudaFuncSetAttribute(k_fwdH, cudaFuncAttributeMaxDynamicSharedMemorySize, 32800);
    cudaFuncSetAttribute(k_mix,  cudaFuncAttributeMaxDynamicSharedMemorySize, 65536);
    cudaFuncSetAttribute(k_invW, cudaFuncAttributeMaxDynamicSharedMemorySize, 73728);
    cudaFuncSetAttribute(k_mlp,  cudaFuncAttributeMaxDynamicSharedMemorySize, 66432);

    k_tab<<<65, 256>>>();
    k_film<<<PB, PC>>>(t, gamma_w, gamma_b, beta_w, beta_b);
    k_fwdW<<<NROWS / 64, 256, 65536>>>(x);
    k_fwdH<<<PB * PC * 2, 256, 32800>>>();
    k_mix<<<256, 512, 65536>>>(w1r, w1i, w2r, w2i);
    k_invH<<<PB * PC, 256>>>();
    k_invW<<<PB * PC * 4, 256, 73728>>>();
    k_red1<<<PB, 256>>>();
    k_mlp<<<PB * PH, 256, 66432>>>(x, norm1_w, norm1_b,
                                   mlp_w1, mlp_b1, mlp_w2, mlp_b2);
    k_red2<<<PB, 256>>>();
    k_final<<<8192, 256>>>(x, out);
}

// round 14
// speedup vs baseline: 1.3487x; 1.0191x over previous
#include <cuda_runtime.h>
#include <math.h>

#define PB 8
#define PC 64
#define PH 256
#define PW 256
#define PKX 64
#define PKY 32
#define NROWS (PB*PC*PH)

typedef unsigned long long u64;

// ---- scratch (device globals; no runtime allocation) ----
__device__ __align__(16) float  g_T[256*64];
__device__ __align__(16) float  g_cos[256];
__device__ __align__(16) float  g_sin[256];
__device__ __align__(16) float2 g_ct[256];            // (cos, sin) pairs
__device__ __align__(16) float2 g_E[128*64];          // fwdH twiddles E[h][kxp]
__device__ __align__(16) float2 g_X1[PB*PC*PH*PKY];   // after fwd-W  [b,c,h,ky]
__device__ __align__(16) float2 g_XF[PB*PC*PKX*PKY];  // after fwd-H  [b,c,kx',ky]
__device__ __align__(16) float2 g_OF[PB*PC*PKX*PKY];  // after mix
__device__ __align__(16) float2 g_Y1[PB*PC*PKY*PH];   // after inv-H  [b,c,ky,h]
__device__ __align__(16) float  g_y[PB*PC*PH*PW];     // spectral conv out
__device__ __align__(16) float  g_z[PB*PC*PH*PW];     // MLP out
__device__ __align__(16) float  g_p1[PB*PC*4*2];
__device__ __align__(16) float  g_p2[PB*PH*2];
__device__ __align__(16) float  g_s1[PB*2];
__device__ __align__(16) float  g_s2[PB*2];
__device__ __align__(16) float  g_gb[PB*PC*2];

__device__ __forceinline__ float gelu_f(float v) {
    return 0.5f * v * (1.0f + erff(v * 0.7071067811865476f));
}

// ---- packed f32x2 helpers (bit-identical fp32 FMA, 2 per issue slot) ----
__device__ __forceinline__ u64 fma2(u64 a, u64 b, u64 c) {
    u64 d;
    asm("fma.rn.f32x2 %0, %1, %2, %3;" : "=l"(d) : "l"(a), "l"(b), "l"(c));
    return d;
}
__device__ __forceinline__ u64 pack2(float v) {
    u64 d;
    asm("mov.b64 %0, {%1, %1};" : "=l"(d) : "f"(v));
    return d;
}
__device__ __forceinline__ void upk2(u64 v, float& lo, float& hi) {
    asm("mov.b64 {%0, %1}, %2;" : "=f"(lo), "=f"(hi) : "l"(v));
}

// ---- twiddle tables: fully parallel grid-stride ----
__global__ void k_tab() {
    int i = blockIdx.x * blockDim.x + threadIdx.x;
    if (i < 8192) {
        int j = i >> 5, ky = i & 31;
        int idx = (ky * j) & 255;
        double s2, c2;
        sincospi((double)idx * (2.0 / 256.0), &s2, &c2);
        g_T[j * 64 + 2 * ky]     = (float)c2;
        g_T[j * 64 + 2 * ky + 1] = (float)(-s2);
    } else if (i < 8448) {
        int j = i - 8192;
        double sd, cd;
        sincospi((double)j * (2.0 / 256.0), &sd, &cd);
        g_cos[j] = (float)cd;
        g_sin[j] = (float)sd;
        g_ct[j] = make_float2((float)cd, (float)sd);
    } else if (i < 16640) {
        int k = i - 8448;
        int h = k >> 6, kxp = k & 63;
        int kxm = kxp + ((kxp >= 32) ? 192 : 0);
        int idx = (kxm * h) & 255;
        double s2, c2;
        sincospi((double)idx * (2.0 / 256.0), &s2, &c2);
        g_E[k] = make_float2((float)c2, (float)s2);
    }
}

// ---- FiLM gamma/beta ----
__global__ void k_film(const float* __restrict__ t,
                       const float* __restrict__ gw, const float* __restrict__ gb,
                       const float* __restrict__ bw, const float* __restrict__ bb) {
    int b = blockIdx.x, o = threadIdx.x;
    float g = gb[o], be = bb[o];
    for (int c = 0; c < PC; ++c) {
        float tv = t[b * PC + c];
        g  += gw[o * PC + c] * tv;
        be += bw[o * PC + c] * tv;
    }
    g_gb[(b * PC + o) * 2]     = g;
    g_gb[(b * PC + o) * 2 + 1] = be;
}

// ---- forward DFT along W, radix-2; T via LDG, packed FFMA2 ----
__global__ void __launch_bounds__(256) k_fwdW(const float* __restrict__ x) {
    extern __shared__ char smraw[];
    float2* su = (float2*)smraw;            // [row 64][w<128] (u0,u1)  64KB
    int tid = threadIdx.x;
    size_t base = (size_t)blockIdx.x * 64 * 256;

    for (int i = tid; i < 2048; i += 256) {
        int row = i >> 5, w4 = (i & 31) * 4;
        float4 a = *(const float4*)&x[base + row * 256 + w4];
        float4 b = *(const float4*)&x[base + row * 256 + w4 + 128];
        float4* d = (float4*)&su[row * 128 + w4];
        d[0] = make_float4(a.x + b.x, a.x - b.x, a.y + b.y, a.y - b.y);
        d[1] = make_float4(a.z + b.z, a.z - b.z, a.w + b.w, a.w - b.w);
    }
    __syncthreads();

    int r0 = (tid >> 3) * 2;
    int c0 = (tid & 7) * 8;

    // packed accumulators: [row][pair]; pair p covers cols c0+2p, c0+2p+1
    u64 acc[2][4];
#pragma unroll
    for (int r = 0; r < 2; ++r)
#pragma unroll
        for (int p = 0; p < 4; ++p) acc[r][p] = 0ull;

    const float2* rowA = su + r0 * 128;
    const float2* rowB = rowA + 128;
#pragma unroll 4
    for (int k = 0; k < 128; ++k) {
        float2 ua = rowA[k];
        float2 ub = rowB[k];
        ulonglong2 t01 = *(const ulonglong2*)&g_T[k * 64 + c0];
        ulonglong2 t23 = *(const ulonglong2*)&g_T[k * 64 + c0 + 4];
        u64 uax = pack2(ua.x), uay = pack2(ua.y);
        u64 ubx = pack2(ub.x), uby = pack2(ub.y);
        acc[0][0] = fma2(uax, t01.x, acc[0][0]);
        acc[0][1] = fma2(uay, t01.y, acc[0][1]);
        acc[0][2] = fma2(uax, t23.x, acc[0][2]);
        acc[0][3] = fma2(uay, t23.y, acc[0][3]);
        acc[1][0] = fma2(ubx, t01.x, acc[1][0]);
        acc[1][1] = fma2(uby, t01.y, acc[1][1]);
        acc[1][2] = fma2(ubx, t23.x, acc[1][2]);
        acc[1][3] = fma2(uby, t23.y, acc[1][3]);
    }
    float* go = (float*)g_X1 + (size_t)blockIdx.x * 64 * 64;
#pragma unroll
    for (int r = 0; r < 2; ++r) {
        float o[8];
#pragma unroll
        for (int p = 0; p < 4; ++p) upk2(acc[r][p], o[2 * p], o[2 * p + 1]);
        *(float4*)&go[(r0 + r) * 64 + c0]     = make_float4(o[0], o[1], o[2], o[3]);
        *(float4*)&go[(r0 + r) * 64 + c0 + 4] = make_float4(o[4], o[5], o[6], o[7]);
    }
}

// ---- forward DFT along H, radix-2; ky-split + E via LDG + packed FFMA2 ----
__global__ void __launch_bounds__(256) k_fwdH() {
    extern __shared__ char smraw[];
    float2* sv0 = (float2*)smraw;                    // [h<128][16] sum operand
    float2* sv1 = (float2*)(smraw + 16384 + 32);     // diff operand (skewed)
    int tid = threadIdx.x;
    int bc = blockIdx.x >> 1, kh = blockIdx.x & 1;

    const float4* src = (const float4*)(g_X1 + (size_t)bc * 8192);
    float4* d0 = (float4*)sv0;
    float4* d1 = (float4*)sv1;
    for (int i = tid; i < 1024; i += 256) {
        int h = i >> 3, j = i & 7;
        int s = h * 16 + kh * 8 + j;
        float4 a = src[s];
        float4 b = src[s + 2048];                    // h+128
        d0[i] = make_float4(a.x + b.x, a.y + b.y, a.z + b.z, a.w + b.w);
        d1[i] = make_float4(a.x - b.x, a.y - b.y, a.z - b.z, a.w - b.w);
    }
    __syncthreads();

    int kxp = tid & 63;
    int ky0 = (tid >> 6) * 4;
    const float2* sv = (kxp & 1) ? sv1 : sv0;
    const float2* E = g_E + kxp;

    // P = sum v*(e.x,e.x), Q = sum v*(e.y,e.y); out=(P.lo+Q.hi, P.hi-Q.lo)
    u64 P[4], Q[4];
#pragma unroll
    for (int j = 0; j < 4; ++j) { P[j] = 0ull; Q[j] = 0ull; }

#pragma unroll 4
    for (int h = 0; h < 128; ++h) {
        float2 e = E[h * 64];
        u64 ex = pack2(e.x), ey = pack2(e.y);
        const float2* row = &sv[h * 16 + ky0];
        ulonglong2 vA = *(const ulonglong2*)&row[0];
        ulonglong2 vB = *(const ulonglong2*)&row[2];
        P[0] = fma2(vA.x, ex, P[0]);  Q[0] = fma2(vA.x, ey, Q[0]);
        P[1] = fma2(vA.y, ex, P[1]);  Q[1] = fma2(vA.y, ey, Q[1]);
        P[2] = fma2(vB.x, ex, P[2]);  Q[2] = fma2(vB.x, ey, Q[2]);
        P[3] = fma2(vB.y, ex, P[3]);  Q[3] = fma2(vB.y, ey, Q[3]);
    }
    float2 acc[4];
#pragma unroll
    for (int j = 0; j < 4; ++j) {
        float px, py, qx, qy;
        upk2(P[j], px, py);
        upk2(Q[j], qx, qy);
        acc[j] = make_float2(px + qy, py - qx);
    }
    int kyg = kh * 16 + ky0;
    float2* o = g_XF + ((size_t)bc * 64 + kxp) * 32 + kyg;
    *(float4*)&o[0] = make_float4(acc[0].x, acc[0].y, acc[1].x, acc[1].y);
    *(float4*)&o[2] = make_float4(acc[2].x, acc[2].y, acc[3].x, acc[3].y);
}

// ---- per-mode complex channel mixing, packed FFMA2 P/Q ----
__global__ void __launch_bounds__(512)
k_mix(const float* __restrict__ w1r, const float* __restrict__ w1i,
      const float* __restrict__ w2r, const float* __restrict__ w2i) {
    extern __shared__ char smraw[];
    float2* sXF = (float2*)smraw;   // [(b*64+i)*16 + kyl], 8192 float2 = 64KB
    int kxp   = blockIdx.x >> 2;
    int ohalf = (blockIdx.x >> 1) & 1;
    int kh    = blockIdx.x & 1;
    int tid = threadIdx.x;

    for (int i = tid; i < 8192; i += 512) {
        int b = i >> 10, rest = i & 1023, ii = rest >> 4, kk = rest & 15;
        sXF[i] = g_XF[(((size_t)b * PC + ii) * PKX + kxp) * PKY + kh * 16 + kk];
    }
    __syncthreads();

    int o   = ohalf * 32 + (tid >> 4);
    int kyl = tid & 15;
    int ky  = kh * 16 + kyl;
    const float* wr; const float* wi; int kxl;
    if (kxp < 32) { wr = w1r; wi = w1i; kxl = kxp; }
    else          { wr = w2r; wi = w2i; kxl = kxp - 32; }

    // P[b] = sum v*(wr,wr), Q[b] = sum v*(wi,wi); ar=P.lo-Q.hi; ai=P.hi+Q.lo
    u64 P[8], Q[8];
#pragma unroll
    for (int b = 0; b < 8; ++b) { P[b] = 0ull; Q[b] = 0ull; }

    const float* wrp = wr + (size_t)o * 1024 + kxl * 32 + ky;
    const float* wip = wi + (size_t)o * 1024 + kxl * 32 + ky;
#pragma unroll 2
    for (int i = 0; i < 64; ++i) {
        u64 wr2 = pack2(wrp[(size_t)i * 65536]);
        u64 wi2 = pack2(wip[(size_t)i * 65536]);
        const u64* vp = (const u64*)&sXF[i * 16 + kyl];   // stride between b: 64*16 float2
#pragma unroll
        for (int b = 0; b < 8; ++b) {
            u64 v = vp[b * 1024];
            P[b] = fma2(v, wr2, P[b]);
            Q[b] = fma2(v, wi2, Q[b]);
        }
    }
#pragma unroll
    for (int b = 0; b < 8; ++b) {
        float px, py, qx, qy;
        upk2(P[b], px, py);
        upk2(Q[b], qx, qy);
        g_OF[(((size_t)b * PC + o) * PKX + kxp) * PKY + ky] =
            make_float2(px - qy, py + qx);
    }
}

// ---- inverse DFT along H, radix-2: Se/So over kx parity, emit h and h+128 ----
__global__ void __launch_bounds__(256) k_invH() {
    __shared__ float2 sOF[2048];
    __shared__ float2 ct[256];
    int tid = threadIdx.x, bc = blockIdx.x;

    const float4* src = (const float4*)(g_OF + (size_t)bc * 2048);
    float4* dst = (float4*)sOF;
    for (int i = tid; i < 1024; i += 256) dst[i] = src[i];
    ct[tid] = g_ct[tid];
    __syncthreads();

    int h0  = (tid >> 3) * 4;     // h<128
    int ky0 = (tid & 7) * 4;

    float2 ae[4][4], ao[4][4];
#pragma unroll
    for (int hh = 0; hh < 4; ++hh)
#pragma unroll
        for (int j = 0; j < 4; ++j) {
            ae[hh][j] = make_float2(0.f, 0.f);
            ao[hh][j] = make_float2(0.f, 0.f);
        }

    for (int kxp = 0; kxp < 64; kxp += 2) {
        int kxm = kxp + ((kxp >= 32) ? 192 : 0);
        float2 te[4], to[4];
#pragma unroll
        for (int hh = 0; hh < 4; ++hh) {
            int h = h0 + hh;
            te[hh] = ct[(kxm * h) & 255];
            to[hh] = ct[((kxm + 1) * h) & 255];
        }
        float4 eA = *(const float4*)&sOF[kxp * 32 + ky0];
        float4 eB = *(const float4*)&sOF[kxp * 32 + ky0 + 2];
        float4 oA = *(const float4*)&sOF[(kxp + 1) * 32 + ky0];
        float4 oB = *(const float4*)&sOF[(kxp + 1) * 32 + ky0 + 2];
        float2 ove[4] = { {eA.x, eA.y}, {eA.z, eA.w}, {eB.x, eB.y}, {eB.z, eB.w} };
        float2 ovo[4] = { {oA.x, oA.y}, {oA.z, oA.w}, {oB.x, oB.y}, {oB.z, oB.w} };
#pragma unroll
        for (int hh = 0; hh < 4; ++hh) {
#pragma unroll
            for (int j = 0; j < 4; ++j) {
                ae[hh][j].x += ove[j].x * te[hh].x - ove[j].y * te[hh].y;
                ae[hh][j].y += ove[j].x * te[hh].y + ove[j].y * te[hh].x;
                ao[hh][j].x += ovo[j].x * to[hh].x - ovo[j].y * to[hh].y;
                ao[hh][j].y += ovo[j].x * to[hh].y + ovo[j].y * to[hh].x;
            }
        }
    }
#pragma unroll
    for (int j = 0; j < 4; ++j) {
        float2* out = g_Y1 + (size_t)bc * 8192 + (ky0 + j) * 256 + h0;
#pragma unroll
        for (int hh = 0; hh < 4; hh += 2) {
            *(float4*)&out[hh] = make_float4(
                ae[hh][j].x + ao[hh][j].x,     ae[hh][j].y + ao[hh][j].y,
                ae[hh+1][j].x + ao[hh+1][j].x, ae[hh+1][j].y + ao[hh+1][j].y);
            *(float4*)&out[hh + 128] = make_float4(
                ae[hh][j].x - ao[hh][j].x,     ae[hh][j].y - ao[hh][j].y,
                ae[hh+1][j].x - ao[hh+1][j].x, ae[hh+1][j].y - ao[hh+1][j].y);
        }
    }
}

// ---- inverse rfft along W, radix-2: Se/So over ky parity, emit w and w+128 ----
__global__ void __launch_bounds__(256) k_invW() {
    extern __shared__ char smraw[];
    float2* sY = (float2*)smraw;               // 8192 float2 (64KB)
    float2* sW = (float2*)(smraw + 65536);     // 31*32 float2
    __shared__ float rbuf[16];
    int tid = threadIdx.x;
    int bc = blockIdx.x >> 2, wt = blockIdx.x & 3;
    int w0 = wt * 32;

    const float4* src = (const float4*)(g_Y1 + (size_t)bc * 8192);
    float4* dst = (float4*)sY;
    for (int i = tid; i < 4096; i += 256) dst[i] = src[i];

    const float inv = 1.0f / 65536.0f;
    for (int i = tid; i < 31 * 32; i += 256) {
        int ky = (i >> 5) + 1;
        int w  = w0 + (i & 31);
        int idx = (ky * w) & 255;
        sW[i] = make_float2(2.0f * inv * g_cos[idx], 2.0f * inv * g_sin[idx]);
    }
    __syncthreads();

    int h0  = (tid >> 3) * 8;
    int wth = (tid & 7) * 4;

    float se[8][4], so[8][4], dc[8];
#pragma unroll
    for (int hh = 0; hh < 8; ++hh) {
        dc[hh] = inv * sY[h0 + hh].x;
#pragma unroll
        for (int ww = 0; ww < 4; ++ww) { se[hh][ww] = 0.f; so[hh][ww] = 0.f; }
    }

    for (int ky = 1; ky < 31; ky += 2) {
        {
            float2 av[8], bv[4];
            const float4* ap = (const float4*)&sY[ky * 256 + h0];
#pragma unroll
            for (int u = 0; u < 4; ++u) {
                float4 t1 = ap[u];
                av[2*u] = make_float2(t1.x, t1.y);
                av[2*u+1] = make_float2(t1.z, t1.w);
            }
            const float4* bp = (const float4*)&sW[(ky - 1) * 32 + wth];
            float4 t2 = bp[0], t3 = bp[1];
            bv[0] = make_float2(t2.x, t2.y); bv[1] = make_float2(t2.z, t2.w);
            bv[2] = make_float2(t3.x, t3.y); bv[3] = make_float2(t3.z, t3.w);
#pragma unroll
            for (int hh = 0; hh < 8; ++hh)
#pragma unroll
                for (int ww = 0; ww < 4; ++ww)
                    so[hh][ww] += av[hh].x * bv[ww].x - av[hh].y * bv[ww].y;
        }
        {
            float2 av[8], bv[4];
            const float4* ap = (const float4*)&sY[(ky + 1) * 256 + h0];
#pragma unroll
            for (int u = 0; u < 4; ++u) {
                float4 t1 = ap[u];
                av[2*u] = make_float2(t1.x, t1.y);
                av[2*u+1] = make_float2(t1.z, t1.w);
            }
            const float4* bp = (const float4*)&sW[ky * 32 + wth];
            float4 t2 = bp[0], t3 = bp[1];
            bv[0] = make_float2(t2.x, t2.y); bv[1] = make_float2(t2.z, t2.w);
            bv[2] = make_float2(t3.x, t3.y); bv[3] = make_float2(t3.z, t3.w);
#pragma unroll
            for (int hh = 0; hh < 8; ++hh)
#pragma unroll
                for (int ww = 0; ww < 4; ++ww)
                    se[hh][ww] += av[hh].x * bv[ww].x - av[hh].y * bv[ww].y;
        }
    }
    {
        float2 av[8], bv[4];
        const float4* ap = (const float4*)&sY[31 * 256 + h0];
#pragma unroll
        for (int u = 0; u < 4; ++u) {
            float4 t1 = ap[u];
            av[2*u] = make_float2(t1.x, t1.y);
            av[2*u+1] = make_float2(t1.z, t1.w);
        }
        const float4* bp = (const float4*)&sW[30 * 32 + wth];
        float4 t2 = bp[0], t3 = bp[1];
        bv[0] = make_float2(t2.x, t2.y); bv[1] = make_float2(t2.z, t2.w);
        bv[2] = make_float2(t3.x, t3.y); bv[3] = make_float2(t3.z, t3.w);
#pragma unroll
        for (int hh = 0; hh < 8; ++hh)
#pragma unroll
            for (int ww = 0; ww < 4; ++ww)
                so[hh][ww] += av[hh].x * bv[ww].x - av[hh].y * bv[ww].y;
    }

    float s = 0.0f, s2 = 0.0f;
#pragma unroll
    for (int hh = 0; hh < 8; ++hh) {
        float lo[4], hi[4];
#pragma unroll
        for (int ww = 0; ww < 4; ++ww) {
            lo[ww] = dc[hh] + se[hh][ww] + so[hh][ww];
            hi[ww] = dc[hh] + se[hh][ww] - so[hh][ww];
            s += lo[ww] + hi[ww];
            s2 += lo[ww] * lo[ww] + hi[ww] * hi[ww];
        }
        size_t base = (size_t)bc * 65536 + (size_t)(h0 + hh) * 256 + w0 + wth;
        *(float4*)&g_y[base]       = make_float4(lo[0], lo[1], lo[2], lo[3]);
        *(float4*)&g_y[base + 128] = make_float4(hi[0], hi[1], hi[2], hi[3]);
    }

    for (int off = 16; off > 0; off >>= 1) {
        s  += __shfl_down_sync(0xffffffffu, s,  off);
        s2 += __shfl_down_sync(0xffffffffu, s2, off);
    }
    int lane = tid & 31, wid = tid >> 5;
    if (lane == 0) { rbuf[wid] = s; rbuf[wid + 8] = s2; }
    __syncthreads();
    if (tid == 0) {
        float S = 0.0f, S2 = 0.0f;
        for (int i = 0; i < 8; ++i) { S += rbuf[i]; S2 += rbuf[i + 8]; }
        g_p1[blockIdx.x * 2] = S;
        g_p1[blockIdx.x * 2 + 1] = S2;
    }
}

__global__ void k_red1() {
    __shared__ float rbuf[16];
    int b = blockIdx.x, tid = threadIdx.x;
    float s  = g_p1[(b * 256 + tid) * 2];
    float s2 = g_p1[(b * 256 + tid) * 2 + 1];
    for (int off = 16; off > 0; off >>= 1) {
        s  += __shfl_down_sync(0xffffffffu, s,  off);
        s2 += __shfl_down_sync(0xffffffffu, s2, off);
    }
    int lane = tid & 31, wid = tid >> 5;
    if (lane == 0) { rbuf[wid] = s; rbuf[wid + 8] = s2; }
    __syncthreads();
    if (tid == 0) {
        float S = 0.0f, S2 = 0.0f;
        for (int i = 0; i < 8; ++i) { S += rbuf[i]; S2 += rbuf[i + 8]; }
        float mean = S * (1.0f / 4194304.0f);
        float var  = S2 * (1.0f / 4194304.0f) - mean * mean;
        g_s1[b * 2] = mean;
        g_s1[b * 2 + 1] = rsqrtf(var + 1e-5f);
    }
}

// ---- GN1 apply + residual + gelu + MLP (FFMA2, natural weight pairs) ----
__global__ void __launch_bounds__(256) k_mlp(const float* __restrict__ x,
                      const float* __restrict__ nw, const float* __restrict__ nb,
                      const float* __restrict__ w1, const float* __restrict__ b1,
                      const float* __restrict__ w2, const float* __restrict__ b2) {
    extern __shared__ char smraw[];
    float* sy2  = (float*)smraw;        // [c][w]  64*128
    float* sh   = sy2 + 8192;           // [m][w]  32*128
    float* sw1  = sh + 4096;            // [c][m]  64*32
    float* sw2  = sw1 + 2048;           // [m][c]  32*64
    float* sb1  = sw2 + 2048;           // 32
    float* sb2v = sb1 + 32;             // 64
    float* snw  = sb2v + 64;            // 64
    float* snb  = snw + 64;             // 64
    __shared__ float rbuf[16];

    int tid = threadIdx.x;
    int b = blockIdx.x >> 8, h = blockIdx.x & 255;

    for (int i = tid; i < 2048; i += 256) {
        int c = i >> 5, m = i & 31;
        sw1[i] = w1[m * 64 + c];
        int m2 = i >> 6, c2 = i & 63;
        sw2[i] = w2[c2 * 32 + m2];
    }
    if (tid < 64) {
        sb2v[tid] = b2[tid];
        snw[tid] = nw[tid];
        snb[tid] = nb[tid];
        if (tid < 32) sb1[tid] = b1[tid];
    }
    float mean1 = g_s1[b * 2], rstd1 = g_s1[b * 2 + 1];
    __syncthreads();

    int m0 = (tid >> 5) * 4;
    int c0 = (tid >> 5) * 8;
    int wl = (tid & 31) * 4;

    float s = 0.0f, s2 = 0.0f;
    for (int half = 0; half < 2; ++half) {
        int wbase = half * 128;

        for (int i = tid; i < 2048; i += 256) {
            int c = i >> 5, w4 = (i & 31) * 4;
            size_t gid = (size_t)(b * 64 + c) * 65536 + (size_t)h * 256 + wbase + w4;
            float4 yv = *(const float4*)&g_y[gid];
            float4 xv = *(const float4*)&x[gid];
            float a = snw[c] * rstd1, bb = snb[c] - mean1 * rstd1 * snw[c];
            float4 o;
            o.x = gelu_f(yv.x * a + bb + xv.x);
            o.y = gelu_f(yv.y * a + bb + xv.y);
            o.z = gelu_f(yv.z * a + bb + xv.z);
            o.w = gelu_f(yv.w * a + bb + xv.w);
            *(float4*)&sy2[c * 128 + w4] = o;
        }
        __syncthreads();

        {   // layer 1
            u64 acc[2][4];
#pragma unroll
            for (int p = 0; p < 2; ++p)
#pragma unroll
                for (int ww = 0; ww < 4; ++ww) acc[p][ww] = 0ull;
            for (int c = 0; c < 64; ++c) {
                ulonglong2 wp = *(const ulonglong2*)&sw1[c * 32 + m0];
                float4 yv = *(const float4*)&sy2[c * 128 + wl];
                u64 y0 = pack2(yv.x), y1 = pack2(yv.y),
                    y2 = pack2(yv.z), y3 = pack2(yv.w);
                acc[0][0] = fma2(wp.x, y0, acc[0][0]);
                acc[0][1] = fma2(wp.x, y1, acc[0][1]);
                acc[0][2] = fma2(wp.x, y2, acc[0][2]);
                acc[0][3] = fma2(wp.x, y3, acc[0][3]);
                acc[1][0] = fma2(wp.y, y0, acc[1][0]);
                acc[1][1] = fma2(wp.y, y1, acc[1][1]);
                acc[1][2] = fma2(wp.y, y2, acc[1][2]);
                acc[1][3] = fma2(wp.y, y3, acc[1][3]);
            }
#pragma unroll
            for (int p = 0; p < 2; ++p) {
                int mA = m0 + 2 * p, mB = mA + 1;
                float bA = sb1[mA], bB = sb1[mB];
#pragma unroll
                for (int ww = 0; ww < 4; ++ww) {
                    float lo, hi;
                    upk2(acc[p][ww], lo, hi);
                    sh[mA * 128 + wl + ww] = gelu_f(lo + bA);
                    sh[mB * 128 + wl + ww] = gelu_f(hi + bB);
                }
            }
        }
        __syncthreads();

        {   // layer 2
            u64 acc2[4][4];
#pragma unroll
            for (int p = 0; p < 4; ++p)
#pragma unroll
                for (int ww = 0; ww < 4; ++ww) acc2[p][ww] = 0ull;
            for (int m = 0; m < 32; ++m) {
                ulonglong2 wA = *(const ulonglong2*)&sw2[m * 64 + c0];
                ulonglong2 wB = *(const ulonglong2*)&sw2[m * 64 + c0 + 4];
                float4 hv = *(const float4*)&sh[m * 128 + wl];
                u64 h0p = pack2(hv.x), h1p = pack2(hv.y),
                    h2p = pack2(hv.z), h3p = pack2(hv.w);
                acc2[0][0] = fma2(wA.x, h0p, acc2[0][0]);
                acc2[0][1] = fma2(wA.x, h1p, acc2[0][1]);
                acc2[0][2] = fma2(wA.x, h2p, acc2[0][2]);
                acc2[0][3] = fma2(wA.x, h3p, acc2[0][3]);
                acc2[1][0] = fma2(wA.y, h0p, acc2[1][0]);
                acc2[1][1] = fma2(wA.y, h1p, acc2[1][1]);
                acc2[1][2] = fma2(wA.y, h2p, acc2[1][2]);
                acc2[1][3] = fma2(wA.y, h3p, acc2[1][3]);
                acc2[2][0] = fma2(wB.x, h0p, acc2[2][0]);
                acc2[2][1] = fma2(wB.x, h1p, acc2[2][1]);
                acc2[2][2] = fma2(wB.x, h2p, acc2[2][2]);
                acc2[2][3] = fma2(wB.x, h3p, acc2[2][3]);
                acc2[3][0] = fma2(wB.y, h0p, acc2[3][0]);
                acc2[3][1] = fma2(wB.y, h1p, acc2[3][1]);
                acc2[3][2] = fma2(wB.y, h2p, acc2[3][2]);
                acc2[3][3] = fma2(wB.y, h3p, acc2[3][3]);
            }
#pragma unroll
            for (int p = 0; p < 4; ++p) {
                int cA = c0 + 2 * p, cB = cA + 1;
                float bA = sb2v[cA], bB = sb2v[cB];
                float oA[4], oB[4];
#pragma unroll
                for (int ww = 0; ww < 4; ++ww) {
                    float lo, hi;
                    upk2(acc2[p][ww], lo, hi);
                    oA[ww] = lo + bA;
                    oB[ww] = hi + bB;
                    s += oA[ww] + oB[ww];
                    s2 += oA[ww] * oA[ww] + oB[ww] * oB[ww];
                }
                size_t gA = (size_t)(b * 64 + cA) * 65536 + (size_t)h * 256 + wbase + wl;
                size_t gB = (size_t)(b * 64 + cB) * 65536 + (size_t)h * 256 + wbase + wl;
                *(float4*)&g_z[gA] = make_float4(oA[0], oA[1], oA[2], oA[3]);
                *(float4*)&g_z[gB] = make_float4(oB[0], oB[1], oB[2], oB[3]);
            }
        }
        __syncthreads();
    }

    for (int off = 16; off > 0; off >>= 1) {
        s  += __shfl_down_sync(0xffffffffu, s,  off);
        s2 += __shfl_down_sync(0xffffffffu, s2, off);
    }
    int lane = tid & 31, widx = tid >> 5;
    if (lane == 0) { rbuf[widx] = s; rbuf[widx + 8] = s2; }
    __syncthreads();
    if (tid == 0) {
        float S = 0.0f, S2 = 0.0f;
        for (int i = 0; i < 8; ++i) { S += rbuf[i]; S2 += rbuf[i + 8]; }
        g_p2[blockIdx.x * 2] = S;
        g_p2[blockIdx.x * 2 + 1] = S2;
    }
}

__global__ void k_red2() {
    __shared__ float rbuf[16];
    int b = blockIdx.x, tid = threadIdx.x;
    float s  = g_p2[(b * 256 + tid) * 2];
    float s2 = g_p2[(b * 256 + tid) * 2 + 1];
    for (int off = 16; off > 0; off >>= 1) {
        s  += __shfl_down_sync(0xffffffffu, s,  off);
        s2 += __shfl_down_sync(0xffffffffu, s2, off);
    }
    int lane = tid & 31, wid = tid >> 5;
    if (lane == 0) { rbuf[wid] = s; rbuf[wid + 8] = s2; }
    __syncthreads();
    if (tid == 0) {
        float S = 0.0f, S2 = 0.0f;
        for (int i = 0; i < 8; ++i) { S += rbuf[i]; S2 += rbuf[i + 8]; }
        float mean = S * (1.0f / 4194304.0f);
        float var  = S2 * (1.0f / 4194304.0f) - mean * mean;
        g_s2[b * 2] = mean;
        g_s2[b * 2 + 1] = rsqrtf(var + 1e-5f);
    }
}

// ---- final: FiLM GN + skip2 ----
__global__ void k_final(const float* __restrict__ x, float* __restrict__ out) {
    int gi = blockIdx.x * 256 + threadIdx.x;
#pragma unroll
    for (int u = 0; u < 4; ++u) {
        size_t i4 = (size_t)gi + (size_t)u * 2097152;
        size_t e = i4 * 4;
        int b = (int)(e >> 22);
        int c = (int)((e >> 16) & 63);
        float mean = g_s2[b * 2], rstd = g_s2[b * 2 + 1];
        float ga = g_gb[(b * 64 + c) * 2], be = g_gb[(b * 64 + c) * 2 + 1];
        float4 zv = ((const float4*)g_z)[i4];
        float4 xv = ((const float4*)x)[i4];
        float4 ov;
        ov.x = ga * (zv.x - mean) * rstd + be + gelu_f(xv.x);
        ov.y = ga * (zv.y - mean) * rstd + be + gelu_f(xv.y);
        ov.z = ga * (zv.z - mean) * rstd + be + gelu_f(xv.z);
        ov.w = ga * (zv.w - mean) * rstd + be + gelu_f(xv.w);
        ((float4*)out)[i4] = ov;
    }
}

extern "C" void kernel_launch(void* const* d_in, const int* in_sizes, int n_in,
                              void* d_out, int out_size) {
    const float* x       = (const float*)d_in[0];
    const float* t       = (const float*)d_in[1];
    const float* w1r     = (const float*)d_in[2];
    const float* w1i     = (const float*)d_in[3];
    const float* w2r     = (const float*)d_in[4];
    const float* w2i     = (const float*)d_in[5];
    const float* norm1_w = (const float*)d_in[6];
    const float* norm1_b = (const float*)d_in[7];
    const float* mlp_w1  = (const float*)d_in[8];
    const float* mlp_b1  = (const float*)d_in[9];
    const float* mlp_w2  = (const float*)d_in[10];
    const float* mlp_b2  = (const float*)d_in[11];
    const float* gamma_w = (const float*)d_in[12];
    const float* gamma_b = (const float*)d_in[13];
    const float* beta_w  = (const float*)d_in[14];
    const float* beta_b  = (const float*)d_in[15];
    float* out = (float*)d_out;

    cudaFuncSetAttribute(k_fwdW, cudaFuncAttributeMaxDynamicSharedMemorySize, 65536);
    cudaFuncSetAttribute(k_fwdH, cudaFuncAttributeMaxDynamicSharedMemorySize, 32800);
    cudaFuncSetAttribute(k_mix,  cudaFuncAttributeMaxDynamicSharedMemorySize, 65536);
    cudaFuncSetAttribute(k_invW, cudaFuncAttributeMaxDynamicSharedMemorySize, 73728);
    cudaFuncSetAttribute(k_mlp,  cudaFuncAttributeMaxDynamicSharedMemorySize, 66432);

    k_tab<<<65, 256>>>();
    k_film<<<PB, PC>>>(t, gamma_w, gamma_b, beta_w, beta_b);
    k_fwdW<<<NROWS / 64, 256, 65536>>>(x);
    k_fwdH<<<PB * PC * 2, 256, 32800>>>();
    k_mix<<<256, 512, 65536>>>(w1r, w1i, w2r, w2i);
    k_invH<<<PB * PC, 256>>>();
    k_invW<<<PB * PC * 4, 256, 73728>>>();
    k_red1<<<PB, 256>>>();
    k_mlp<<<PB * PH, 256, 66432>>>(x, norm1_w, norm1_b,
                                   mlp_w1, mlp_b1, mlp_w2, mlp_b2);
    k_red2<<<PB, 256>>>();
    k_final<<<8192, 256>>>(x, out);
}

// round 15
// speedup vs baseline: 1.3760x; 1.0203x over previous
#include <cuda_runtime.h>
#include <math.h>

#define PB 8
#define PC 64
#define PH 256
#define PW 256
#define PKX 64
#define PKY 32
#define NROWS (PB*PC*PH)

typedef unsigned long long u64;

// ---- scratch (device globals; no runtime allocation) ----
__device__ __align__(16) float  g_T[256*64];
__device__ __align__(16) float  g_cos[256];
__device__ __align__(16) float  g_sin[256];
__device__ __align__(16) float2 g_ct[256];            // (cos, sin) pairs
__device__ __align__(16) float2 g_E[128*64];          // fwdH twiddles E[h][kxp]
__device__ __align__(16) float2 g_X1[PB*PC*PH*PKY];   // after fwd-W  [b,c,h,ky]
__device__ __align__(16) float2 g_XF[PB*PC*PKX*PKY];  // after fwd-H  [b,c,kx',ky]
__device__ __align__(16) float2 g_OF[PB*PC*PKX*PKY];  // after mix
__device__ __align__(16) float2 g_Y1[PB*PC*PKY*PH];   // after inv-H  [b,c,ky,h]
__device__ __align__(16) float  g_y[PB*PC*PH*PW];     // spectral conv out
__device__ __align__(16) float  g_z[PB*PC*PH*PW];     // MLP out
__device__ __align__(16) float  g_p1[PB*PC*4*2];
__device__ __align__(16) float  g_p2[PB*PH*2];
__device__ __align__(16) float  g_s1[PB*2];
__device__ __align__(16) float  g_s2[PB*2];
__device__ __align__(16) float  g_gb[PB*PC*2];

__device__ __forceinline__ float gelu_f(float v) {
    return 0.5f * v * (1.0f + erff(v * 0.7071067811865476f));
}

// ---- packed f32x2 helpers (bit-identical fp32 FMA, 2 per issue slot) ----
__device__ __forceinline__ u64 fma2(u64 a, u64 b, u64 c) {
    u64 d;
    asm("fma.rn.f32x2 %0, %1, %2, %3;" : "=l"(d) : "l"(a), "l"(b), "l"(c));
    return d;
}
__device__ __forceinline__ u64 pack2(float v) {
    u64 d;
    asm("mov.b64 %0, {%1, %1};" : "=l"(d) : "f"(v));
    return d;
}
__device__ __forceinline__ u64 packab(float a, float b) {
    u64 d;
    asm("mov.b64 %0, {%1, %2};" : "=l"(d) : "f"(a), "f"(b));
    return d;
}
__device__ __forceinline__ void upk2(u64 v, float& lo, float& hi) {
    asm("mov.b64 {%0, %1}, %2;" : "=f"(lo), "=f"(hi) : "l"(v));
}

// ---- twiddle tables: fully parallel grid-stride ----
__global__ void k_tab() {
    int i = blockIdx.x * blockDim.x + threadIdx.x;
    if (i < 8192) {
        int j = i >> 5, ky = i & 31;
        int idx = (ky * j) & 255;
        double s2, c2;
        sincospi((double)idx * (2.0 / 256.0), &s2, &c2);
        g_T[j * 64 + 2 * ky]     = (float)c2;
        g_T[j * 64 + 2 * ky + 1] = (float)(-s2);
    } else if (i < 8448) {
        int j = i - 8192;
        double sd, cd;
        sincospi((double)j * (2.0 / 256.0), &sd, &cd);
        g_cos[j] = (float)cd;
        g_sin[j] = (float)sd;
        g_ct[j] = make_float2((float)cd, (float)sd);
    } else if (i < 16640) {
        int k = i - 8448;
        int h = k >> 6, kxp = k & 63;
        int kxm = kxp + ((kxp >= 32) ? 192 : 0);
        int idx = (kxm * h) & 255;
        double s2, c2;
        sincospi((double)idx * (2.0 / 256.0), &s2, &c2);
        g_E[k] = make_float2((float)c2, (float)s2);
    }
}

// ---- FiLM gamma/beta ----
__global__ void k_film(const float* __restrict__ t,
                       const float* __restrict__ gw, const float* __restrict__ gb,
                       const float* __restrict__ bw, const float* __restrict__ bb) {
    int b = blockIdx.x, o = threadIdx.x;
    float g = gb[o], be = bb[o];
    for (int c = 0; c < PC; ++c) {
        float tv = t[b * PC + c];
        g  += gw[o * PC + c] * tv;
        be += bw[o * PC + c] * tv;
    }
    g_gb[(b * PC + o) * 2]     = g;
    g_gb[(b * PC + o) * 2 + 1] = be;
}

// ---- forward DFT along W, radix-2; T via LDG, packed FFMA2 ----
__global__ void __launch_bounds__(256) k_fwdW(const float* __restrict__ x) {
    extern __shared__ char smraw[];
    float2* su = (float2*)smraw;            // [row 64][w<128] (u0,u1)  64KB
    int tid = threadIdx.x;
    size_t base = (size_t)blockIdx.x * 64 * 256;

    for (int i = tid; i < 2048; i += 256) {
        int row = i >> 5, w4 = (i & 31) * 4;
        float4 a = *(const float4*)&x[base + row * 256 + w4];
        float4 b = *(const float4*)&x[base + row * 256 + w4 + 128];
        float4* d = (float4*)&su[row * 128 + w4];
        d[0] = make_float4(a.x + b.x, a.x - b.x, a.y + b.y, a.y - b.y);
        d[1] = make_float4(a.z + b.z, a.z - b.z, a.w + b.w, a.w - b.w);
    }
    __syncthreads();

    int r0 = (tid >> 3) * 2;
    int c0 = (tid & 7) * 8;

    u64 acc[2][4];
#pragma unroll
    for (int r = 0; r < 2; ++r)
#pragma unroll
        for (int p = 0; p < 4; ++p) acc[r][p] = 0ull;

    const float2* rowA = su + r0 * 128;
    const float2* rowB = rowA + 128;
#pragma unroll 4
    for (int k = 0; k < 128; ++k) {
        float2 ua = rowA[k];
        float2 ub = rowB[k];
        ulonglong2 t01 = *(const ulonglong2*)&g_T[k * 64 + c0];
        ulonglong2 t23 = *(const ulonglong2*)&g_T[k * 64 + c0 + 4];
        u64 uax = pack2(ua.x), uay = pack2(ua.y);
        u64 ubx = pack2(ub.x), uby = pack2(ub.y);
        acc[0][0] = fma2(uax, t01.x, acc[0][0]);
        acc[0][1] = fma2(uay, t01.y, acc[0][1]);
        acc[0][2] = fma2(uax, t23.x, acc[0][2]);
        acc[0][3] = fma2(uay, t23.y, acc[0][3]);
        acc[1][0] = fma2(ubx, t01.x, acc[1][0]);
        acc[1][1] = fma2(uby, t01.y, acc[1][1]);
        acc[1][2] = fma2(ubx, t23.x, acc[1][2]);
        acc[1][3] = fma2(uby, t23.y, acc[1][3]);
    }
    float* go = (float*)g_X1 + (size_t)blockIdx.x * 64 * 64;
#pragma unroll
    for (int r = 0; r < 2; ++r) {
        float o[8];
#pragma unroll
        for (int p = 0; p < 4; ++p) upk2(acc[r][p], o[2 * p], o[2 * p + 1]);
        *(float4*)&go[(r0 + r) * 64 + c0]     = make_float4(o[0], o[1], o[2], o[3]);
        *(float4*)&go[(r0 + r) * 64 + c0 + 4] = make_float4(o[4], o[5], o[6], o[7]);
    }
}

// ---- forward DFT along H, radix-2; ky-split + E via LDG + packed FFMA2 ----
__global__ void __launch_bounds__(256) k_fwdH() {
    extern __shared__ char smraw[];
    float2* sv0 = (float2*)smraw;                    // [h<128][16] sum operand
    float2* sv1 = (float2*)(smraw + 16384 + 32);     // diff operand (skewed)
    int tid = threadIdx.x;
    int bc = blockIdx.x >> 1, kh = blockIdx.x & 1;

    const float4* src = (const float4*)(g_X1 + (size_t)bc * 8192);
    float4* d0 = (float4*)sv0;
    float4* d1 = (float4*)sv1;
    for (int i = tid; i < 1024; i += 256) {
        int h = i >> 3, j = i & 7;
        int s = h * 16 + kh * 8 + j;
        float4 a = src[s];
        float4 b = src[s + 2048];                    // h+128
        d0[i] = make_float4(a.x + b.x, a.y + b.y, a.z + b.z, a.w + b.w);
        d1[i] = make_float4(a.x - b.x, a.y - b.y, a.z - b.z, a.w - b.w);
    }
    __syncthreads();

    int kxp = tid & 63;
    int ky0 = (tid >> 6) * 4;
    const float2* sv = (kxp & 1) ? sv1 : sv0;
    const float2* E = g_E + kxp;

    u64 P[4], Q[4];
#pragma unroll
    for (int j = 0; j < 4; ++j) { P[j] = 0ull; Q[j] = 0ull; }

#pragma unroll 4
    for (int h = 0; h < 128; ++h) {
        float2 e = E[h * 64];
        u64 ex = pack2(e.x), ey = pack2(e.y);
        const float2* row = &sv[h * 16 + ky0];
        ulonglong2 vA = *(const ulonglong2*)&row[0];
        ulonglong2 vB = *(const ulonglong2*)&row[2];
        P[0] = fma2(vA.x, ex, P[0]);  Q[0] = fma2(vA.x, ey, Q[0]);
        P[1] = fma2(vA.y, ex, P[1]);  Q[1] = fma2(vA.y, ey, Q[1]);
        P[2] = fma2(vB.x, ex, P[2]);  Q[2] = fma2(vB.x, ey, Q[2]);
        P[3] = fma2(vB.y, ex, P[3]);  Q[3] = fma2(vB.y, ey, Q[3]);
    }
    float2 acc[4];
#pragma unroll
    for (int j = 0; j < 4; ++j) {
        float px, py, qx, qy;
        upk2(P[j], px, py);
        upk2(Q[j], qx, qy);
        acc[j] = make_float2(px + qy, py - qx);
    }
    int kyg = kh * 16 + ky0;
    float2* o = g_XF + ((size_t)bc * 64 + kxp) * 32 + kyg;
    *(float4*)&o[0] = make_float4(acc[0].x, acc[0].y, acc[1].x, acc[1].y);
    *(float4*)&o[2] = make_float4(acc[2].x, acc[2].y, acc[3].x, acc[3].y);
}

// ---- per-mode complex channel mixing, packed FFMA2 P/Q ----
__global__ void __launch_bounds__(512)
k_mix(const float* __restrict__ w1r, const float* __restrict__ w1i,
      const float* __restrict__ w2r, const float* __restrict__ w2i) {
    extern __shared__ char smraw[];
    float2* sXF = (float2*)smraw;   // [(b*64+i)*16 + kyl], 8192 float2 = 64KB
    int kxp   = blockIdx.x >> 2;
    int ohalf = (blockIdx.x >> 1) & 1;
    int kh    = blockIdx.x & 1;
    int tid = threadIdx.x;

    for (int i = tid; i < 8192; i += 512) {
        int b = i >> 10, rest = i & 1023, ii = rest >> 4, kk = rest & 15;
        sXF[i] = g_XF[(((size_t)b * PC + ii) * PKX + kxp) * PKY + kh * 16 + kk];
    }
    __syncthreads();

    int o   = ohalf * 32 + (tid >> 4);
    int kyl = tid & 15;
    int ky  = kh * 16 + kyl;
    const float* wr; const float* wi; int kxl;
    if (kxp < 32) { wr = w1r; wi = w1i; kxl = kxp; }
    else          { wr = w2r; wi = w2i; kxl = kxp - 32; }

    u64 P[8], Q[8];
#pragma unroll
    for (int b = 0; b < 8; ++b) { P[b] = 0ull; Q[b] = 0ull; }

    const float* wrp = wr + (size_t)o * 1024 + kxl * 32 + ky;
    const float* wip = wi + (size_t)o * 1024 + kxl * 32 + ky;
#pragma unroll 2
    for (int i = 0; i < 64; ++i) {
        u64 wr2 = pack2(wrp[(size_t)i * 65536]);
        u64 wi2 = pack2(wip[(size_t)i * 65536]);
        const u64* vp = (const u64*)&sXF[i * 16 + kyl];
#pragma unroll
        for (int b = 0; b < 8; ++b) {
            u64 v = vp[b * 1024];
            P[b] = fma2(v, wr2, P[b]);
            Q[b] = fma2(v, wi2, Q[b]);
        }
    }
#pragma unroll
    for (int b = 0; b < 8; ++b) {
        float px, py, qx, qy;
        upk2(P[b], px, py);
        upk2(Q[b], qx, qy);
        g_OF[(((size_t)b * PC + o) * PKX + kxp) * PKY + ky] =
            make_float2(px - qy, py + qx);
    }
}

// ---- inverse DFT along H, radix-2; h-pair packed FFMA2 (bit-identical) ----
__global__ void __launch_bounds__(256) k_invH() {
    __shared__ float2 sOF[2048];
    __shared__ float2 ct[256];
    int tid = threadIdx.x, bc = blockIdx.x;

    const float4* src = (const float4*)(g_OF + (size_t)bc * 2048);
    float4* dst = (float4*)sOF;
    for (int i = tid; i < 1024; i += 256) dst[i] = src[i];
    ct[tid] = g_ct[tid];
    __syncthreads();

    int h0  = (tid >> 3) * 4;     // 4 h = 2 packed pairs
    int ky0 = (tid & 7) * 4;

    // packed accumulators: [parity][hpair][j] — lanes (h, h+1)
    u64 Re[2][2][4], Im[2][2][4];
#pragma unroll
    for (int q = 0; q < 2; ++q)
#pragma unroll
        for (int p = 0; p < 2; ++p)
#pragma unroll
            for (int j = 0; j < 4; ++j) { Re[q][p][j] = 0ull; Im[q][p][j] = 0ull; }

    for (int kxp = 0; kxp < 64; kxp += 2) {
        int kxm = kxp + ((kxp >= 32) ? 192 : 0);
        float2 te[4], to[4];
#pragma unroll
        for (int hh = 0; hh < 4; ++hh) {
            int h = h0 + hh;
            te[hh] = ct[(kxm * h) & 255];
            to[hh] = ct[((kxm + 1) * h) & 255];
        }
        u64 tex[2], tey[2], teyn[2], tox[2], toy[2], toyn[2];
#pragma unroll
        for (int p = 0; p < 2; ++p) {
            tex[p]  = packab(te[2*p].x,  te[2*p+1].x);
            tey[p]  = packab(te[2*p].y,  te[2*p+1].y);
            teyn[p] = packab(-te[2*p].y, -te[2*p+1].y);
            tox[p]  = packab(to[2*p].x,  to[2*p+1].x);
            toy[p]  = packab(to[2*p].y,  to[2*p+1].y);
            toyn[p] = packab(-to[2*p].y, -to[2*p+1].y);
        }
        float4 eA = *(const float4*)&sOF[kxp * 32 + ky0];
        float4 eB = *(const float4*)&sOF[kxp * 32 + ky0 + 2];
        float4 oA = *(const float4*)&sOF[(kxp + 1) * 32 + ky0];
        float4 oB = *(const float4*)&sOF[(kxp + 1) * 32 + ky0 + 2];
        float2 ove[4] = { {eA.x, eA.y}, {eA.z, eA.w}, {eB.x, eB.y}, {eB.z, eB.w} };
        float2 ovo[4] = { {oA.x, oA.y}, {oA.z, oA.w}, {oB.x, oB.y}, {oB.z, oB.w} };
#pragma unroll
        for (int j = 0; j < 4; ++j) {
            u64 evx = pack2(ove[j].x), evy = pack2(ove[j].y);
            u64 ovx = pack2(ovo[j].x), ovy = pack2(ovo[j].y);
#pragma unroll
            for (int p = 0; p < 2; ++p) {
                Re[0][p][j] = fma2(evx, tex[p],  Re[0][p][j]);
                Re[0][p][j] = fma2(evy, teyn[p], Re[0][p][j]);
                Im[0][p][j] = fma2(evx, tey[p],  Im[0][p][j]);
                Im[0][p][j] = fma2(evy, tex[p],  Im[0][p][j]);
                Re[1][p][j] = fma2(ovx, tox[p],  Re[1][p][j]);
                Re[1][p][j] = fma2(ovy, toyn[p], Re[1][p][j]);
                Im[1][p][j] = fma2(ovx, toy[p],  Im[1][p][j]);
                Im[1][p][j] = fma2(ovy, tox[p],  Im[1][p][j]);
            }
        }
    }

    float2 ae[4][4], ao[4][4];
#pragma unroll
    for (int p = 0; p < 2; ++p)
#pragma unroll
        for (int j = 0; j < 4; ++j) {
            upk2(Re[0][p][j], ae[2*p][j].x, ae[2*p+1][j].x);
            upk2(Im[0][p][j], ae[2*p][j].y, ae[2*p+1][j].y);
            upk2(Re[1][p][j], ao[2*p][j].x, ao[2*p+1][j].x);
            upk2(Im[1][p][j], ao[2*p][j].y, ao[2*p+1][j].y);
        }
#pragma unroll
    for (int j = 0; j < 4; ++j) {
        float2* out = g_Y1 + (size_t)bc * 8192 + (ky0 + j) * 256 + h0;
#pragma unroll
        for (int hh = 0; hh < 4; hh += 2) {
            *(float4*)&out[hh] = make_float4(
                ae[hh][j].x + ao[hh][j].x,     ae[hh][j].y + ao[hh][j].y,
                ae[hh+1][j].x + ao[hh+1][j].x, ae[hh+1][j].y + ao[hh+1][j].y);
            *(float4*)&out[hh + 128] = make_float4(
                ae[hh][j].x - ao[hh][j].x,     ae[hh][j].y - ao[hh][j].y,
                ae[hh+1][j].x - ao[hh+1][j].x, ae[hh+1][j].y - ao[hh+1][j].y);
        }
    }
}

// ---- inverse rfft along W, radix-2; w-pair packed FFMA2 SoA (bit-identical) ----
__global__ void __launch_bounds__(256) k_invW() {
    extern __shared__ char smraw[];
    float2* sY  = (float2*)smraw;               // 8192 float2 (64KB)
    float*  sWc = (float*)(smraw + 65536);      // 31*32 cos*2inv
    float*  sWn = sWc + 31 * 32;                // 31*32 (-sin)*2inv
    __shared__ float rbuf[16];
    int tid = threadIdx.x;
    int bc = blockIdx.x >> 2, wt = blockIdx.x & 3;
    int w0 = wt * 32;

    const float4* src = (const float4*)(g_Y1 + (size_t)bc * 8192);
    float4* dst = (float4*)sY;
    for (int i = tid; i < 4096; i += 256) dst[i] = src[i];

    const float inv = 1.0f / 65536.0f;
    for (int i = tid; i < 31 * 32; i += 256) {
        int ky = (i >> 5) + 1;
        int w  = w0 + (i & 31);
        int idx = (ky * w) & 255;
        sWc[i] = 2.0f * inv * g_cos[idx];
        sWn[i] = -2.0f * inv * g_sin[idx];
    }
    __syncthreads();

    int h0  = (tid >> 3) * 8;
    int wth = (tid & 7) * 4;

    u64 se2[8][2], so2[8][2];
    float dc[8];
#pragma unroll
    for (int hh = 0; hh < 8; ++hh) {
        dc[hh] = inv * sY[h0 + hh].x;
#pragma unroll
        for (int wp = 0; wp < 2; ++wp) { se2[hh][wp] = 0ull; so2[hh][wp] = 0ull; }
    }

    for (int ky = 1; ky < 31; ky += 2) {
        {   // odd ky -> so
            float2 av[8];
            const float4* ap = (const float4*)&sY[ky * 256 + h0];
#pragma unroll
            for (int u = 0; u < 4; ++u) {
                float4 t1 = ap[u];
                av[2*u] = make_float2(t1.x, t1.y);
                av[2*u+1] = make_float2(t1.z, t1.w);
            }
            ulonglong2 bc2 = *(const ulonglong2*)&sWc[(ky - 1) * 32 + wth];
            ulonglong2 bn2 = *(const ulonglong2*)&sWn[(ky - 1) * 32 + wth];
#pragma unroll
            for (int hh = 0; hh < 8; ++hh) {
                u64 axp = pack2(av[hh].x), ayp = pack2(av[hh].y);
                so2[hh][0] = fma2(axp, bc2.x, so2[hh][0]);
                so2[hh][0] = fma2(ayp, bn2.x, so2[hh][0]);
                so2[hh][1] = fma2(axp, bc2.y, so2[hh][1]);
                so2[hh][1] = fma2(ayp, bn2.y, so2[hh][1]);
            }
        }
        {   // even ky+1 -> se
            float2 av[8];
            const float4* ap = (const float4*)&sY[(ky + 1) * 256 + h0];
#pragma unroll
            for (int u = 0; u < 4; ++u) {
                float4 t1 = ap[u];
                av[2*u] = make_float2(t1.x, t1.y);
                av[2*u+1] = make_float2(t1.z, t1.w);
            }
            ulonglong2 bc2 = *(const ulonglong2*)&sWc[ky * 32 + wth];
            ulonglong2 bn2 = *(const ulonglong2*)&sWn[ky * 32 + wth];
#pragma unroll
            for (int hh = 0; hh < 8; ++hh) {
                u64 axp = pack2(av[hh].x), ayp = pack2(av[hh].y);
                se2[hh][0] = fma2(axp, bc2.x, se2[hh][0]);
                se2[hh][0] = fma2(ayp, bn2.x, se2[hh][0]);
                se2[hh][1] = fma2(axp, bc2.y, se2[hh][1]);
                se2[hh][1] = fma2(ayp, bn2.y, se2[hh][1]);
            }
        }
    }
    {   // ky = 31 (odd) -> so
        float2 av[8];
        const float4* ap = (const float4*)&sY[31 * 256 + h0];
#pragma unroll
        for (int u = 0; u < 4; ++u) {
            float4 t1 = ap[u];
            av[2*u] = make_float2(t1.x, t1.y);
            av[2*u+1] = make_float2(t1.z, t1.w);
        }
        ulonglong2 bc2 = *(const ulonglong2*)&sWc[30 * 32 + wth];
        ulonglong2 bn2 = *(const ulonglong2*)&sWn[30 * 32 + wth];
#pragma unroll
        for (int hh = 0; hh < 8; ++hh) {
            u64 axp = pack2(av[hh].x), ayp = pack2(av[hh].y);
            so2[hh][0] = fma2(axp, bc2.x, so2[hh][0]);
            so2[hh][0] = fma2(ayp, bn2.x, so2[hh][0]);
            so2[hh][1] = fma2(axp, bc2.y, so2[hh][1]);
            so2[hh][1] = fma2(ayp, bn2.y, so2[hh][1]);
        }
    }

    float s = 0.0f, s2 = 0.0f;
#pragma unroll
    for (int hh = 0; hh < 8; ++hh) {
        float se[4], so[4];
        upk2(se2[hh][0], se[0], se[1]);
        upk2(se2[hh][1], se[2], se[3]);
        upk2(so2[hh][0], so[0], so[1]);
        upk2(so2[hh][1], so[2], so[3]);
        float lo[4], hi[4];
#pragma unroll
        for (int ww = 0; ww < 4; ++ww) {
            lo[ww] = dc[hh] + se[ww] + so[ww];
            hi[ww] = dc[hh] + se[ww] - so[ww];
            s += lo[ww] + hi[ww];
            s2 += lo[ww] * lo[ww] + hi[ww] * hi[ww];
        }
        size_t base = (size_t)bc * 65536 + (size_t)(h0 + hh) * 256 + w0 + wth;
        *(float4*)&g_y[base]       = make_float4(lo[0], lo[1], lo[2], lo[3]);
        *(float4*)&g_y[base + 128] = make_float4(hi[0], hi[1], hi[2], hi[3]);
    }

    for (int off = 16; off > 0; off >>= 1) {
        s  += __shfl_down_sync(0xffffffffu, s,  off);
        s2 += __shfl_down_sync(0xffffffffu, s2, off);
    }
    int lane = tid & 31, wid = tid >> 5;
    if (lane == 0) { rbuf[wid] = s; rbuf[wid + 8] = s2; }
    __syncthreads();
    if (tid == 0) {
        float S = 0.0f, S2 = 0.0f;
        for (int i = 0; i < 8; ++i) { S += rbuf[i]; S2 += rbuf[i + 8]; }
        g_p1[blockIdx.x * 2] = S;
        g_p1[blockIdx.x * 2 + 1] = S2;
    }
}

__global__ void k_red1() {
    __shared__ float rbuf[16];
    int b = blockIdx.x, tid = threadIdx.x;
    float s  = g_p1[(b * 256 + tid) * 2];
    float s2 = g_p1[(b * 256 + tid) * 2 + 1];
    for (int off = 16; off > 0; off >>= 1) {
        s  += __shfl_down_sync(0xffffffffu, s,  off);
        s2 += __shfl_down_sync(0xffffffffu, s2, off);
    }
    int lane = tid & 31, wid = tid >> 5;
    if (lane == 0) { rbuf[wid] = s; rbuf[wid + 8] = s2; }
    __syncthreads();
    if (tid == 0) {
        float S = 0.0f, S2 = 0.0f;
        for (int i = 0; i < 8; ++i) { S += rbuf[i]; S2 += rbuf[i + 8]; }
        float mean = S * (1.0f / 4194304.0f);
        float var  = S2 * (1.0f / 4194304.0f) - mean * mean;
        g_s1[b * 2] = mean;
        g_s1[b * 2 + 1] = rsqrtf(var + 1e-5f);
    }
}

// ---- GN1 apply + residual + gelu + MLP (FFMA2, natural weight pairs) ----
__global__ void __launch_bounds__(256) k_mlp(const float* __restrict__ x,
                      const float* __restrict__ nw, const float* __restrict__ nb,
                      const float* __restrict__ w1, const float* __restrict__ b1,
                      const float* __restrict__ w2, const float* __restrict__ b2) {
    extern __shared__ char smraw[];
    float* sy2  = (float*)smraw;        // [c][w]  64*128
    float* sh   = sy2 + 8192;           // [m][w]  32*128
    float* sw1  = sh + 4096;            // [c][m]  64*32
    float* sw2  = sw1 + 2048;           // [m][c]  32*64
    float* sb1  = sw2 + 2048;           // 32
    float* sb2v = sb1 + 32;             // 64
    float* snw  = sb2v + 64;            // 64
    float* snb  = snw + 64;             // 64
    __shared__ float rbuf[16];

    int tid = threadIdx.x;
    int b = blockIdx.x >> 8, h = blockIdx.x & 255;

    for (int i = tid; i < 2048; i += 256) {
        int c = i >> 5, m = i & 31;
        sw1[i] = w1[m * 64 + c];
        int m2 = i >> 6, c2 = i & 63;
        sw2[i] = w2[c2 * 32 + m2];
    }
    if (tid < 64) {
        sb2v[tid] = b2[tid];
        snw[tid] = nw[tid];
        snb[tid] = nb[tid];
        if (tid < 32) sb1[tid] = b1[tid];
    }
    float mean1 = g_s1[b * 2], rstd1 = g_s1[b * 2 + 1];
    __syncthreads();

    int m0 = (tid >> 5) * 4;
    int c0 = (tid >> 5) * 8;
    int wl = (tid & 31) * 4;

    float s = 0.0f, s2 = 0.0f;
    for (int half = 0; half < 2; ++half) {
        int wbase = half * 128;

        for (int i = tid; i < 2048; i += 256) {
            int c = i >> 5, w4 = (i & 31) * 4;
            size_t gid = (size_t)(b * 64 + c) * 65536 + (size_t)h * 256 + wbase + w4;
            float4 yv = *(const float4*)&g_y[gid];
            float4 xv = *(const float4*)&x[gid];
            float a = snw[c] * rstd1, bb = snb[c] - mean1 * rstd1 * snw[c];
            float4 o;
            o.x = gelu_f(yv.x * a + bb + xv.x);
            o.y = gelu_f(yv.y * a + bb + xv.y);
            o.z = gelu_f(yv.z * a + bb + xv.z);
            o.w = gelu_f(yv.w * a + bb + xv.w);
            *(float4*)&sy2[c * 128 + w4] = o;
        }
        __syncthreads();

        {   // layer 1
            u64 acc[2][4];
#pragma unroll
            for (int p = 0; p < 2; ++p)
#pragma unroll
                for (int ww = 0; ww < 4; ++ww) acc[p][ww] = 0ull;
            for (int c = 0; c < 64; ++c) {
                ulonglong2 wp = *(const ulonglong2*)&sw1[c * 32 + m0];
                float4 yv = *(const float4*)&sy2[c * 128 + wl];
                u64 y0 = pack2(yv.x), y1 = pack2(yv.y),
                    y2 = pack2(yv.z), y3 = pack2(yv.w);
                acc[0][0] = fma2(wp.x, y0, acc[0][0]);
                acc[0][1] = fma2(wp.x, y1, acc[0][1]);
                acc[0][2] = fma2(wp.x, y2, acc[0][2]);
                acc[0][3] = fma2(wp.x, y3, acc[0][3]);
                acc[1][0] = fma2(wp.y, y0, acc[1][0]);
                acc[1][1] = fma2(wp.y, y1, acc[1][1]);
                acc[1][2] = fma2(wp.y, y2, acc[1][2]);
                acc[1][3] = fma2(wp.y, y3, acc[1][3]);
            }
#pragma unroll
            for (int p = 0; p < 2; ++p) {
                int mA = m0 + 2 * p, mB = mA + 1;
                float bA = sb1[mA], bB = sb1[mB];
#pragma unroll
                for (int ww = 0; ww < 4; ++ww) {
                    float lo, hi;
                    upk2(acc[p][ww], lo, hi);
                    sh[mA * 128 + wl + ww] = gelu_f(lo + bA);
                    sh[mB * 128 + wl + ww] = gelu_f(hi + bB);
                }
            }
        }
        __syncthreads();

        {   // layer 2
            u64 acc2[4][4];
#pragma unroll
            for (int p = 0; p < 4; ++p)
#pragma unroll
                for (int ww = 0; ww < 4; ++ww) acc2[p][ww] = 0ull;
            for (int m = 0; m < 32; ++m) {
                ulonglong2 wA = *(const ulonglong2*)&sw2[m * 64 + c0];
                ulonglong2 wB = *(const ulonglong2*)&sw2[m * 64 + c0 + 4];
                float4 hv = *(const float4*)&sh[m * 128 + wl];
                u64 h0p = pack2(hv.x), h1p = pack2(hv.y),
                    h2p = pack2(hv.z), h3p = pack2(hv.w);
                acc2[0][0] = fma2(wA.x, h0p, acc2[0][0]);
                acc2[0][1] = fma2(wA.x, h1p, acc2[0][1]);
                acc2[0][2] = fma2(wA.x, h2p, acc2[0][2]);
                acc2[0][3] = fma2(wA.x, h3p, acc2[0][3]);
                acc2[1][0] = fma2(wA.y, h0p, acc2[1][0]);
                acc2[1][1] = fma2(wA.y, h1p, acc2[1][1]);
                acc2[1][2] = fma2(wA.y, h2p, acc2[1][2]);
                acc2[1][3] = fma2(wA.y, h3p, acc2[1][3]);
                acc2[2][0] = fma2(wB.x, h0p, acc2[2][0]);
                acc2[2][1] = fma2(wB.x, h1p, acc2[2][1]);
                acc2[2][2] = fma2(wB.x, h2p, acc2[2][2]);
                acc2[2][3] = fma2(wB.x, h3p, acc2[2][3]);
                acc2[3][0] = fma2(wB.y, h0p, acc2[3][0]);
                acc2[3][1] = fma2(wB.y, h1p, acc2[3][1]);
                acc2[3][2] = fma2(wB.y, h2p, acc2[3][2]);
                acc2[3][3] = fma2(wB.y, h3p, acc2[3][3]);
            }
#pragma unroll
            for (int p = 0; p < 4; ++p) {
                int cA = c0 + 2 * p, cB = cA + 1;
                float bA = sb2v[cA], bB = sb2v[cB];
                float oA[4], oB[4];
#pragma unroll
                for (int ww = 0; ww < 4; ++ww) {
                    float lo, hi;
                    upk2(acc2[p][ww], lo, hi);
                    oA[ww] = lo + bA;
                    oB[ww] = hi + bB;
                    s += oA[ww] + oB[ww];
                    s2 += oA[ww] * oA[ww] + oB[ww] * oB[ww];
                }
                size_t gA = (size_t)(b * 64 + cA) * 65536 + (size_t)h * 256 + wbase + wl;
                size_t gB = (size_t)(b * 64 + cB) * 65536 + (size_t)h * 256 + wbase + wl;
                *(float4*)&g_z[gA] = make_float4(oA[0], oA[1], oA[2], oA[3]);
                *(float4*)&g_z[gB] = make_float4(oB[0], oB[1], oB[2], oB[3]);
            }
        }
        __syncthreads();
    }

    for (int off = 16; off > 0; off >>= 1) {
        s  += __shfl_down_sync(0xffffffffu, s,  off);
        s2 += __shfl_down_sync(0xffffffffu, s2, off);
    }
    int lane = tid & 31, widx = tid >> 5;
    if (lane == 0) { rbuf[widx] = s; rbuf[widx + 8] = s2; }
    __syncthreads();
    if (tid == 0) {
        float S = 0.0f, S2 = 0.0f;
        for (int i = 0; i < 8; ++i) { S += rbuf[i]; S2 += rbuf[i + 8]; }
        g_p2[blockIdx.x * 2] = S;
        g_p2[blockIdx.x * 2 + 1] = S2;
    }
}

__global__ void k_red2() {
    __shared__ float rbuf[16];
    int b = blockIdx.x, tid = threadIdx.x;
    float s  = g_p2[(b * 256 + tid) * 2];
    float s2 = g_p2[(b * 256 + tid) * 2 + 1];
    for (int off = 16; off > 0; off >>= 1) {
        s  += __shfl_down_sync(0xffffffffu, s,  off);
        s2 += __shfl_down_sync(0xffffffffu, s2, off);
    }
    int lane = tid & 31, wid = tid >> 5;
    if (lane == 0) { rbuf[wid] = s; rbuf[wid + 8] = s2; }
    __syncthreads();
    if (tid == 0) {
        float S = 0.0f, S2 = 0.0f;
        for (int i = 0; i < 8; ++i) { S += rbuf[i]; S2 += rbuf[i + 8]; }
        float mean = S * (1.0f / 4194304.0f);
        float var  = S2 * (1.0f / 4194304.0f) - mean * mean;
        g_s2[b * 2] = mean;
        g_s2[b * 2 + 1] = rsqrtf(var + 1e-5f);
    }
}

// ---- final: FiLM GN + skip2 ----
__global__ void k_final(const float* __restrict__ x, float* __restrict__ out) {
    int gi = blockIdx.x * 256 + threadIdx.x;
#pragma unroll
    for (int u = 0; u < 4; ++u) {
        size_t i4 = (size_t)gi + (size_t)u * 2097152;
        size_t e = i4 * 4;
        int b = (int)(e >> 22);
        int c = (int)((e >> 16) & 63);
        float mean = g_s2[b * 2], rstd = g_s2[b * 2 + 1];
        float ga = g_gb[(b * 64 + c) * 2], be = g_gb[(b * 64 + c) * 2 + 1];
        float4 zv = ((const float4*)g_z)[i4];
        float4 xv = ((const float4*)x)[i4];
        float4 ov;
        ov.x = ga * (zv.x - mean) * rstd + be + gelu_f(xv.x);
        ov.y = ga * (zv.y - mean) * rstd + be + gelu_f(xv.y);
        ov.z = ga * (zv.z - mean) * rstd + be + gelu_f(xv.z);
        ov.w = ga * (zv.w - mean) * rstd + be + gelu_f(xv.w);
        ((float4*)out)[i4] = ov;
    }
}

extern "C" void kernel_launch(void* const* d_in, const int* in_sizes, int n_in,
                              void* d_out, int out_size) {
    const float* x       = (const float*)d_in[0];
    const float* t       = (const float*)d_in[1];
    const float* w1r     = (const float*)d_in[2];
    const float* w1i     = (const float*)d_in[3];
    const float* w2r     = (const float*)d_in[4];
    const float* w2i     = (const float*)d_in[5];
    const float* norm1_w = (const float*)d_in[6];
    const float* norm1_b = (const float*)d_in[7];
    const float* mlp_w1  = (const float*)d_in[8];
    const float* mlp_b1  = (const float*)d_in[9];
    const float* mlp_w2  = (const float*)d_in[10];
    const float* mlp_b2  = (const float*)d_in[11];
    const float* gamma_w = (const float*)d_in[12];
    const float* gamma_b = (const float*)d_in[13];
    const float* beta_w  = (const float*)d_in[14];
    const float* beta_b  = (const float*)d_in[15];
    float* out = (float*)d_out;

    cudaFuncSetAttribute(k_fwdW, cudaFuncAttributeMaxDynamicSharedMemorySize, 65536);
    cudaFuncSetAttribute(k_fwdH, cudaFuncAttributeMaxDynamicSharedMemorySize, 32800);
    cudaFuncSetAttribute(k_mix,  cudaFuncAttributeMaxDynamicSharedMemorySize, 65536);
    cudaFuncSetAttribute(k_invW, cudaFuncAttributeMaxDynamicSharedMemorySize, 73728);
    cudaFuncSetAttribute(k_mlp,  cudaFuncAttributeMaxDynamicSharedMemorySize, 66432);

    k_tab<<<65, 256>>>();
    k_film<<<PB, PC>>>(t, gamma_w, gamma_b, beta_w, beta_b);
    k_fwdW<<<NROWS / 64, 256, 65536>>>(x);
    k_fwdH<<<PB * PC * 2, 256, 32800>>>();
    k_mix<<<256, 512, 65536>>>(w1r, w1i, w2r, w2i);
    k_invH<<<PB * PC, 256>>>();
    k_invW<<<PB * PC * 4, 256, 73728>>>();
    k_red1<<<PB, 256>>>();
    k_mlp<<<PB * PH, 256, 66432>>>(x, norm1_w, norm1_b,
                                   mlp_w1, mlp_b1, mlp_w2, mlp_b2);
    k_red2<<<PB, 256>>>();
    k_final<<<8192, 256>>>(x, out);
}